// round 10
// baseline (speedup 1.0000x reference)
#include <cuda_runtime.h>
#include <cuda_bf16.h>
#include <math.h>
#include <stdint.h>

#define BBATCH 32
#define LSEQ   1024
#define HDIM   256
#define NROWS  (BBATCH * LSEQ)      // 32768
#define NH     (NROWS * HDIM)       // 8388608
#define EPSV   1e-3f

typedef unsigned long long ull;

// ---------------- scratch (__device__ globals; allocation is forbidden) ----------------
__device__ float g_h[2][NH];
__device__ float g_c[2][NH];
__device__ float g_emb[NH];
__device__ float g_E[NROWS * 1536];
__device__ float g_PRE[NROWS * 1536];
__device__ float g_GFp[NH];
__device__ float g_dh[2][BBATCH * HDIM];
__device__ float g_dc[2][BBATCH * HDIM];
__device__ float g_comb[BBATCH * HDIM];
__device__ float g_gd[BBATCH * HDIM];
__device__ float g_gi[BBATCH * HDIM];
__device__ float g_go[BBATCH * HDIM];
__device__ float g_tln[BBATCH * HDIM];
__device__ float g_Bfx[BBATCH * HDIM];
__device__ float g_Bd[BBATCH * 1536];
__device__ float g_p1[BBATCH * 8 * HDIM];
__device__ float g_p2[BBATCH * 8 * HDIM];
__device__ float g_cp[BBATCH * 8 * HDIM];

// bf16 split operands
__device__ __nv_bfloat16 g_Whi[1536 * 768];   // main weights, [n][k] (B operand layout)
__device__ __nv_bfloat16 g_Wlo[1536 * 768];
__device__ __nv_bfloat16 g_Wxhi[1536 * 256];  // Wx packed transposed
__device__ __nv_bfloat16 g_Wxlo[1536 * 256];
__device__ __nv_bfloat16 g_gfhi[256 * 256];   // gWh[3] transposed
__device__ __nv_bfloat16 g_gflo[256 * 256];
__device__ __nv_bfloat16 g_hhi[NH];
__device__ __nv_bfloat16 g_hlo[NH];
__device__ __nv_bfloat16 g_ehi[NH];
__device__ __nv_bfloat16 g_elo[NH];

// ---------------- low-level helpers ----------------
__device__ __forceinline__ uint32_t smem_to_u32(const void* smem_ptr) {
    uint32_t addr;
    asm("{ .reg .u64 tmp; cvta.to.shared.u64 tmp, %1; cvt.u32.u64 %0, tmp; }"
        : "=r"(addr) : "l"(smem_ptr));
    return addr;
}
__device__ __forceinline__ uint32_t swz(uint32_t off) { return off ^ ((off >> 3) & 0x70); }

__device__ __forceinline__ void cpasync16(uint32_t dst, const void* src, int sz) {
    asm volatile("cp.async.cg.shared.global [%0], [%1], 16, %2;"
                 :: "r"(dst), "l"(src), "r"(sz) : "memory");
}
__device__ __forceinline__ void cp_commit() {
    asm volatile("cp.async.commit_group;" ::: "memory");
}
__device__ __forceinline__ void cp_wait2() {
    asm volatile("cp.async.wait_group 2;" ::: "memory");
}
__device__ __forceinline__ void ldsm4(uint32_t& r0, uint32_t& r1, uint32_t& r2, uint32_t& r3,
                                      uint32_t addr) {
    asm volatile("ldmatrix.sync.aligned.m8n8.x4.shared.b16 {%0,%1,%2,%3}, [%4];"
                 : "=r"(r0), "=r"(r1), "=r"(r2), "=r"(r3) : "r"(addr));
}
__device__ __forceinline__ void mma16816(float* c, const uint32_t* a, const uint32_t* b) {
    asm volatile(
        "mma.sync.aligned.m16n8k16.row.col.f32.bf16.bf16.f32 "
        "{%0,%1,%2,%3}, {%4,%5,%6,%7}, {%8,%9}, {%0,%1,%2,%3};"
        : "+f"(c[0]), "+f"(c[1]), "+f"(c[2]), "+f"(c[3])
        : "r"(a[0]), "r"(a[1]), "r"(a[2]), "r"(a[3]), "r"(b[0]), "r"(b[1]));
}

__device__ __forceinline__ float sigf(float x) { return 1.f / (1.f + __expf(-x)); }

__device__ __forceinline__ float2 blk_reduce2(float a, float b) {
    __shared__ float sA[8], sB[8];
    int lane = threadIdx.x & 31, w = threadIdx.x >> 5;
#pragma unroll
    for (int o = 16; o; o >>= 1) {
        a += __shfl_xor_sync(0xffffffffu, a, o);
        b += __shfl_xor_sync(0xffffffffu, b, o);
    }
    __syncthreads();
    if (lane == 0) { sA[w] = a; sB[w] = b; }
    __syncthreads();
    float ra = 0.f, rb = 0.f;
#pragma unroll
    for (int i = 0; i < 8; i++) { ra += sA[i]; rb += sB[i]; }
    return make_float2(ra, rb);
}

__device__ __forceinline__ void bf_split(float v, __nv_bfloat16& h, __nv_bfloat16& l) {
    h = __float2bfloat16(v);
    l = __float2bfloat16(v - __bfloat162float(h));
}

// ---------------- prep: masked inputs ----------------
__global__ void prep_k(const float* __restrict__ word, const float* __restrict__ h0,
                       const float* __restrict__ c0, const float* __restrict__ mask,
                       float* __restrict__ emb, float* __restrict__ h, float* __restrict__ c) {
    int i4 = blockIdx.x * blockDim.x + threadIdx.x;
    if (i4 >= NH / 4) return;
    float m = mask[i4 >> 6];
    float4 w = ((const float4*)word)[i4];
    float4 a = ((const float4*)h0)[i4];
    float4 b = ((const float4*)c0)[i4];
    w.x *= m; w.y *= m; w.z *= m; w.w *= m;
    a.x *= m; a.y *= m; a.z *= m; a.w *= m;
    b.x *= m; b.y *= m; b.z *= m; b.w *= m;
    ((float4*)emb)[i4] = w;
    ((float4*)h)[i4]   = a;
    ((float4*)c)[i4]   = b;
}

// ---------------- column mean over L (two-stage) ----------------
__global__ void colpart_k(const float* __restrict__ X, float* __restrict__ part) {
    int b = blockIdx.x, s = blockIdx.y, c = threadIdx.x;
    float acc = 0.f;
    int rbase = (b << 10) + s * 128;
#pragma unroll 4
    for (int j = 0; j < 128; j++) acc += X[(size_t)(rbase + j) * HDIM + c];
    part[(b * 8 + s) * HDIM + c] = acc;
}
__global__ void colfin_k(const float* __restrict__ part, float* __restrict__ out) {
    int b = blockIdx.x, c = threadIdx.x;
    float a = 0.f;
#pragma unroll
    for (int s = 0; s < 8; s++) a += part[(b * 8 + s) * HDIM + c];
    out[b * HDIM + c] = a * (1.f / 1024.f);
}

// ---------------- bf16 split packing ----------------
__global__ void packW_k(const float* __restrict__ Wh_g, const float* __restrict__ Wi_g) {
    int idx = blockIdx.x * 256 + threadIdx.x;            // 1536*768
    if (idx >= 1536 * 768) return;
    int n = idx / 768, kk = idx - n * 768;
    int g = n >> 8, c = n & 255;
    float v = (kk < 512) ? Wh_g[g * 131072 + kk * 256 + c]
                         : Wi_g[g * 65536 + (kk - 512) * 256 + c];
    bf_split(v, g_Whi[idx], g_Wlo[idx]);
}
__global__ void packWx_k(const float* __restrict__ Wx_g) {
    int idx = blockIdx.x * 256 + threadIdx.x;            // 1536*256
    if (idx >= 1536 * 256) return;
    int n = idx / 256, k = idx - n * 256;
    int g = n >> 8, c = n & 255;
    bf_split(Wx_g[g * 65536 + k * 256 + c], g_Wxhi[idx], g_Wxlo[idx]);
}
__global__ void packGf_k(const float* __restrict__ gWh) {
    int idx = blockIdx.x * 256 + threadIdx.x;            // 256*256
    if (idx >= 256 * 256) return;
    int n = idx / 256, k = idx - n * 256;
    bf_split(gWh[3 * 65536 + k * 256 + n], g_gfhi[idx], g_gflo[idx]);
}
__global__ void split_k(const float4* __restrict__ src, uint2* __restrict__ hi,
                        uint2* __restrict__ lo) {
    int i = blockIdx.x * blockDim.x + threadIdx.x;       // NH/4
    float4 v = src[i];
    __nv_bfloat16 h0, h1, h2, h3, l0, l1, l2, l3;
    bf_split(v.x, h0, l0); bf_split(v.y, h1, l1);
    bf_split(v.z, h2, l2); bf_split(v.w, h3, l3);
    uint2 H, L;
    H.x = ((uint32_t)__bfloat16_as_ushort(h1) << 16) | __bfloat16_as_ushort(h0);
    H.y = ((uint32_t)__bfloat16_as_ushort(h3) << 16) | __bfloat16_as_ushort(h2);
    L.x = ((uint32_t)__bfloat16_as_ushort(l1) << 16) | __bfloat16_as_ushort(l0);
    L.y = ((uint32_t)__bfloat16_as_ushort(l3) << 16) | __bfloat16_as_ushort(l2);
    hi[i] = H; lo[i] = L;
}

// ---------------- bf16-split GEMM via legacy mma.sync (HMMA) ----------------
// C[NROWS x cols] = sum_{3 splits} A @ B^T (+Cadd +colbias +mask*pbias)
// CTA tile 128x64, K-stage 64 (128B rows, SW128), 3-stage cp.async pipeline.
// 256 threads, warp tile 32x32, ~80 regs/thread -> true 2 CTAs/SM without spills.
#define SMEM_MMA (3 * 24576)
template <bool TAPS>
__global__ __launch_bounds__(256, 2) void gemm_mma_k(
    const __nv_bfloat16* __restrict__ Ahi, const __nv_bfloat16* __restrict__ Alo,
    const __nv_bfloat16* __restrict__ Bhi, const __nv_bfloat16* __restrict__ Blo,
    const float* __restrict__ Cadd, const float* __restrict__ colbias,
    const float* __restrict__ pbias, const float* __restrict__ mask,
    float* __restrict__ C, int cols, int K) {
    extern __shared__ char sm[];
    const uint32_t sbase = smem_to_u32(sm);
    const int tid = threadIdx.x, wid = tid >> 5, lane = tid & 31;
    const int wm = wid >> 1, wn = wid & 1;         // 4 x 2 warp grid
    const int rowBase = blockIdx.y * 128;
    const int colBase = blockIdx.x * 64;
    const int KC = K >> 6;             // 64-elem chunks per split
    const int NC = 3 * KC;

    float acc[2][4][4];
#pragma unroll
    for (int a = 0; a < 2; a++)
#pragma unroll
        for (int b = 0; b < 4; b++)
#pragma unroll
            for (int d = 0; d < 4; d++) acc[a][b][d] = 0.f;

    auto issue = [&](int cc) {
        const int buf = cc % 3;
        const int split = cc / KC;
        const int kc = cc - split * KC;
        const __nv_bfloat16* Ab = (split == 1) ? Alo : Ahi;
        const __nv_bfloat16* Bb = (split == 2) ? Blo : Bhi;
        const int tap = TAPS ? (kc >> 2) : 2;
        const int chA = TAPS ? ((kc & 3) << 6) : (kc << 6);
        const int kB = kc << 6;
        const int d = (tap == 0) ? -1 : ((tap == 1) ? 1 : 0);
        const uint32_t sA = sbase + buf * 24576;
        const uint32_t sB = sA + 16384;
#pragma unroll
        for (int i = 0; i < 4; ++i) {
            int idx = tid + i * 256;                  // 0..1023 (128 rows x 8 vec)
            int r = idx >> 3, g = idx & 7;
            int grow = rowBase + r, l = grow & 1023;
            bool ok = (tap == 0) ? (l > 0) : ((tap == 1) ? (l < 1023) : true);
            const __nv_bfloat16* src = Ab + (size_t)(grow + (ok ? d : 0)) * 256 + chA + g * 8;
            cpasync16(sA + swz(r * 128 + g * 16), src, ok ? 16 : 0);
        }
#pragma unroll
        for (int i = 0; i < 2; ++i) {
            int idx = tid + i * 256;                  // 0..511 (64 rows x 8 vec)
            int n = idx >> 3, g = idx & 7;
            const __nv_bfloat16* src = Bb + (size_t)(colBase + n) * K + kB + g * 8;
            cpasync16(sB + swz(n * 128 + g * 16), src, 16);
        }
    };

    issue(0); cp_commit();
    issue(1); cp_commit();

    const int aRow = wm * 32 + (lane & 15);
    const int bRow = wn * 32 + (lane & 15);
    const int gSel = lane >> 4;

    for (int cc = 0; cc < NC; ++cc) {
        if (cc + 2 < NC) issue(cc + 2);
        cp_commit();
        cp_wait2();
        __syncthreads();
        const int buf = cc % 3;
        const uint32_t sA = sbase + buf * 24576;
        const uint32_t sB = sA + 16384;
#pragma unroll
        for (int ks = 0; ks < 4; ++ks) {
            uint32_t aT[2][4], bT[4][2];
            const int g = ks * 2 + gSel;
#pragma unroll
            for (int mt = 0; mt < 2; ++mt) {
                uint32_t addr = sA + swz((aRow + mt * 16) * 128 + g * 16);
                ldsm4(aT[mt][0], aT[mt][1], aT[mt][2], aT[mt][3], addr);
            }
#pragma unroll
            for (int bt = 0; bt < 2; ++bt) {
                uint32_t r0, r1, r2, r3;
                uint32_t addr = sB + swz((bRow + bt * 16) * 128 + g * 16);
                ldsm4(r0, r1, r2, r3, addr);
                bT[bt * 2 + 0][0] = r0; bT[bt * 2 + 0][1] = r2;
                bT[bt * 2 + 1][0] = r1; bT[bt * 2 + 1][1] = r3;
            }
#pragma unroll
            for (int mt = 0; mt < 2; ++mt)
#pragma unroll
                for (int nt = 0; nt < 4; ++nt)
                    mma16816(acc[mt][nt], aT[mt], bT[nt]);
        }
        __syncthreads();
    }

    // epilogue: direct frag stores with fused adds
#pragma unroll
    for (int mt = 0; mt < 2; ++mt) {
#pragma unroll
        for (int i = 0; i < 2; ++i) {
            int r = rowBase + wm * 32 + mt * 16 + (lane >> 2) + i * 8;
            float mk = mask[r];
            int bb = r >> 10;
            size_t rowoff = (size_t)r * cols;
#pragma unroll
            for (int nt = 0; nt < 4; ++nt) {
                int ccol = colBase + wn * 32 + nt * 8 + (lane & 3) * 2;
                float2 v = make_float2(acc[mt][nt][2 * i], acc[mt][nt][2 * i + 1]);
                if (Cadd) {
                    float2 a = *(const float2*)(Cadd + rowoff + ccol);
                    v.x += a.x; v.y += a.y;
                }
                if (colbias) {
                    float2 a = *(const float2*)(colbias + ccol);
                    v.x += a.x; v.y += a.y;
                }
                if (pbias) {
                    float2 p = *(const float2*)(pbias + (size_t)bb * cols + ccol);
                    v.x += mk * p.x; v.y += mk * p.y;
                }
                *(float2*)(C + rowoff + ccol) = v;
            }
        }
    }
}

// ---------------- sentence-level gates: gd / gi / go ----------------
__global__ void small_gates_k(const float* __restrict__ dh, const float* __restrict__ se,
                              const float* __restrict__ comb, const float* __restrict__ gWx,
                              const float* __restrict__ gWg, const float* __restrict__ gWh,
                              const float* __restrict__ gb, const float* __restrict__ ln_a,
                              const float* __restrict__ ln_b) {
    int b = blockIdx.x, g = blockIdx.y, c = threadIdx.x;
    __shared__ float sx[256], ss[256], sc[256];
    sx[c] = dh[b * 256 + c];
    ss[c] = se[b * 256 + c];
    sc[c] = comb[b * 256 + c];
    __syncthreads();
    const float* Wx = gWx + g * 65536;
    const float* Wg = gWg + g * 65536;
    const float* Wh = gWh + g * 65536;
    float acc = (g == 0) ? gb[c] : ((g == 2) ? gb[512 + c] : 0.f);
#pragma unroll 8
    for (int k = 0; k < 256; k++) {
        acc += sx[k] * Wx[k * 256 + c];
        acc += ss[k] * Wg[k * 256 + c];
        acc += sc[k] * Wh[k * 256 + c];
    }
    float2 r = blk_reduce2(acc, acc * acc);
    float mean = r.x * (1.f / 256.f);
    float sd2 = fmaxf(r.y - 256.f * mean * mean, 0.f);
    float invs = 1.f / (sqrtf(sd2 * (1.f / 255.f)) + EPSV);
    int lnrow = (g == 0) ? 6 : ((g == 1) ? 9 : 7);
    float y = ln_a[lnrow * 256 + c] * (acc - mean) * invs + ln_b[lnrow * 256 + c];
    if (g == 1) y += gb[256 + c];
    float sg = sigf(y);
    if (g == 0) g_gd[b * 256 + c] = sg;
    else if (g == 1) g_gi[b * 256 + c] = sg;
    else g_go[b * 256 + c] = sg;
}

// ---------------- per-batch biases: Bd = dh@Wd_g ; Bfx = dh@gWx3 ----------------
__global__ void bd_k(const float* __restrict__ dh, const float* __restrict__ Wd_g) {
    int b = blockIdx.x, g = blockIdx.y, c = threadIdx.x;
    __shared__ float sx[256];
    sx[c] = dh[b * 256 + c];
    __syncthreads();
    const float* W = Wd_g + g * 65536;
    float acc = 0.f;
#pragma unroll 8
    for (int k = 0; k < 256; k++) acc += sx[k] * W[k * 256 + c];
    g_Bd[b * 1536 + g * 256 + c] = acc;
}
__global__ void bfx_k(const float* __restrict__ dh, const float* __restrict__ gWx) {
    int b = blockIdx.x, c = threadIdx.x;
    __shared__ float sx[256];
    sx[c] = dh[b * 256 + c];
    __syncthreads();
    const float* W = gWx + 3 * 65536;
    float acc = 0.f;
#pragma unroll 8
    for (int k = 0; k < 256; k++) acc += sx[k] * W[k * 256 + c];
    g_Bfx[b * 256 + c] = acc;
}

// ---------------- layer-invariant: tln = tanh(ln(se @ gWg3)) ----------------
__global__ void tln_k(const float* __restrict__ se, const float* __restrict__ gWg,
                      const float* __restrict__ ln_a, const float* __restrict__ ln_b) {
    int b = blockIdx.x, c = threadIdx.x;
    __shared__ float ss[256];
    ss[c] = se[b * 256 + c];
    __syncthreads();
    const float* W = gWg + 3 * 65536;
    float acc = 0.f;
#pragma unroll 8
    for (int k = 0; k < 256; k++) acc += ss[k] * W[k * 256 + c];
    float2 r = blk_reduce2(acc, acc * acc);
    float mean = r.x * (1.f / 256.f);
    float sd2 = fmaxf(r.y - 256.f * mean * mean, 0.f);
    float invs = 1.f / (sqrtf(sd2 * (1.f / 255.f)) + EPSV);
    float y = ln_a[10 * 256 + c] * (acc - mean) * invs + ln_b[10 * 256 + c];
    g_tln[b * 256 + c] = tanhf(y);
}

// ---------------- fused gf LN + sigmoid + exp + score partial sums ----------------
__global__ void score_fused_k(const float* __restrict__ GFp, const float* __restrict__ Cc,
                              const float* __restrict__ mask, const float* __restrict__ ln_a,
                              const float* __restrict__ ln_b) {
    int b = blockIdx.x, s = blockIdx.y, c = threadIdx.x;
    int rbase = (b << 10) + s * 128;
    const float la = ln_a[8 * 256 + c];
    const float lb = ln_b[8 * 256 + c];
    float s1 = 0.f, s2 = 0.f;
    float xcur = GFp[(size_t)rbase * 256 + c];
    float ccur = Cc[(size_t)rbase * 256 + c];
    for (int j = 0; j < 128; ++j) {
        float xn = 0.f, cn = 0.f;
        if (j + 1 < 128) {
            xn = GFp[(size_t)(rbase + j + 1) * 256 + c];
            cn = Cc[(size_t)(rbase + j + 1) * 256 + c];
        }
        float2 r = blk_reduce2(xcur, xcur * xcur);
        float mean = r.x * (1.f / 256.f);
        float sd2 = fmaxf(r.y - 256.f * mean * mean, 0.f);
        float invs = 1.f / (sqrtf(sd2 * (1.f / 255.f)) + EPSV);
        float y = la * (xcur - mean) * invs + lb;
        float msm = mask[rbase + j] * 1e25f - 1e25f;
        float e = __expf(sigf(y) + msm);
        s1 += e;
        s2 += e * ccur;
        xcur = xn;
        ccur = cn;
    }
    g_p1[(b * 8 + s) * 256 + c] = s1;
    g_p2[(b * 8 + s) * 256 + c] = s2;
}

__global__ void score_fin_k(const float* __restrict__ dcOld, float* __restrict__ dhN,
                            float* __restrict__ dcN) {
    int b = blockIdx.x, c = threadIdx.x;
    int i = b * 256 + c;
    float S1 = 0.f, S2 = 0.f;
#pragma unroll
    for (int s = 0; s < 8; s++) {
        S1 += g_p1[(b * 8 + s) * 256 + c];
        S2 += g_p2[(b * 8 + s) * 256 + c];
    }
    float ed = __expf(g_gd[i]);
    float ei = __expf(g_gi[i]);
    float den = S1 + ed + ei;
    float dcn = (S2 + ed * dcOld[i] + ei * g_tln[i]) / den;
    dcN[i] = dcn;
    dhN[i] = g_go[i] * tanhf(dcn);
}

// ---------------- main epilogue: 6-gate LN + sigmoid + 5-softmax + state update ----------------
__global__ void gates_epi_k(const float* __restrict__ Cc, const float* __restrict__ dcOld,
                            const float* __restrict__ mask, const float* __restrict__ ln_a,
                            const float* __restrict__ ln_b, float* __restrict__ Hn,
                            float* __restrict__ Cn) {
    __shared__ float sP[6][256];
    __shared__ float sMean[6], sInv[6];
    int n = blockIdx.x, tid = threadIdx.x;
    size_t base = (size_t)n * 1536;
#pragma unroll
    for (int g = 0; g < 6; g++) sP[g][tid] = g_PRE[base + g * 256 + tid];
    __syncthreads();
    int w = tid >> 5, lane = tid & 31;
    if (w < 6) {
        float s = 0.f, q = 0.f;
#pragma unroll
        for (int j = 0; j < 8; j++) {
            float v = sP[w][lane + j * 32];
            s += v;
            q += v * v;
        }
#pragma unroll
        for (int o = 16; o; o >>= 1) {
            s += __shfl_xor_sync(0xffffffffu, s, o);
            q += __shfl_xor_sync(0xffffffffu, q, o);
        }
        if (lane == 0) {
            float mean = s * (1.f / 256.f);
            float sd2 = fmaxf(q - 256.f * mean * mean, 0.f);
            sMean[w] = mean;
            sInv[w] = 1.f / (sqrtf(sd2 * (1.f / 255.f)) + EPSV);
        }
    }
    __syncthreads();
    int c = tid;
    float sgm[6];
#pragma unroll
    for (int g = 0; g < 6; g++) {
        float y = ln_a[g * 256 + c] * (sP[g][c] - sMean[g]) * sInv[g] + ln_b[g * 256 + c];
        sgm[g] = sigf(y);
    }
    float e[5], es = 0.f;
#pragma unroll
    for (int g = 0; g < 5; g++) { e[g] = __expf(sgm[g]); es += e[g]; }
    float inv = 1.f / es;
    int l = n & 1023, b = n >> 10;
    float mk = mask[n];
    float cb = (l > 0) ? Cc[(size_t)(n - 1) * 256 + c] : 0.f;
    float ca = (l < 1023) ? Cc[(size_t)(n + 1) * 256 + c] : 0.f;
    float ccur = Cc[(size_t)n * 256 + c];
    float tdc = dcOld[b * 256 + c] * mk;
    float cnew = (cb * e[0] + ca * e[1] + g_emb[(size_t)n * 256 + c] * e[2] + tdc * e[3] + ccur * e[4]) * inv;
    float hnew = sgm[5] * tanhf(cnew) * mk;
    Hn[(size_t)n * 256 + c] = hnew;
    Cn[(size_t)n * 256 + c] = cnew * mk;
    __nv_bfloat16 bh, bl;
    bf_split(hnew, bh, bl);
    g_hhi[(size_t)n * 256 + c] = bh;
    g_hlo[(size_t)n * 256 + c] = bl;
}

// ---------------- host orchestration ----------------
extern "C" void kernel_launch(void* const* d_in, const int* in_sizes, int n_in,
                              void* d_out, int out_size) {
    const float* word = (const float*)d_in[0];
    const float* se   = (const float*)d_in[1];
    const float* mask = (const float*)d_in[2];
    const float* h0   = (const float*)d_in[3];
    const float* c0   = (const float*)d_in[4];
    const float* Wx_g = (const float*)d_in[5];
    const float* Wh_g = (const float*)d_in[6];
    const float* Wi_g = (const float*)d_in[7];
    const float* Wd_g = (const float*)d_in[8];
    const float* b_g  = (const float*)d_in[9];
    const float* gWx  = (const float*)d_in[10];
    const float* gWh  = (const float*)d_in[11];
    const float* gWg  = (const float*)d_in[12];
    const float* gb   = (const float*)d_in[13];
    const float* ln_a = (const float*)d_in[14];
    const float* ln_b = (const float*)d_in[15];
    float* out = (float*)d_out;

    cudaFuncSetAttribute(gemm_mma_k<true>,  cudaFuncAttributeMaxDynamicSharedMemorySize, SMEM_MMA);
    cudaFuncSetAttribute(gemm_mma_k<false>, cudaFuncAttributeMaxDynamicSharedMemorySize, SMEM_MMA);

    float *ph, *pc, *pemb, *pE, *pPRE, *pGFp, *pdh, *pdc, *pcomb, *pcp, *pBd, *pBfx;
    __nv_bfloat16 *pWhi, *pWlo, *pWxhi, *pWxlo, *pgfhi, *pgflo, *phhi, *phlo, *pehi, *pelo;
    cudaGetSymbolAddress((void**)&ph,    g_h);
    cudaGetSymbolAddress((void**)&pc,    g_c);
    cudaGetSymbolAddress((void**)&pemb,  g_emb);
    cudaGetSymbolAddress((void**)&pE,    g_E);
    cudaGetSymbolAddress((void**)&pPRE,  g_PRE);
    cudaGetSymbolAddress((void**)&pGFp,  g_GFp);
    cudaGetSymbolAddress((void**)&pdh,   g_dh);
    cudaGetSymbolAddress((void**)&pdc,   g_dc);
    cudaGetSymbolAddress((void**)&pcomb, g_comb);
    cudaGetSymbolAddress((void**)&pcp,   g_cp);
    cudaGetSymbolAddress((void**)&pBd,   g_Bd);
    cudaGetSymbolAddress((void**)&pBfx,  g_Bfx);
    cudaGetSymbolAddress((void**)&pWhi,  g_Whi);
    cudaGetSymbolAddress((void**)&pWlo,  g_Wlo);
    cudaGetSymbolAddress((void**)&pWxhi, g_Wxhi);
    cudaGetSymbolAddress((void**)&pWxlo, g_Wxlo);
    cudaGetSymbolAddress((void**)&pgfhi, g_gfhi);
    cudaGetSymbolAddress((void**)&pgflo, g_gflo);
    cudaGetSymbolAddress((void**)&phhi,  g_hhi);
    cudaGetSymbolAddress((void**)&phlo,  g_hlo);
    cudaGetSymbolAddress((void**)&pehi,  g_ehi);
    cudaGetSymbolAddress((void**)&pelo,  g_elo);

    const int SB = BBATCH * HDIM;

    // prep + initial means
    prep_k<<<NH / 1024, 256>>>(word, h0, c0, mask, pemb, ph, pc);
    colpart_k<<<dim3(32, 8), 256>>>(ph, pcp);
    colfin_k<<<32, 256>>>(pcp, pdh);
    colpart_k<<<dim3(32, 8), 256>>>(pc, pcp);
    colfin_k<<<32, 256>>>(pcp, pdc);

    // bf16 packing + layer-invariants
    packW_k<<<4608, 256>>>(Wh_g, Wi_g);
    packWx_k<<<1536, 256>>>(Wx_g);
    packGf_k<<<256, 256>>>(gWh);
    split_k<<<NH / 4 / 256, 256>>>((const float4*)pemb, (uint2*)pehi, (uint2*)pelo);
    split_k<<<NH / 4 / 256, 256>>>((const float4*)ph, (uint2*)phhi, (uint2*)phlo);
    tln_k<<<32, 256>>>(se, gWg, ln_a, ln_b);
    gemm_mma_k<false><<<dim3(24, 256), 256, SMEM_MMA>>>(
        pehi, pelo, pWxhi, pWxlo, nullptr, nullptr, nullptr, mask, pE, 1536, 256);

    for (int layer = 0; layer < 4; ++layer) {
        int cur = layer & 1, nxt = 1 - cur;
        float* hc = ph + (size_t)cur * NH;
        float* hn = ph + (size_t)nxt * NH;
        float* cc = pc + (size_t)cur * NH;
        float* cn = pc + (size_t)nxt * NH;
        float* dhc = pdh + cur * SB;
        float* dhn = pdh + nxt * SB;
        float* dcc = pdc + cur * SB;
        float* dcn = pdc + nxt * SB;
        float* htarget = (layer == 3) ? out : hn;

        colpart_k<<<dim3(32, 8), 256>>>(hc, pcp);
        colfin_k<<<32, 256>>>(pcp, pcomb);

        small_gates_k<<<dim3(32, 3), 256>>>(dhc, se, pcomb, gWx, gWg, gWh, gb, ln_a, ln_b);
        bd_k<<<dim3(32, 6), 256>>>(dhc, Wd_g);
        bfx_k<<<32, 256>>>(dhc, gWx);

        // gf path (K=256, N=256): LN+exp+partials fused
        gemm_mma_k<false><<<dim3(4, 256), 256, SMEM_MMA>>>(
            phhi, phlo, pgfhi, pgflo, nullptr, gb + 768, pBfx, mask, pGFp, 256, 256);
        score_fused_k<<<dim3(32, 8), 256>>>(pGFp, cc, mask, ln_a, ln_b);
        score_fin_k<<<32, 256>>>(dcc, dhn, dcn);

        // main pre-activation GEMM (3-tap conv over h) + fused E/bias epilogue
        gemm_mma_k<true><<<dim3(24, 256), 256, SMEM_MMA>>>(
            phhi, phlo, pWhi, pWlo, pE, b_g, pBd, mask, pPRE, 1536, 768);
        gates_epi_k<<<NROWS, 256>>>(cc, dcc, mask, ln_a, ln_b, htarget, cn);
    }
}

// round 11
// speedup vs baseline: 1.5157x; 1.5157x over previous
#include <cuda_runtime.h>
#include <cuda_bf16.h>
#include <math.h>
#include <stdint.h>

#define BBATCH 32
#define LSEQ   1024
#define HDIM   256
#define NROWS  (BBATCH * LSEQ)      // 32768
#define NH     (NROWS * HDIM)       // 8388608
#define EPSV   1e-3f

typedef unsigned long long ull;

// ---------------- scratch (__device__ globals; allocation is forbidden) ----------------
__device__ float g_h[2][NH];
__device__ float g_c[2][NH];
__device__ float g_emb[NH];
__device__ float g_E[NROWS * 1536];
__device__ float g_PRE[NROWS * 1536];
__device__ float g_GFp[NH];
__device__ float g_GF[NH];
__device__ float g_dh[2][BBATCH * HDIM];
__device__ float g_dc[2][BBATCH * HDIM];
__device__ float g_comb[BBATCH * HDIM];
__device__ float g_gd[BBATCH * HDIM];
__device__ float g_gi[BBATCH * HDIM];
__device__ float g_go[BBATCH * HDIM];
__device__ float g_tln[BBATCH * HDIM];
__device__ float g_Bfx[BBATCH * HDIM];
__device__ float g_Bd[BBATCH * 1536];
__device__ float g_p1[BBATCH * 8 * HDIM];
__device__ float g_p2[BBATCH * 8 * HDIM];
__device__ float g_cp[BBATCH * 8 * HDIM];

// bf16 split operands
__device__ __nv_bfloat16 g_Whi[1536 * 768];   // main weights, [n][k] (B operand layout)
__device__ __nv_bfloat16 g_Wlo[1536 * 768];
__device__ __nv_bfloat16 g_Wxhi[1536 * 256];  // Wx packed transposed
__device__ __nv_bfloat16 g_Wxlo[1536 * 256];
__device__ __nv_bfloat16 g_gfhi[256 * 256];   // gWh[3] transposed
__device__ __nv_bfloat16 g_gflo[256 * 256];
__device__ __nv_bfloat16 g_hhi[NH];
__device__ __nv_bfloat16 g_hlo[NH];
__device__ __nv_bfloat16 g_ehi[NH];
__device__ __nv_bfloat16 g_elo[NH];

// ---------------- low-level helpers ----------------
__device__ __forceinline__ uint32_t smem_to_u32(const void* smem_ptr) {
    uint32_t addr;
    asm("{ .reg .u64 tmp; cvta.to.shared.u64 tmp, %1; cvt.u32.u64 %0, tmp; }"
        : "=r"(addr) : "l"(smem_ptr));
    return addr;
}
__device__ __forceinline__ uint32_t swz(uint32_t off) { return off ^ ((off >> 3) & 0x70); }

__device__ __forceinline__ void cpasync16(uint32_t dst, const void* src, int sz) {
    asm volatile("cp.async.cg.shared.global [%0], [%1], 16, %2;"
                 :: "r"(dst), "l"(src), "r"(sz) : "memory");
}
__device__ __forceinline__ void cp_commit() {
    asm volatile("cp.async.commit_group;" ::: "memory");
}
__device__ __forceinline__ void cp_wait2() {
    asm volatile("cp.async.wait_group 2;" ::: "memory");
}
__device__ __forceinline__ void ldsm4(uint32_t& r0, uint32_t& r1, uint32_t& r2, uint32_t& r3,
                                      uint32_t addr) {
    asm volatile("ldmatrix.sync.aligned.m8n8.x4.shared.b16 {%0,%1,%2,%3}, [%4];"
                 : "=r"(r0), "=r"(r1), "=r"(r2), "=r"(r3) : "r"(addr));
}
__device__ __forceinline__ void mma16816(float* c, const uint32_t* a, const uint32_t* b) {
    asm volatile(
        "mma.sync.aligned.m16n8k16.row.col.f32.bf16.bf16.f32 "
        "{%0,%1,%2,%3}, {%4,%5,%6,%7}, {%8,%9}, {%0,%1,%2,%3};"
        : "+f"(c[0]), "+f"(c[1]), "+f"(c[2]), "+f"(c[3])
        : "r"(a[0]), "r"(a[1]), "r"(a[2]), "r"(a[3]), "r"(b[0]), "r"(b[1]));
}

__device__ __forceinline__ float sigf(float x) { return 1.f / (1.f + __expf(-x)); }

__device__ __forceinline__ float2 blk_reduce2(float a, float b) {
    __shared__ float sA[8], sB[8];
    int lane = threadIdx.x & 31, w = threadIdx.x >> 5;
#pragma unroll
    for (int o = 16; o; o >>= 1) {
        a += __shfl_xor_sync(0xffffffffu, a, o);
        b += __shfl_xor_sync(0xffffffffu, b, o);
    }
    __syncthreads();
    if (lane == 0) { sA[w] = a; sB[w] = b; }
    __syncthreads();
    float ra = 0.f, rb = 0.f;
#pragma unroll
    for (int i = 0; i < 8; i++) { ra += sA[i]; rb += sB[i]; }
    return make_float2(ra, rb);
}

__device__ __forceinline__ void bf_split(float v, __nv_bfloat16& h, __nv_bfloat16& l) {
    h = __float2bfloat16(v);
    l = __float2bfloat16(v - __bfloat162float(h));
}

// ---------------- prep: masked inputs ----------------
__global__ void prep_k(const float* __restrict__ word, const float* __restrict__ h0,
                       const float* __restrict__ c0, const float* __restrict__ mask,
                       float* __restrict__ emb, float* __restrict__ h, float* __restrict__ c) {
    int i4 = blockIdx.x * blockDim.x + threadIdx.x;
    if (i4 >= NH / 4) return;
    float m = mask[i4 >> 6];
    float4 w = ((const float4*)word)[i4];
    float4 a = ((const float4*)h0)[i4];
    float4 b = ((const float4*)c0)[i4];
    w.x *= m; w.y *= m; w.z *= m; w.w *= m;
    a.x *= m; a.y *= m; a.z *= m; a.w *= m;
    b.x *= m; b.y *= m; b.z *= m; b.w *= m;
    ((float4*)emb)[i4] = w;
    ((float4*)h)[i4]   = a;
    ((float4*)c)[i4]   = b;
}

// ---------------- column mean over L (two-stage) ----------------
__global__ void colpart_k(const float* __restrict__ X, float* __restrict__ part) {
    int b = blockIdx.x, s = blockIdx.y, c = threadIdx.x;
    float acc = 0.f;
    int rbase = (b << 10) + s * 128;
#pragma unroll 4
    for (int j = 0; j < 128; j++) acc += X[(size_t)(rbase + j) * HDIM + c];
    part[(b * 8 + s) * HDIM + c] = acc;
}
__global__ void colfin_k(const float* __restrict__ part, float* __restrict__ out) {
    int b = blockIdx.x, c = threadIdx.x;
    float a = 0.f;
#pragma unroll
    for (int s = 0; s < 8; s++) a += part[(b * 8 + s) * HDIM + c];
    out[b * HDIM + c] = a * (1.f / 1024.f);
}

// ---------------- bf16 split packing ----------------
__global__ void packW_k(const float* __restrict__ Wh_g, const float* __restrict__ Wi_g) {
    int idx = blockIdx.x * 256 + threadIdx.x;            // 1536*768
    if (idx >= 1536 * 768) return;
    int n = idx / 768, kk = idx - n * 768;
    int g = n >> 8, c = n & 255;
    float v = (kk < 512) ? Wh_g[g * 131072 + kk * 256 + c]
                         : Wi_g[g * 65536 + (kk - 512) * 256 + c];
    bf_split(v, g_Whi[idx], g_Wlo[idx]);
}
__global__ void packWx_k(const float* __restrict__ Wx_g) {
    int idx = blockIdx.x * 256 + threadIdx.x;            // 1536*256
    if (idx >= 1536 * 256) return;
    int n = idx / 256, k = idx - n * 256;
    int g = n >> 8, c = n & 255;
    bf_split(Wx_g[g * 65536 + k * 256 + c], g_Wxhi[idx], g_Wxlo[idx]);
}
__global__ void packGf_k(const float* __restrict__ gWh) {
    int idx = blockIdx.x * 256 + threadIdx.x;            // 256*256
    if (idx >= 256 * 256) return;
    int n = idx / 256, k = idx - n * 256;
    bf_split(gWh[3 * 65536 + k * 256 + n], g_gfhi[idx], g_gflo[idx]);
}
__global__ void split_k(const float4* __restrict__ src, uint2* __restrict__ hi,
                        uint2* __restrict__ lo) {
    int i = blockIdx.x * blockDim.x + threadIdx.x;       // NH/4
    float4 v = src[i];
    __nv_bfloat16 h0, h1, h2, h3, l0, l1, l2, l3;
    bf_split(v.x, h0, l0); bf_split(v.y, h1, l1);
    bf_split(v.z, h2, l2); bf_split(v.w, h3, l3);
    uint2 H, L;
    H.x = ((uint32_t)__bfloat16_as_ushort(h1) << 16) | __bfloat16_as_ushort(h0);
    H.y = ((uint32_t)__bfloat16_as_ushort(h3) << 16) | __bfloat16_as_ushort(h2);
    L.x = ((uint32_t)__bfloat16_as_ushort(l1) << 16) | __bfloat16_as_ushort(l0);
    L.y = ((uint32_t)__bfloat16_as_ushort(l3) << 16) | __bfloat16_as_ushort(l2);
    hi[i] = H; lo[i] = L;
}

// ---------------- bf16-split GEMM via legacy mma.sync (HMMA) ----------------
// C[NROWS x cols] = sum_{3 splits} A @ B^T (+Cadd +colbias +mask*pbias)
// CTA 128x128 (round-6 proven shape), K-stage 64 (128B rows, SW128),
// 4-stage cp.async pipeline with ONE barrier per chunk (issue-after-compute).
#define SMEM_MMA (4 * 32768)
template <bool TAPS>
__global__ __launch_bounds__(256) void gemm_mma_k(
    const __nv_bfloat16* __restrict__ Ahi, const __nv_bfloat16* __restrict__ Alo,
    const __nv_bfloat16* __restrict__ Bhi, const __nv_bfloat16* __restrict__ Blo,
    const float* __restrict__ Cadd, const float* __restrict__ colbias,
    const float* __restrict__ pbias, const float* __restrict__ mask,
    float* __restrict__ C, int cols, int K) {
    extern __shared__ char sm[];
    const uint32_t sbase = smem_to_u32(sm);
    const int tid = threadIdx.x, wid = tid >> 5, lane = tid & 31;
    const int wm = wid >> 2, wn = wid & 3;
    const int rowBase = blockIdx.y * 128;
    const int colBase = blockIdx.x * 128;
    const int KC = K >> 6;             // 64-elem chunks per split
    const int NC = 3 * KC;

    float acc[4][4][4];
#pragma unroll
    for (int a = 0; a < 4; a++)
#pragma unroll
        for (int b = 0; b < 4; b++)
#pragma unroll
            for (int d = 0; d < 4; d++) acc[a][b][d] = 0.f;

    auto issue = [&](int cc) {
        const int buf = cc & 3;
        const int split = cc / KC;
        const int kc = cc - split * KC;
        const __nv_bfloat16* Ab = (split == 1) ? Alo : Ahi;
        const __nv_bfloat16* Bb = (split == 2) ? Blo : Bhi;
        const int tap = TAPS ? (kc >> 2) : 2;
        const int chA = TAPS ? ((kc & 3) << 6) : (kc << 6);
        const int kB = kc << 6;
        const int d = (tap == 0) ? -1 : ((tap == 1) ? 1 : 0);
        const uint32_t sA = sbase + buf * 32768;
        const uint32_t sB = sA + 16384;
#pragma unroll
        for (int i = 0; i < 4; ++i) {
            int idx = tid + i * 256;                  // 0..1023
            int r = idx >> 3, g = idx & 7;
            int grow = rowBase + r, l = grow & 1023;
            bool ok = (tap == 0) ? (l > 0) : ((tap == 1) ? (l < 1023) : true);
            const __nv_bfloat16* src = Ab + (size_t)(grow + (ok ? d : 0)) * 256 + chA + g * 8;
            cpasync16(sA + swz(r * 128 + g * 16), src, ok ? 16 : 0);
        }
#pragma unroll
        for (int i = 0; i < 4; ++i) {
            int idx = tid + i * 256;
            int n = idx >> 3, g = idx & 7;
            const __nv_bfloat16* src = Bb + (size_t)(colBase + n) * K + kB + g * 8;
            cpasync16(sB + swz(n * 128 + g * 16), src, 16);
        }
    };

    issue(0); cp_commit();
    issue(1); cp_commit();
    issue(2); cp_commit();

    const int aRow = wm * 64 + (lane & 15);
    const int bRow = wn * 32 + (lane & 15);
    const int gSel = lane >> 4;

    for (int cc = 0; cc < NC; ++cc) {
        cp_wait2();
        __syncthreads();   // loads of cc visible + all warps done with cc-1 (buffer (cc+3)&3)
        const int buf = cc & 3;
        const uint32_t sA = sbase + buf * 32768;
        const uint32_t sB = sA + 16384;
#pragma unroll
        for (int ks = 0; ks < 4; ++ks) {
            uint32_t aT[4][4], bT[4][2];
            const int g = ks * 2 + gSel;
#pragma unroll
            for (int mt = 0; mt < 4; ++mt) {
                uint32_t addr = sA + swz((aRow + mt * 16) * 128 + g * 16);
                ldsm4(aT[mt][0], aT[mt][1], aT[mt][2], aT[mt][3], addr);
            }
#pragma unroll
            for (int bt = 0; bt < 2; ++bt) {
                uint32_t r0, r1, r2, r3;
                uint32_t addr = sB + swz((bRow + bt * 16) * 128 + g * 16);
                ldsm4(r0, r1, r2, r3, addr);
                bT[bt * 2 + 0][0] = r0; bT[bt * 2 + 0][1] = r2;
                bT[bt * 2 + 1][0] = r1; bT[bt * 2 + 1][1] = r3;
            }
#pragma unroll
            for (int mt = 0; mt < 4; ++mt)
#pragma unroll
                for (int nt = 0; nt < 4; ++nt)
                    mma16816(acc[mt][nt], aT[mt], bT[nt]);
        }
        if (cc + 3 < NC) issue(cc + 3);
        cp_commit();
    }

    // epilogue: direct frag stores with fused adds
#pragma unroll
    for (int mt = 0; mt < 4; ++mt) {
#pragma unroll
        for (int i = 0; i < 2; ++i) {
            int r = rowBase + wm * 64 + mt * 16 + (lane >> 2) + i * 8;
            float mk = mask[r];
            int bb = r >> 10;
            size_t rowoff = (size_t)r * cols;
#pragma unroll
            for (int nt = 0; nt < 4; ++nt) {
                int ccol = colBase + wn * 32 + nt * 8 + (lane & 3) * 2;
                float2 v = make_float2(acc[mt][nt][2 * i], acc[mt][nt][2 * i + 1]);
                if (Cadd) {
                    float2 a = *(const float2*)(Cadd + rowoff + ccol);
                    v.x += a.x; v.y += a.y;
                }
                if (colbias) {
                    float2 a = *(const float2*)(colbias + ccol);
                    v.x += a.x; v.y += a.y;
                }
                if (pbias) {
                    float2 p = *(const float2*)(pbias + (size_t)bb * cols + ccol);
                    v.x += mk * p.x; v.y += mk * p.y;
                }
                *(float2*)(C + rowoff + ccol) = v;
            }
        }
    }
}

// ---------------- sentence-level gates: gd / gi / go ----------------
__global__ void small_gates_k(const float* __restrict__ dh, const float* __restrict__ se,
                              const float* __restrict__ comb, const float* __restrict__ gWx,
                              const float* __restrict__ gWg, const float* __restrict__ gWh,
                              const float* __restrict__ gb, const float* __restrict__ ln_a,
                              const float* __restrict__ ln_b) {
    int b = blockIdx.x, g = blockIdx.y, c = threadIdx.x;
    __shared__ float sx[256], ss[256], sc[256];
    sx[c] = dh[b * 256 + c];
    ss[c] = se[b * 256 + c];
    sc[c] = comb[b * 256 + c];
    __syncthreads();
    const float* Wx = gWx + g * 65536;
    const float* Wg = gWg + g * 65536;
    const float* Wh = gWh + g * 65536;
    float acc = (g == 0) ? gb[c] : ((g == 2) ? gb[512 + c] : 0.f);
#pragma unroll 8
    for (int k = 0; k < 256; k++) {
        acc += sx[k] * Wx[k * 256 + c];
        acc += ss[k] * Wg[k * 256 + c];
        acc += sc[k] * Wh[k * 256 + c];
    }
    float2 r = blk_reduce2(acc, acc * acc);
    float mean = r.x * (1.f / 256.f);
    float sd2 = fmaxf(r.y - 256.f * mean * mean, 0.f);
    float invs = 1.f / (sqrtf(sd2 * (1.f / 255.f)) + EPSV);
    int lnrow = (g == 0) ? 6 : ((g == 1) ? 9 : 7);
    float y = ln_a[lnrow * 256 + c] * (acc - mean) * invs + ln_b[lnrow * 256 + c];
    if (g == 1) y += gb[256 + c];
    float sg = sigf(y);
    if (g == 0) g_gd[b * 256 + c] = sg;
    else if (g == 1) g_gi[b * 256 + c] = sg;
    else g_go[b * 256 + c] = sg;
}

// ---------------- per-batch biases: Bd = dh@Wd_g ; Bfx = dh@gWx3 ----------------
__global__ void bd_k(const float* __restrict__ dh, const float* __restrict__ Wd_g) {
    int b = blockIdx.x, g = blockIdx.y, c = threadIdx.x;
    __shared__ float sx[256];
    sx[c] = dh[b * 256 + c];
    __syncthreads();
    const float* W = Wd_g + g * 65536;
    float acc = 0.f;
#pragma unroll 8
    for (int k = 0; k < 256; k++) acc += sx[k] * W[k * 256 + c];
    g_Bd[b * 1536 + g * 256 + c] = acc;
}
__global__ void bfx_k(const float* __restrict__ dh, const float* __restrict__ gWx) {
    int b = blockIdx.x, c = threadIdx.x;
    __shared__ float sx[256];
    sx[c] = dh[b * 256 + c];
    __syncthreads();
    const float* W = gWx + 3 * 65536;
    float acc = 0.f;
#pragma unroll 8
    for (int k = 0; k < 256; k++) acc += sx[k] * W[k * 256 + c];
    g_Bfx[b * 256 + c] = acc;
}

// ---------------- layer-invariant: tln = tanh(ln(se @ gWg3)) ----------------
__global__ void tln_k(const float* __restrict__ se, const float* __restrict__ gWg,
                      const float* __restrict__ ln_a, const float* __restrict__ ln_b) {
    int b = blockIdx.x, c = threadIdx.x;
    __shared__ float ss[256];
    ss[c] = se[b * 256 + c];
    __syncthreads();
    const float* W = gWg + 3 * 65536;
    float acc = 0.f;
#pragma unroll 8
    for (int k = 0; k < 256; k++) acc += ss[k] * W[k * 256 + c];
    float2 r = blk_reduce2(acc, acc * acc);
    float mean = r.x * (1.f / 256.f);
    float sd2 = fmaxf(r.y - 256.f * mean * mean, 0.f);
    float invs = 1.f / (sqrtf(sd2 * (1.f / 255.f)) + EPSV);
    float y = ln_a[10 * 256 + c] * (acc - mean) * invs + ln_b[10 * 256 + c];
    g_tln[b * 256 + c] = tanhf(y);
}

// ---------------- gf: LN + sigmoid + mask offset ----------------
__global__ void gf_ln_k(const float* __restrict__ GFp, const float* __restrict__ mask,
                        const float* __restrict__ ln_a, const float* __restrict__ ln_b) {
    int n = blockIdx.x, c = threadIdx.x;
    float x = GFp[(size_t)n * 256 + c];
    float2 r = blk_reduce2(x, x * x);
    float mean = r.x * (1.f / 256.f);
    float sd2 = fmaxf(r.y - 256.f * mean * mean, 0.f);
    float invs = 1.f / (sqrtf(sd2 * (1.f / 255.f)) + EPSV);
    float y = ln_a[8 * 256 + c] * (x - mean) * invs + ln_b[8 * 256 + c];
    float msm = mask[n] * 1e25f - 1e25f;
    g_GF[(size_t)n * 256 + c] = sigf(y) + msm;
}

// ---------------- score exp-sum over L (partials) + finalize dc/dh ----------------
__global__ void score_part_k(const float* __restrict__ Cc) {
    int b = blockIdx.x, s = blockIdx.y, c = threadIdx.x;
    float s1 = 0.f, s2 = 0.f;
    int rbase = (b << 10) + s * 128;
    for (int j = 0; j < 128; j++) {
        size_t idx = (size_t)(rbase + j) * 256 + c;
        float e = __expf(g_GF[idx]);
        s1 += e;
        s2 += e * Cc[idx];
    }
    g_p1[(b * 8 + s) * 256 + c] = s1;
    g_p2[(b * 8 + s) * 256 + c] = s2;
}
__global__ void score_fin_k(const float* __restrict__ dcOld, float* __restrict__ dhN,
                            float* __restrict__ dcN) {
    int b = blockIdx.x, c = threadIdx.x;
    int i = b * 256 + c;
    float S1 = 0.f, S2 = 0.f;
#pragma unroll
    for (int s = 0; s < 8; s++) {
        S1 += g_p1[(b * 8 + s) * 256 + c];
        S2 += g_p2[(b * 8 + s) * 256 + c];
    }
    float ed = __expf(g_gd[i]);
    float ei = __expf(g_gi[i]);
    float den = S1 + ed + ei;
    float dcn = (S2 + ed * dcOld[i] + ei * g_tln[i]) / den;
    dcN[i] = dcn;
    dhN[i] = g_go[i] * tanhf(dcn);
}

// ---------------- main epilogue: 6-gate LN + sigmoid + 5-softmax + state update ----------------
// also emits the bf16 hi/lo split of h_new (next layer's GEMM A operand)
__global__ void gates_epi_k(const float* __restrict__ Cc, const float* __restrict__ dcOld,
                            const float* __restrict__ mask, const float* __restrict__ ln_a,
                            const float* __restrict__ ln_b, float* __restrict__ Hn,
                            float* __restrict__ Cn) {
    __shared__ float sP[6][256];
    __shared__ float sMean[6], sInv[6];
    int n = blockIdx.x, tid = threadIdx.x;
    size_t base = (size_t)n * 1536;
#pragma unroll
    for (int g = 0; g < 6; g++) sP[g][tid] = g_PRE[base + g * 256 + tid];
    __syncthreads();
    int w = tid >> 5, lane = tid & 31;
    if (w < 6) {
        float s = 0.f, q = 0.f;
#pragma unroll
        for (int j = 0; j < 8; j++) {
            float v = sP[w][lane + j * 32];
            s += v;
            q += v * v;
        }
#pragma unroll
        for (int o = 16; o; o >>= 1) {
            s += __shfl_xor_sync(0xffffffffu, s, o);
            q += __shfl_xor_sync(0xffffffffu, q, o);
        }
        if (lane == 0) {
            float mean = s * (1.f / 256.f);
            float sd2 = fmaxf(q - 256.f * mean * mean, 0.f);
            sMean[w] = mean;
            sInv[w] = 1.f / (sqrtf(sd2 * (1.f / 255.f)) + EPSV);
        }
    }
    __syncthreads();
    int c = tid;
    float sgm[6];
#pragma unroll
    for (int g = 0; g < 6; g++) {
        float y = ln_a[g * 256 + c] * (sP[g][c] - sMean[g]) * sInv[g] + ln_b[g * 256 + c];
        sgm[g] = sigf(y);
    }
    float e[5], es = 0.f;
#pragma unroll
    for (int g = 0; g < 5; g++) { e[g] = __expf(sgm[g]); es += e[g]; }
    float inv = 1.f / es;
    int l = n & 1023, b = n >> 10;
    float mk = mask[n];
    float cb = (l > 0) ? Cc[(size_t)(n - 1) * 256 + c] : 0.f;
    float ca = (l < 1023) ? Cc[(size_t)(n + 1) * 256 + c] : 0.f;
    float ccur = Cc[(size_t)n * 256 + c];
    float tdc = dcOld[b * 256 + c] * mk;
    float cnew = (cb * e[0] + ca * e[1] + g_emb[(size_t)n * 256 + c] * e[2] + tdc * e[3] + ccur * e[4]) * inv;
    float hnew = sgm[5] * tanhf(cnew) * mk;
    Hn[(size_t)n * 256 + c] = hnew;
    Cn[(size_t)n * 256 + c] = cnew * mk;
    __nv_bfloat16 bh, bl;
    bf_split(hnew, bh, bl);
    g_hhi[(size_t)n * 256 + c] = bh;
    g_hlo[(size_t)n * 256 + c] = bl;
}

// ---------------- host orchestration ----------------
extern "C" void kernel_launch(void* const* d_in, const int* in_sizes, int n_in,
                              void* d_out, int out_size) {
    const float* word = (const float*)d_in[0];
    const float* se   = (const float*)d_in[1];
    const float* mask = (const float*)d_in[2];
    const float* h0   = (const float*)d_in[3];
    const float* c0   = (const float*)d_in[4];
    const float* Wx_g = (const float*)d_in[5];
    const float* Wh_g = (const float*)d_in[6];
    const float* Wi_g = (const float*)d_in[7];
    const float* Wd_g = (const float*)d_in[8];
    const float* b_g  = (const float*)d_in[9];
    const float* gWx  = (const float*)d_in[10];
    const float* gWh  = (const float*)d_in[11];
    const float* gWg  = (const float*)d_in[12];
    const float* gb   = (const float*)d_in[13];
    const float* ln_a = (const float*)d_in[14];
    const float* ln_b = (const float*)d_in[15];
    float* out = (float*)d_out;

    cudaFuncSetAttribute(gemm_mma_k<true>,  cudaFuncAttributeMaxDynamicSharedMemorySize, SMEM_MMA);
    cudaFuncSetAttribute(gemm_mma_k<false>, cudaFuncAttributeMaxDynamicSharedMemorySize, SMEM_MMA);

    float *ph, *pc, *pemb, *pE, *pPRE, *pGFp, *pdh, *pdc, *pcomb, *pcp, *pBd, *pBfx;
    __nv_bfloat16 *pWhi, *pWlo, *pWxhi, *pWxlo, *pgfhi, *pgflo, *phhi, *phlo, *pehi, *pelo;
    cudaGetSymbolAddress((void**)&ph,    g_h);
    cudaGetSymbolAddress((void**)&pc,    g_c);
    cudaGetSymbolAddress((void**)&pemb,  g_emb);
    cudaGetSymbolAddress((void**)&pE,    g_E);
    cudaGetSymbolAddress((void**)&pPRE,  g_PRE);
    cudaGetSymbolAddress((void**)&pGFp,  g_GFp);
    cudaGetSymbolAddress((void**)&pdh,   g_dh);
    cudaGetSymbolAddress((void**)&pdc,   g_dc);
    cudaGetSymbolAddress((void**)&pcomb, g_comb);
    cudaGetSymbolAddress((void**)&pcp,   g_cp);
    cudaGetSymbolAddress((void**)&pBd,   g_Bd);
    cudaGetSymbolAddress((void**)&pBfx,  g_Bfx);
    cudaGetSymbolAddress((void**)&pWhi,  g_Whi);
    cudaGetSymbolAddress((void**)&pWlo,  g_Wlo);
    cudaGetSymbolAddress((void**)&pWxhi, g_Wxhi);
    cudaGetSymbolAddress((void**)&pWxlo, g_Wxlo);
    cudaGetSymbolAddress((void**)&pgfhi, g_gfhi);
    cudaGetSymbolAddress((void**)&pgflo, g_gflo);
    cudaGetSymbolAddress((void**)&phhi,  g_hhi);
    cudaGetSymbolAddress((void**)&phlo,  g_hlo);
    cudaGetSymbolAddress((void**)&pehi,  g_ehi);
    cudaGetSymbolAddress((void**)&pelo,  g_elo);

    const int SB = BBATCH * HDIM;

    // prep + initial means
    prep_k<<<NH / 1024, 256>>>(word, h0, c0, mask, pemb, ph, pc);
    colpart_k<<<dim3(32, 8), 256>>>(ph, pcp);
    colfin_k<<<32, 256>>>(pcp, pdh);
    colpart_k<<<dim3(32, 8), 256>>>(pc, pcp);
    colfin_k<<<32, 256>>>(pcp, pdc);

    // bf16 packing + layer-invariants
    packW_k<<<4608, 256>>>(Wh_g, Wi_g);
    packWx_k<<<1536, 256>>>(Wx_g);
    packGf_k<<<256, 256>>>(gWh);
    split_k<<<NH / 4 / 256, 256>>>((const float4*)pemb, (uint2*)pehi, (uint2*)pelo);
    split_k<<<NH / 4 / 256, 256>>>((const float4*)ph, (uint2*)phhi, (uint2*)phlo);
    tln_k<<<32, 256>>>(se, gWg, ln_a, ln_b);
    gemm_mma_k<false><<<dim3(12, 256), 256, SMEM_MMA>>>(
        pehi, pelo, pWxhi, pWxlo, nullptr, nullptr, nullptr, mask, pE, 1536, 256);

    for (int layer = 0; layer < 4; ++layer) {
        int cur = layer & 1, nxt = 1 - cur;
        float* hc = ph + (size_t)cur * NH;
        float* hn = ph + (size_t)nxt * NH;
        float* cc = pc + (size_t)cur * NH;
        float* cn = pc + (size_t)nxt * NH;
        float* dhc = pdh + cur * SB;
        float* dhn = pdh + nxt * SB;
        float* dcc = pdc + cur * SB;
        float* dcn = pdc + nxt * SB;
        float* htarget = (layer == 3) ? out : hn;

        colpart_k<<<dim3(32, 8), 256>>>(hc, pcp);
        colfin_k<<<32, 256>>>(pcp, pcomb);

        small_gates_k<<<dim3(32, 3), 256>>>(dhc, se, pcomb, gWx, gWg, gWh, gb, ln_a, ln_b);
        bd_k<<<dim3(32, 6), 256>>>(dhc, Wd_g);
        bfx_k<<<32, 256>>>(dhc, gWx);

        // gf path (K=256, N=256)
        gemm_mma_k<false><<<dim3(2, 256), 256, SMEM_MMA>>>(
            phhi, phlo, pgfhi, pgflo, nullptr, gb + 768, pBfx, mask, pGFp, 256, 256);
        gf_ln_k<<<NROWS, 256>>>(pGFp, mask, ln_a, ln_b);
        score_part_k<<<dim3(32, 8), 256>>>(cc);
        score_fin_k<<<32, 256>>>(dcc, dhn, dcn);

        // main pre-activation GEMM (3-tap conv over h) + fused E/bias epilogue
        gemm_mma_k<true><<<dim3(12, 256), 256, SMEM_MMA>>>(
            phhi, phlo, pWhi, pWlo, pE, b_g, pBd, mask, pPRE, 1536, 768);
        gates_epi_k<<<NROWS, 256>>>(cc, dcc, mask, ln_a, ln_b, htarget, cn);
    }
}

// round 12
// speedup vs baseline: 1.5710x; 1.0364x over previous
#include <cuda_runtime.h>
#include <cuda_bf16.h>
#include <math.h>
#include <stdint.h>

#define BBATCH 32
#define LSEQ   1024
#define HDIM   256
#define NROWS  (BBATCH * LSEQ)      // 32768
#define NH     (NROWS * HDIM)       // 8388608
#define EPSV   1e-3f

typedef unsigned long long ull;

// ---------------- scratch (__device__ globals; allocation is forbidden) ----------------
__device__ float g_h[2][NH];
__device__ float g_c[2][NH];
__device__ float g_emb[NH];
__device__ float g_E[NROWS * 1536];
__device__ float g_PRE[NROWS * 1536];
__device__ float g_GFp[NH];
__device__ float g_dh[2][BBATCH * HDIM];
__device__ float g_dc[2][BBATCH * HDIM];
__device__ float g_comb[BBATCH * HDIM];
__device__ float g_gd[BBATCH * HDIM];
__device__ float g_gi[BBATCH * HDIM];
__device__ float g_go[BBATCH * HDIM];
__device__ float g_tln[BBATCH * HDIM];
__device__ float g_Bfx[BBATCH * HDIM];
__device__ float g_Bd[BBATCH * 1536];
__device__ float g_p1[BBATCH * 64 * HDIM];   // per-warp partial slices
__device__ float g_p2[BBATCH * 64 * HDIM];
__device__ float g_cp[BBATCH * 8 * HDIM];

// bf16 split operands
__device__ __nv_bfloat16 g_Whi[1536 * 768];   // main weights, [n][k] (B operand layout)
__device__ __nv_bfloat16 g_Wlo[1536 * 768];
__device__ __nv_bfloat16 g_Wxhi[1536 * 256];  // Wx packed transposed
__device__ __nv_bfloat16 g_Wxlo[1536 * 256];
__device__ __nv_bfloat16 g_gfhi[256 * 256];   // gWh[3] transposed
__device__ __nv_bfloat16 g_gflo[256 * 256];
__device__ __nv_bfloat16 g_hhi[NH];
__device__ __nv_bfloat16 g_hlo[NH];
__device__ __nv_bfloat16 g_ehi[NH];
__device__ __nv_bfloat16 g_elo[NH];

// ---------------- low-level helpers ----------------
__device__ __forceinline__ uint32_t smem_to_u32(const void* smem_ptr) {
    uint32_t addr;
    asm("{ .reg .u64 tmp; cvta.to.shared.u64 tmp, %1; cvt.u32.u64 %0, tmp; }"
        : "=r"(addr) : "l"(smem_ptr));
    return addr;
}
__device__ __forceinline__ uint32_t swz(uint32_t off) { return off ^ ((off >> 3) & 0x70); }

__device__ __forceinline__ void cpasync16(uint32_t dst, const void* src, int sz) {
    asm volatile("cp.async.cg.shared.global [%0], [%1], 16, %2;"
                 :: "r"(dst), "l"(src), "r"(sz) : "memory");
}
__device__ __forceinline__ void cp_commit() {
    asm volatile("cp.async.commit_group;" ::: "memory");
}
__device__ __forceinline__ void cp_wait2() {
    asm volatile("cp.async.wait_group 2;" ::: "memory");
}
__device__ __forceinline__ void ldsm4(uint32_t& r0, uint32_t& r1, uint32_t& r2, uint32_t& r3,
                                      uint32_t addr) {
    asm volatile("ldmatrix.sync.aligned.m8n8.x4.shared.b16 {%0,%1,%2,%3}, [%4];"
                 : "=r"(r0), "=r"(r1), "=r"(r2), "=r"(r3) : "r"(addr));
}
__device__ __forceinline__ void mma16816(float* c, const uint32_t* a, const uint32_t* b) {
    asm volatile(
        "mma.sync.aligned.m16n8k16.row.col.f32.bf16.bf16.f32 "
        "{%0,%1,%2,%3}, {%4,%5,%6,%7}, {%8,%9}, {%0,%1,%2,%3};"
        : "+f"(c[0]), "+f"(c[1]), "+f"(c[2]), "+f"(c[3])
        : "r"(a[0]), "r"(a[1]), "r"(a[2]), "r"(a[3]), "r"(b[0]), "r"(b[1]));
}

__device__ __forceinline__ float sigf(float x) { return 1.f / (1.f + __expf(-x)); }

__device__ __forceinline__ float2 blk_reduce2(float a, float b) {
    __shared__ float sA[8], sB[8];
    int lane = threadIdx.x & 31, w = threadIdx.x >> 5;
#pragma unroll
    for (int o = 16; o; o >>= 1) {
        a += __shfl_xor_sync(0xffffffffu, a, o);
        b += __shfl_xor_sync(0xffffffffu, b, o);
    }
    __syncthreads();
    if (lane == 0) { sA[w] = a; sB[w] = b; }
    __syncthreads();
    float ra = 0.f, rb = 0.f;
#pragma unroll
    for (int i = 0; i < 8; i++) { ra += sA[i]; rb += sB[i]; }
    return make_float2(ra, rb);
}

__device__ __forceinline__ void bf_split(float v, __nv_bfloat16& h, __nv_bfloat16& l) {
    h = __float2bfloat16(v);
    l = __float2bfloat16(v - __bfloat162float(h));
}

// ---------------- prep: masked inputs ----------------
__global__ void prep_k(const float* __restrict__ word, const float* __restrict__ h0,
                       const float* __restrict__ c0, const float* __restrict__ mask,
                       float* __restrict__ emb, float* __restrict__ h, float* __restrict__ c) {
    int i4 = blockIdx.x * blockDim.x + threadIdx.x;
    if (i4 >= NH / 4) return;
    float m = mask[i4 >> 6];
    float4 w = ((const float4*)word)[i4];
    float4 a = ((const float4*)h0)[i4];
    float4 b = ((const float4*)c0)[i4];
    w.x *= m; w.y *= m; w.z *= m; w.w *= m;
    a.x *= m; a.y *= m; a.z *= m; a.w *= m;
    b.x *= m; b.y *= m; b.z *= m; b.w *= m;
    ((float4*)emb)[i4] = w;
    ((float4*)h)[i4]   = a;
    ((float4*)c)[i4]   = b;
}

// ---------------- column mean over L (two-stage) ----------------
__global__ void colpart_k(const float* __restrict__ X, float* __restrict__ part) {
    int b = blockIdx.x, s = blockIdx.y, c = threadIdx.x;
    float acc = 0.f;
    int rbase = (b << 10) + s * 128;
#pragma unroll 4
    for (int j = 0; j < 128; j++) acc += X[(size_t)(rbase + j) * HDIM + c];
    part[(b * 8 + s) * HDIM + c] = acc;
}
__global__ void colfin_k(const float* __restrict__ part, float* __restrict__ out) {
    int b = blockIdx.x, c = threadIdx.x;
    float a = 0.f;
#pragma unroll
    for (int s = 0; s < 8; s++) a += part[(b * 8 + s) * HDIM + c];
    out[b * HDIM + c] = a * (1.f / 1024.f);
}

// ---------------- bf16 split packing ----------------
__global__ void packW_k(const float* __restrict__ Wh_g, const float* __restrict__ Wi_g) {
    int idx = blockIdx.x * 256 + threadIdx.x;            // 1536*768
    if (idx >= 1536 * 768) return;
    int n = idx / 768, kk = idx - n * 768;
    int g = n >> 8, c = n & 255;
    float v = (kk < 512) ? Wh_g[g * 131072 + kk * 256 + c]
                         : Wi_g[g * 65536 + (kk - 512) * 256 + c];
    bf_split(v, g_Whi[idx], g_Wlo[idx]);
}
__global__ void packWx_k(const float* __restrict__ Wx_g) {
    int idx = blockIdx.x * 256 + threadIdx.x;            // 1536*256
    if (idx >= 1536 * 256) return;
    int n = idx / 256, k = idx - n * 256;
    int g = n >> 8, c = n & 255;
    bf_split(Wx_g[g * 65536 + k * 256 + c], g_Wxhi[idx], g_Wxlo[idx]);
}
__global__ void packGf_k(const float* __restrict__ gWh) {
    int idx = blockIdx.x * 256 + threadIdx.x;            // 256*256
    if (idx >= 256 * 256) return;
    int n = idx / 256, k = idx - n * 256;
    bf_split(gWh[3 * 65536 + k * 256 + n], g_gfhi[idx], g_gflo[idx]);
}
__global__ void split_k(const float4* __restrict__ src, uint2* __restrict__ hi,
                        uint2* __restrict__ lo) {
    int i = blockIdx.x * blockDim.x + threadIdx.x;       // NH/4
    float4 v = src[i];
    __nv_bfloat16 h0, h1, h2, h3, l0, l1, l2, l3;
    bf_split(v.x, h0, l0); bf_split(v.y, h1, l1);
    bf_split(v.z, h2, l2); bf_split(v.w, h3, l3);
    uint2 H, L;
    H.x = ((uint32_t)__bfloat16_as_ushort(h1) << 16) | __bfloat16_as_ushort(h0);
    H.y = ((uint32_t)__bfloat16_as_ushort(h3) << 16) | __bfloat16_as_ushort(h2);
    L.x = ((uint32_t)__bfloat16_as_ushort(l1) << 16) | __bfloat16_as_ushort(l0);
    L.y = ((uint32_t)__bfloat16_as_ushort(l3) << 16) | __bfloat16_as_ushort(l2);
    hi[i] = H; lo[i] = L;
}

// ---------------- bf16-split GEMM via legacy mma.sync (HMMA) ----------------
// C[NROWS x cols] = sum_{3 splits} A @ B^T (+Cadd +colbias +mask*pbias)
// CTA tile 256x128 (halved L2 traffic vs 128x128), K-stage 64, SW128,
// 4-stage cp.async pipeline, ONE barrier per chunk. 256 thr, warp tile 128x32.
#define SMEM_MMA (4 * 49152)
template <bool TAPS>
__global__ __launch_bounds__(256) void gemm_mma_k(
    const __nv_bfloat16* __restrict__ Ahi, const __nv_bfloat16* __restrict__ Alo,
    const __nv_bfloat16* __restrict__ Bhi, const __nv_bfloat16* __restrict__ Blo,
    const float* __restrict__ Cadd, const float* __restrict__ colbias,
    const float* __restrict__ pbias, const float* __restrict__ mask,
    float* __restrict__ C, int cols, int K) {
    extern __shared__ char sm[];
    const uint32_t sbase = smem_to_u32(sm);
    const int tid = threadIdx.x, wid = tid >> 5, lane = tid & 31;
    const int wm = wid >> 2, wn = wid & 3;         // 2 x 4 warp grid, warp = 128x32
    const int rowBase = blockIdx.y * 256;
    const int colBase = blockIdx.x * 128;
    const int KC = K >> 6;             // 64-elem chunks per split
    const int NC = 3 * KC;

    float acc[8][4][4];
#pragma unroll
    for (int a = 0; a < 8; a++)
#pragma unroll
        for (int b = 0; b < 4; b++)
#pragma unroll
            for (int d = 0; d < 4; d++) acc[a][b][d] = 0.f;

    auto issue = [&](int cc) {
        const int buf = cc & 3;
        const int split = cc / KC;
        const int kc = cc - split * KC;
        const __nv_bfloat16* Ab = (split == 1) ? Alo : Ahi;
        const __nv_bfloat16* Bb = (split == 2) ? Blo : Bhi;
        const int tap = TAPS ? (kc >> 2) : 2;
        const int chA = TAPS ? ((kc & 3) << 6) : (kc << 6);
        const int kB = kc << 6;
        const int d = (tap == 0) ? -1 : ((tap == 1) ? 1 : 0);
        const uint32_t sA = sbase + buf * 49152;   // 32KB A + 16KB B
        const uint32_t sB = sA + 32768;
#pragma unroll
        for (int i = 0; i < 8; ++i) {
            int idx = tid + i * 256;                  // 0..2047 (256 rows x 8 vec)
            int r = idx >> 3, g = idx & 7;
            int grow = rowBase + r, l = grow & 1023;
            bool ok = (tap == 0) ? (l > 0) : ((tap == 1) ? (l < 1023) : true);
            const __nv_bfloat16* src = Ab + (size_t)(grow + (ok ? d : 0)) * 256 + chA + g * 8;
            cpasync16(sA + swz(r * 128 + g * 16), src, ok ? 16 : 0);
        }
#pragma unroll
        for (int i = 0; i < 4; ++i) {
            int idx = tid + i * 256;                  // 0..1023 (128 n-rows x 8 vec)
            int n = idx >> 3, g = idx & 7;
            const __nv_bfloat16* src = Bb + (size_t)(colBase + n) * K + kB + g * 8;
            cpasync16(sB + swz(n * 128 + g * 16), src, 16);
        }
    };

    issue(0); cp_commit();
    issue(1); cp_commit();
    issue(2); cp_commit();

    const int aRow = wm * 128 + (lane & 15);
    const int bRow = wn * 32 + (lane & 15);
    const int gSel = lane >> 4;

    for (int cc = 0; cc < NC; ++cc) {
        cp_wait2();
        __syncthreads();   // loads of cc visible + all warps done with cc-1 (buffer (cc+3)&3)
        const int buf = cc & 3;
        const uint32_t sA = sbase + buf * 49152;
        const uint32_t sB = sA + 32768;
#pragma unroll
        for (int ks = 0; ks < 4; ++ks) {
            uint32_t aT[8][4], bT[4][2];
            const int g = ks * 2 + gSel;
#pragma unroll
            for (int bt = 0; bt < 2; ++bt) {
                uint32_t r0, r1, r2, r3;
                uint32_t addr = sB + swz((bRow + bt * 16) * 128 + g * 16);
                ldsm4(r0, r1, r2, r3, addr);
                bT[bt * 2 + 0][0] = r0; bT[bt * 2 + 0][1] = r2;
                bT[bt * 2 + 1][0] = r1; bT[bt * 2 + 1][1] = r3;
            }
#pragma unroll
            for (int mt = 0; mt < 8; ++mt) {
                uint32_t addr = sA + swz((aRow + mt * 16) * 128 + g * 16);
                ldsm4(aT[mt][0], aT[mt][1], aT[mt][2], aT[mt][3], addr);
            }
#pragma unroll
            for (int mt = 0; mt < 8; ++mt)
#pragma unroll
                for (int nt = 0; nt < 4; ++nt)
                    mma16816(acc[mt][nt], aT[mt], bT[nt]);
        }
        if (cc + 3 < NC) issue(cc + 3);
        cp_commit();
    }

    // epilogue: direct frag stores with fused adds
#pragma unroll
    for (int mt = 0; mt < 8; ++mt) {
#pragma unroll
        for (int i = 0; i < 2; ++i) {
            int r = rowBase + wm * 128 + mt * 16 + (lane >> 2) + i * 8;
            float mk = mask[r];
            int bb = r >> 10;
            size_t rowoff = (size_t)r * cols;
#pragma unroll
            for (int nt = 0; nt < 4; ++nt) {
                int ccol = colBase + wn * 32 + nt * 8 + (lane & 3) * 2;
                float2 v = make_float2(acc[mt][nt][2 * i], acc[mt][nt][2 * i + 1]);
                if (Cadd) {
                    float2 a = *(const float2*)(Cadd + rowoff + ccol);
                    v.x += a.x; v.y += a.y;
                }
                if (colbias) {
                    float2 a = *(const float2*)(colbias + ccol);
                    v.x += a.x; v.y += a.y;
                }
                if (pbias) {
                    float2 p = *(const float2*)(pbias + (size_t)bb * cols + ccol);
                    v.x += mk * p.x; v.y += mk * p.y;
                }
                *(float2*)(C + rowoff + ccol) = v;
            }
        }
    }
}

// ---------------- sentence-level gates: gd / gi / go ----------------
__global__ void small_gates_k(const float* __restrict__ dh, const float* __restrict__ se,
                              const float* __restrict__ comb, const float* __restrict__ gWx,
                              const float* __restrict__ gWg, const float* __restrict__ gWh,
                              const float* __restrict__ gb, const float* __restrict__ ln_a,
                              const float* __restrict__ ln_b) {
    int b = blockIdx.x, g = blockIdx.y, c = threadIdx.x;
    __shared__ float sx[256], ss[256], sc[256];
    sx[c] = dh[b * 256 + c];
    ss[c] = se[b * 256 + c];
    sc[c] = comb[b * 256 + c];
    __syncthreads();
    const float* Wx = gWx + g * 65536;
    const float* Wg = gWg + g * 65536;
    const float* Wh = gWh + g * 65536;
    float acc = (g == 0) ? gb[c] : ((g == 2) ? gb[512 + c] : 0.f);
#pragma unroll 8
    for (int k = 0; k < 256; k++) {
        acc += sx[k] * Wx[k * 256 + c];
        acc += ss[k] * Wg[k * 256 + c];
        acc += sc[k] * Wh[k * 256 + c];
    }
    float2 r = blk_reduce2(acc, acc * acc);
    float mean = r.x * (1.f / 256.f);
    float sd2 = fmaxf(r.y - 256.f * mean * mean, 0.f);
    float invs = 1.f / (sqrtf(sd2 * (1.f / 255.f)) + EPSV);
    int lnrow = (g == 0) ? 6 : ((g == 1) ? 9 : 7);
    float y = ln_a[lnrow * 256 + c] * (acc - mean) * invs + ln_b[lnrow * 256 + c];
    if (g == 1) y += gb[256 + c];
    float sg = sigf(y);
    if (g == 0) g_gd[b * 256 + c] = sg;
    else if (g == 1) g_gi[b * 256 + c] = sg;
    else g_go[b * 256 + c] = sg;
}

// ---------------- per-batch biases: Bd = dh@Wd_g ; Bfx = dh@gWx3 ----------------
__global__ void bd_k(const float* __restrict__ dh, const float* __restrict__ Wd_g) {
    int b = blockIdx.x, g = blockIdx.y, c = threadIdx.x;
    __shared__ float sx[256];
    sx[c] = dh[b * 256 + c];
    __syncthreads();
    const float* W = Wd_g + g * 65536;
    float acc = 0.f;
#pragma unroll 8
    for (int k = 0; k < 256; k++) acc += sx[k] * W[k * 256 + c];
    g_Bd[b * 1536 + g * 256 + c] = acc;
}
__global__ void bfx_k(const float* __restrict__ dh, const float* __restrict__ gWx) {
    int b = blockIdx.x, c = threadIdx.x;
    __shared__ float sx[256];
    sx[c] = dh[b * 256 + c];
    __syncthreads();
    const float* W = gWx + 3 * 65536;
    float acc = 0.f;
#pragma unroll 8
    for (int k = 0; k < 256; k++) acc += sx[k] * W[k * 256 + c];
    g_Bfx[b * 256 + c] = acc;
}

// ---------------- layer-invariant: tln = tanh(ln(se @ gWg3)) ----------------
__global__ void tln_k(const float* __restrict__ se, const float* __restrict__ gWg,
                      const float* __restrict__ ln_a, const float* __restrict__ ln_b) {
    int b = blockIdx.x, c = threadIdx.x;
    __shared__ float ss[256];
    ss[c] = se[b * 256 + c];
    __syncthreads();
    const float* W = gWg + 3 * 65536;
    float acc = 0.f;
#pragma unroll 8
    for (int k = 0; k < 256; k++) acc += ss[k] * W[k * 256 + c];
    float2 r = blk_reduce2(acc, acc * acc);
    float mean = r.x * (1.f / 256.f);
    float sd2 = fmaxf(r.y - 256.f * mean * mean, 0.f);
    float invs = 1.f / (sqrtf(sd2 * (1.f / 255.f)) + EPSV);
    float y = ln_a[10 * 256 + c] * (acc - mean) * invs + ln_b[10 * 256 + c];
    g_tln[b * 256 + c] = tanhf(y);
}

// ---------------- fused gf LN + sigmoid + exp + score partials (warp-per-row) ----------------
// Each warp LNs one row at a time via shuffle reductions (no block barriers),
// accumulating per-channel exp sums over its 16 rows into its own partial slice.
__global__ void score_ln_part_k(const float* __restrict__ GFp, const float* __restrict__ Cc,
                                const float* __restrict__ mask, const float* __restrict__ ln_a,
                                const float* __restrict__ ln_b) {
    int b = blockIdx.x, s = blockIdx.y;
    int w = threadIdx.x >> 5, lane = threadIdx.x & 31;
    int rbase = (b << 10) + s * 128 + w * 16;
    float la[8], lb[8];
#pragma unroll
    for (int j = 0; j < 8; ++j) {
        la[j] = ln_a[8 * 256 + lane + 32 * j];
        lb[j] = ln_b[8 * 256 + lane + 32 * j];
    }
    float s1[8], s2[8];
#pragma unroll
    for (int j = 0; j < 8; ++j) { s1[j] = 0.f; s2[j] = 0.f; }
    for (int r16 = 0; r16 < 16; ++r16) {
        int row = rbase + r16;
        size_t off = (size_t)row * 256;
        float x[8], cv[8];
        float sum = 0.f, sq = 0.f;
#pragma unroll
        for (int j = 0; j < 8; ++j) {
            x[j] = GFp[off + lane + 32 * j];
            cv[j] = Cc[off + lane + 32 * j];
            sum += x[j];
            sq += x[j] * x[j];
        }
#pragma unroll
        for (int o = 16; o; o >>= 1) {
            sum += __shfl_xor_sync(0xffffffffu, sum, o);
            sq  += __shfl_xor_sync(0xffffffffu, sq, o);
        }
        float mean = sum * (1.f / 256.f);
        float sd2 = fmaxf(sq - 256.f * mean * mean, 0.f);
        float invs = 1.f / (sqrtf(sd2 * (1.f / 255.f)) + EPSV);
        float msm = mask[row] * 1e25f - 1e25f;
#pragma unroll
        for (int j = 0; j < 8; ++j) {
            float y = la[j] * (x[j] - mean) * invs + lb[j];
            float e = __expf(sigf(y) + msm);
            s1[j] += e;
            s2[j] += e * cv[j];
        }
    }
    int slice = b * 64 + s * 8 + w;
#pragma unroll
    for (int j = 0; j < 8; ++j) {
        g_p1[slice * 256 + lane + 32 * j] = s1[j];
        g_p2[slice * 256 + lane + 32 * j] = s2[j];
    }
}

__global__ void score_fin_k(const float* __restrict__ dcOld, float* __restrict__ dhN,
                            float* __restrict__ dcN) {
    int b = blockIdx.x, c = threadIdx.x;
    int i = b * 256 + c;
    float S1 = 0.f, S2 = 0.f;
#pragma unroll 8
    for (int s = 0; s < 64; s++) {
        S1 += g_p1[(b * 64 + s) * 256 + c];
        S2 += g_p2[(b * 64 + s) * 256 + c];
    }
    float ed = __expf(g_gd[i]);
    float ei = __expf(g_gi[i]);
    float den = S1 + ed + ei;
    float dcn = (S2 + ed * dcOld[i] + ei * g_tln[i]) / den;
    dcN[i] = dcn;
    dhN[i] = g_go[i] * tanhf(dcn);
}

// ---------------- main epilogue: 6-gate LN + sigmoid + 5-softmax + state update ----------------
// also emits the bf16 hi/lo split of h_new (next layer's GEMM A operand)
__global__ void gates_epi_k(const float* __restrict__ Cc, const float* __restrict__ dcOld,
                            const float* __restrict__ mask, const float* __restrict__ ln_a,
                            const float* __restrict__ ln_b, float* __restrict__ Hn,
                            float* __restrict__ Cn) {
    __shared__ float sP[6][256];
    __shared__ float sMean[6], sInv[6];
    int n = blockIdx.x, tid = threadIdx.x;
    size_t base = (size_t)n * 1536;
#pragma unroll
    for (int g = 0; g < 6; g++) sP[g][tid] = g_PRE[base + g * 256 + tid];
    __syncthreads();
    int w = tid >> 5, lane = tid & 31;
    if (w < 6) {
        float s = 0.f, q = 0.f;
#pragma unroll
        for (int j = 0; j < 8; j++) {
            float v = sP[w][lane + j * 32];
            s += v;
            q += v * v;
        }
#pragma unroll
        for (int o = 16; o; o >>= 1) {
            s += __shfl_xor_sync(0xffffffffu, s, o);
            q += __shfl_xor_sync(0xffffffffu, q, o);
        }
        if (lane == 0) {
            float mean = s * (1.f / 256.f);
            float sd2 = fmaxf(q - 256.f * mean * mean, 0.f);
            sMean[w] = mean;
            sInv[w] = 1.f / (sqrtf(sd2 * (1.f / 255.f)) + EPSV);
        }
    }
    __syncthreads();
    int c = tid;
    float sgm[6];
#pragma unroll
    for (int g = 0; g < 6; g++) {
        float y = ln_a[g * 256 + c] * (sP[g][c] - sMean[g]) * sInv[g] + ln_b[g * 256 + c];
        sgm[g] = sigf(y);
    }
    float e[5], es = 0.f;
#pragma unroll
    for (int g = 0; g < 5; g++) { e[g] = __expf(sgm[g]); es += e[g]; }
    float inv = 1.f / es;
    int l = n & 1023, b = n >> 10;
    float mk = mask[n];
    float cb = (l > 0) ? Cc[(size_t)(n - 1) * 256 + c] : 0.f;
    float ca = (l < 1023) ? Cc[(size_t)(n + 1) * 256 + c] : 0.f;
    float ccur = Cc[(size_t)n * 256 + c];
    float tdc = dcOld[b * 256 + c] * mk;
    float cnew = (cb * e[0] + ca * e[1] + g_emb[(size_t)n * 256 + c] * e[2] + tdc * e[3] + ccur * e[4]) * inv;
    float hnew = sgm[5] * tanhf(cnew) * mk;
    Hn[(size_t)n * 256 + c] = hnew;
    Cn[(size_t)n * 256 + c] = cnew * mk;
    __nv_bfloat16 bh, bl;
    bf_split(hnew, bh, bl);
    g_hhi[(size_t)n * 256 + c] = bh;
    g_hlo[(size_t)n * 256 + c] = bl;
}

// ---------------- host orchestration ----------------
extern "C" void kernel_launch(void* const* d_in, const int* in_sizes, int n_in,
                              void* d_out, int out_size) {
    const float* word = (const float*)d_in[0];
    const float* se   = (const float*)d_in[1];
    const float* mask = (const float*)d_in[2];
    const float* h0   = (const float*)d_in[3];
    const float* c0   = (const float*)d_in[4];
    const float* Wx_g = (const float*)d_in[5];
    const float* Wh_g = (const float*)d_in[6];
    const float* Wi_g = (const float*)d_in[7];
    const float* Wd_g = (const float*)d_in[8];
    const float* b_g  = (const float*)d_in[9];
    const float* gWx  = (const float*)d_in[10];
    const float* gWh  = (const float*)d_in[11];
    const float* gWg  = (const float*)d_in[12];
    const float* gb   = (const float*)d_in[13];
    const float* ln_a = (const float*)d_in[14];
    const float* ln_b = (const float*)d_in[15];
    float* out = (float*)d_out;

    cudaFuncSetAttribute(gemm_mma_k<true>,  cudaFuncAttributeMaxDynamicSharedMemorySize, SMEM_MMA);
    cudaFuncSetAttribute(gemm_mma_k<false>, cudaFuncAttributeMaxDynamicSharedMemorySize, SMEM_MMA);

    float *ph, *pc, *pemb, *pE, *pPRE, *pGFp, *pdh, *pdc, *pcomb, *pcp, *pBd, *pBfx;
    __nv_bfloat16 *pWhi, *pWlo, *pWxhi, *pWxlo, *pgfhi, *pgflo, *phhi, *phlo, *pehi, *pelo;
    cudaGetSymbolAddress((void**)&ph,    g_h);
    cudaGetSymbolAddress((void**)&pc,    g_c);
    cudaGetSymbolAddress((void**)&pemb,  g_emb);
    cudaGetSymbolAddress((void**)&pE,    g_E);
    cudaGetSymbolAddress((void**)&pPRE,  g_PRE);
    cudaGetSymbolAddress((void**)&pGFp,  g_GFp);
    cudaGetSymbolAddress((void**)&pdh,   g_dh);
    cudaGetSymbolAddress((void**)&pdc,   g_dc);
    cudaGetSymbolAddress((void**)&pcomb, g_comb);
    cudaGetSymbolAddress((void**)&pcp,   g_cp);
    cudaGetSymbolAddress((void**)&pBd,   g_Bd);
    cudaGetSymbolAddress((void**)&pBfx,  g_Bfx);
    cudaGetSymbolAddress((void**)&pWhi,  g_Whi);
    cudaGetSymbolAddress((void**)&pWlo,  g_Wlo);
    cudaGetSymbolAddress((void**)&pWxhi, g_Wxhi);
    cudaGetSymbolAddress((void**)&pWxlo, g_Wxlo);
    cudaGetSymbolAddress((void**)&pgfhi, g_gfhi);
    cudaGetSymbolAddress((void**)&pgflo, g_gflo);
    cudaGetSymbolAddress((void**)&phhi,  g_hhi);
    cudaGetSymbolAddress((void**)&phlo,  g_hlo);
    cudaGetSymbolAddress((void**)&pehi,  g_ehi);
    cudaGetSymbolAddress((void**)&pelo,  g_elo);

    const int SB = BBATCH * HDIM;

    // prep + initial means
    prep_k<<<NH / 1024, 256>>>(word, h0, c0, mask, pemb, ph, pc);
    colpart_k<<<dim3(32, 8), 256>>>(ph, pcp);
    colfin_k<<<32, 256>>>(pcp, pdh);
    colpart_k<<<dim3(32, 8), 256>>>(pc, pcp);
    colfin_k<<<32, 256>>>(pcp, pdc);

    // bf16 packing + layer-invariants
    packW_k<<<4608, 256>>>(Wh_g, Wi_g);
    packWx_k<<<1536, 256>>>(Wx_g);
    packGf_k<<<256, 256>>>(gWh);
    split_k<<<NH / 4 / 256, 256>>>((const float4*)pemb, (uint2*)pehi, (uint2*)pelo);
    split_k<<<NH / 4 / 256, 256>>>((const float4*)ph, (uint2*)phhi, (uint2*)phlo);
    tln_k<<<32, 256>>>(se, gWg, ln_a, ln_b);
    gemm_mma_k<false><<<dim3(12, 128), 256, SMEM_MMA>>>(
        pehi, pelo, pWxhi, pWxlo, nullptr, nullptr, nullptr, mask, pE, 1536, 256);

    for (int layer = 0; layer < 4; ++layer) {
        int cur = layer & 1, nxt = 1 - cur;
        float* hc = ph + (size_t)cur * NH;
        float* hn = ph + (size_t)nxt * NH;
        float* cc = pc + (size_t)cur * NH;
        float* cn = pc + (size_t)nxt * NH;
        float* dhc = pdh + cur * SB;
        float* dhn = pdh + nxt * SB;
        float* dcc = pdc + cur * SB;
        float* dcn = pdc + nxt * SB;
        float* htarget = (layer == 3) ? out : hn;

        colpart_k<<<dim3(32, 8), 256>>>(hc, pcp);
        colfin_k<<<32, 256>>>(pcp, pcomb);

        small_gates_k<<<dim3(32, 3), 256>>>(dhc, se, pcomb, gWx, gWg, gWh, gb, ln_a, ln_b);
        bd_k<<<dim3(32, 6), 256>>>(dhc, Wd_g);
        bfx_k<<<32, 256>>>(dhc, gWx);

        // gf path (K=256, N=256): GEMM then fused warp-level LN+exp+partials
        gemm_mma_k<false><<<dim3(2, 128), 256, SMEM_MMA>>>(
            phhi, phlo, pgfhi, pgflo, nullptr, gb + 768, pBfx, mask, pGFp, 256, 256);
        score_ln_part_k<<<dim3(32, 8), 256>>>(pGFp, cc, mask, ln_a, ln_b);
        score_fin_k<<<32, 256>>>(dcc, dhn, dcn);

        // main pre-activation GEMM (3-tap conv over h) + fused E/bias epilogue
        gemm_mma_k<true><<<dim3(12, 128), 256, SMEM_MMA>>>(
            phhi, phlo, pWhi, pWlo, pE, b_g, pBd, mask, pPRE, 1536, 768);
        gates_epi_k<<<NROWS, 256>>>(cc, dcc, mask, ln_a, ln_b, htarget, cn);
    }
}

// round 13
// speedup vs baseline: 2.0159x; 1.2832x over previous
#include <cuda_runtime.h>
#include <cuda_fp16.h>
#include <math.h>
#include <stdint.h>

#define BBATCH 32
#define LSEQ   1024
#define HDIM   256
#define NROWS  (BBATCH * LSEQ)      // 32768
#define NH     (NROWS * HDIM)       // 8388608
#define EPSV   1e-3f

typedef unsigned long long ull;

// ---------------- scratch (__device__ globals; allocation is forbidden) ----------------
__device__ float g_h[2][NH];
__device__ float g_c[2][NH];
__device__ float g_emb[NH];
__device__ float g_E[NROWS * 1536];
__device__ float g_PRE[NROWS * 1536];
__device__ float g_GFp[NH];
__device__ float g_dh[2][BBATCH * HDIM];
__device__ float g_dc[2][BBATCH * HDIM];
__device__ float g_comb[BBATCH * HDIM];
__device__ float g_gd[BBATCH * HDIM];
__device__ float g_gi[BBATCH * HDIM];
__device__ float g_go[BBATCH * HDIM];
__device__ float g_tln[BBATCH * HDIM];
__device__ float g_Bfx[BBATCH * HDIM];
__device__ float g_Bd[BBATCH * 1536];
__device__ float g_p1[BBATCH * 64 * HDIM];   // per-warp partial slices
__device__ float g_p2[BBATCH * 64 * HDIM];
__device__ float g_cp[BBATCH * 8 * HDIM];

// fp16 operands: A 2-split (hi+lo), B single fp16
__device__ __half g_Wf[1536 * 768];    // main weights, [n][k] (B operand layout)
__device__ __half g_Wxf[1536 * 256];   // Wx packed transposed
__device__ __half g_gff[256 * 256];    // gWh[3] transposed
__device__ __half g_hhi[NH];
__device__ __half g_hlo[NH];
__device__ __half g_ehi[NH];
__device__ __half g_elo[NH];

// ---------------- low-level helpers ----------------
__device__ __forceinline__ uint32_t smem_to_u32(const void* smem_ptr) {
    uint32_t addr;
    asm("{ .reg .u64 tmp; cvta.to.shared.u64 tmp, %1; cvt.u32.u64 %0, tmp; }"
        : "=r"(addr) : "l"(smem_ptr));
    return addr;
}
__device__ __forceinline__ uint32_t swz(uint32_t off) { return off ^ ((off >> 3) & 0x70); }

__device__ __forceinline__ void cpasync16(uint32_t dst, const void* src, int sz) {
    asm volatile("cp.async.cg.shared.global [%0], [%1], 16, %2;"
                 :: "r"(dst), "l"(src), "r"(sz) : "memory");
}
__device__ __forceinline__ void cp_commit() {
    asm volatile("cp.async.commit_group;" ::: "memory");
}
__device__ __forceinline__ void cp_wait2() {
    asm volatile("cp.async.wait_group 2;" ::: "memory");
}
__device__ __forceinline__ void ldsm4(uint32_t& r0, uint32_t& r1, uint32_t& r2, uint32_t& r3,
                                      uint32_t addr) {
    asm volatile("ldmatrix.sync.aligned.m8n8.x4.shared.b16 {%0,%1,%2,%3}, [%4];"
                 : "=r"(r0), "=r"(r1), "=r"(r2), "=r"(r3) : "r"(addr));
}
__device__ __forceinline__ void mma16816(float* c, const uint32_t* a, const uint32_t* b) {
    asm volatile(
        "mma.sync.aligned.m16n8k16.row.col.f32.f16.f16.f32 "
        "{%0,%1,%2,%3}, {%4,%5,%6,%7}, {%8,%9}, {%0,%1,%2,%3};"
        : "+f"(c[0]), "+f"(c[1]), "+f"(c[2]), "+f"(c[3])
        : "r"(a[0]), "r"(a[1]), "r"(a[2]), "r"(a[3]), "r"(b[0]), "r"(b[1]));
}

__device__ __forceinline__ float sigf(float x) { return 1.f / (1.f + __expf(-x)); }

__device__ __forceinline__ float2 blk_reduce2(float a, float b) {
    __shared__ float sA[8], sB[8];
    int lane = threadIdx.x & 31, w = threadIdx.x >> 5;
#pragma unroll
    for (int o = 16; o; o >>= 1) {
        a += __shfl_xor_sync(0xffffffffu, a, o);
        b += __shfl_xor_sync(0xffffffffu, b, o);
    }
    __syncthreads();
    if (lane == 0) { sA[w] = a; sB[w] = b; }
    __syncthreads();
    float ra = 0.f, rb = 0.f;
#pragma unroll
    for (int i = 0; i < 8; i++) { ra += sA[i]; rb += sB[i]; }
    return make_float2(ra, rb);
}

__device__ __forceinline__ void h_split(float v, __half& h, __half& l) {
    h = __float2half_rn(v);
    l = __float2half_rn(v - __half2float(h));
}

// ---------------- prep: masked inputs ----------------
__global__ void prep_k(const float* __restrict__ word, const float* __restrict__ h0,
                       const float* __restrict__ c0, const float* __restrict__ mask,
                       float* __restrict__ emb, float* __restrict__ h, float* __restrict__ c) {
    int i4 = blockIdx.x * blockDim.x + threadIdx.x;
    if (i4 >= NH / 4) return;
    float m = mask[i4 >> 6];
    float4 w = ((const float4*)word)[i4];
    float4 a = ((const float4*)h0)[i4];
    float4 b = ((const float4*)c0)[i4];
    w.x *= m; w.y *= m; w.z *= m; w.w *= m;
    a.x *= m; a.y *= m; a.z *= m; a.w *= m;
    b.x *= m; b.y *= m; b.z *= m; b.w *= m;
    ((float4*)emb)[i4] = w;
    ((float4*)h)[i4]   = a;
    ((float4*)c)[i4]   = b;
}

// ---------------- column mean over L (two-stage) ----------------
__global__ void colpart_k(const float* __restrict__ X, float* __restrict__ part) {
    int b = blockIdx.x, s = blockIdx.y, c = threadIdx.x;
    float acc = 0.f;
    int rbase = (b << 10) + s * 128;
#pragma unroll 4
    for (int j = 0; j < 128; j++) acc += X[(size_t)(rbase + j) * HDIM + c];
    part[(b * 8 + s) * HDIM + c] = acc;
}
__global__ void colfin_k(const float* __restrict__ part, float* __restrict__ out) {
    int b = blockIdx.x, c = threadIdx.x;
    float a = 0.f;
#pragma unroll
    for (int s = 0; s < 8; s++) a += part[(b * 8 + s) * HDIM + c];
    out[b * HDIM + c] = a * (1.f / 1024.f);
}

// ---------------- fp16 packing ----------------
__global__ void packW_k(const float* __restrict__ Wh_g, const float* __restrict__ Wi_g) {
    int idx = blockIdx.x * 256 + threadIdx.x;            // 1536*768
    if (idx >= 1536 * 768) return;
    int n = idx / 768, kk = idx - n * 768;
    int g = n >> 8, c = n & 255;
    float v = (kk < 512) ? Wh_g[g * 131072 + kk * 256 + c]
                         : Wi_g[g * 65536 + (kk - 512) * 256 + c];
    g_Wf[idx] = __float2half_rn(v);
}
__global__ void packWx_k(const float* __restrict__ Wx_g) {
    int idx = blockIdx.x * 256 + threadIdx.x;            // 1536*256
    if (idx >= 1536 * 256) return;
    int n = idx / 256, k = idx - n * 256;
    int g = n >> 8, c = n & 255;
    g_Wxf[idx] = __float2half_rn(Wx_g[g * 65536 + k * 256 + c]);
}
__global__ void packGf_k(const float* __restrict__ gWh) {
    int idx = blockIdx.x * 256 + threadIdx.x;            // 256*256
    if (idx >= 256 * 256) return;
    int n = idx / 256, k = idx - n * 256;
    g_gff[idx] = __float2half_rn(gWh[3 * 65536 + k * 256 + n]);
}
__global__ void split_k(const float4* __restrict__ src, uint2* __restrict__ hi,
                        uint2* __restrict__ lo) {
    int i = blockIdx.x * blockDim.x + threadIdx.x;       // NH/4
    float4 v = src[i];
    __half h0, h1, h2, h3, l0, l1, l2, l3;
    h_split(v.x, h0, l0); h_split(v.y, h1, l1);
    h_split(v.z, h2, l2); h_split(v.w, h3, l3);
    uint2 H, L;
    H.x = ((uint32_t)__half_as_ushort(h1) << 16) | __half_as_ushort(h0);
    H.y = ((uint32_t)__half_as_ushort(h3) << 16) | __half_as_ushort(h2);
    L.x = ((uint32_t)__half_as_ushort(l1) << 16) | __half_as_ushort(l0);
    L.y = ((uint32_t)__half_as_ushort(l3) << 16) | __half_as_ushort(l2);
    hi[i] = H; lo[i] = L;
}

// ---------------- fp16 2-split GEMM via legacy mma.sync (HMMA) ----------------
// C[NROWS x cols] = (Ahi + Alo) @ B^T (+Cadd +colbias +mask*pbias), B single fp16
// CTA tile 256x128, K-stage 64, SW128, 4-stage cp.async, ONE barrier per chunk.
#define SMEM_MMA (4 * 49152)
template <bool TAPS>
__global__ __launch_bounds__(256) void gemm_mma_k(
    const __half* __restrict__ Ahi, const __half* __restrict__ Alo,
    const __half* __restrict__ Bf,
    const float* __restrict__ Cadd, const float* __restrict__ colbias,
    const float* __restrict__ pbias, const float* __restrict__ mask,
    float* __restrict__ C, int cols, int K) {
    extern __shared__ char sm[];
    const uint32_t sbase = smem_to_u32(sm);
    const int tid = threadIdx.x, wid = tid >> 5, lane = tid & 31;
    const int wm = wid >> 2, wn = wid & 3;         // 2 x 4 warp grid, warp = 128x32
    const int rowBase = blockIdx.y * 256;
    const int colBase = blockIdx.x * 128;
    const int KC = K >> 6;             // 64-elem chunks per split
    const int NC = 2 * KC;             // 2 splits: Ahi, Alo

    float acc[8][4][4];
#pragma unroll
    for (int a = 0; a < 8; a++)
#pragma unroll
        for (int b = 0; b < 4; b++)
#pragma unroll
            for (int d = 0; d < 4; d++) acc[a][b][d] = 0.f;

    auto issue = [&](int cc) {
        const int buf = cc & 3;
        const int split = cc / KC;
        const int kc = cc - split * KC;
        const __half* Ab = split ? Alo : Ahi;
        const int tap = TAPS ? (kc >> 2) : 2;
        const int chA = TAPS ? ((kc & 3) << 6) : (kc << 6);
        const int kB = kc << 6;
        const int d = (tap == 0) ? -1 : ((tap == 1) ? 1 : 0);
        const uint32_t sA = sbase + buf * 49152;   // 32KB A + 16KB B
        const uint32_t sB = sA + 32768;
#pragma unroll
        for (int i = 0; i < 8; ++i) {
            int idx = tid + i * 256;                  // 0..2047 (256 rows x 8 vec)
            int r = idx >> 3, g = idx & 7;
            int grow = rowBase + r, l = grow & 1023;
            bool ok = (tap == 0) ? (l > 0) : ((tap == 1) ? (l < 1023) : true);
            const __half* src = Ab + (size_t)(grow + (ok ? d : 0)) * 256 + chA + g * 8;
            cpasync16(sA + swz(r * 128 + g * 16), src, ok ? 16 : 0);
        }
#pragma unroll
        for (int i = 0; i < 4; ++i) {
            int idx = tid + i * 256;                  // 0..1023 (128 n-rows x 8 vec)
            int n = idx >> 3, g = idx & 7;
            const __half* src = Bf + (size_t)(colBase + n) * K + kB + g * 8;
            cpasync16(sB + swz(n * 128 + g * 16), src, 16);
        }
    };

    issue(0); cp_commit();
    issue(1); cp_commit();
    issue(2); cp_commit();

    const int aRow = wm * 128 + (lane & 15);
    const int bRow = wn * 32 + (lane & 15);
    const int gSel = lane >> 4;

    for (int cc = 0; cc < NC; ++cc) {
        cp_wait2();
        __syncthreads();   // loads of cc visible + all warps done with cc-1 (buffer (cc+3)&3)
        const int buf = cc & 3;
        const uint32_t sA = sbase + buf * 49152;
        const uint32_t sB = sA + 32768;
#pragma unroll
        for (int ks = 0; ks < 4; ++ks) {
            uint32_t aT[8][4], bT[4][2];
            const int g = ks * 2 + gSel;
#pragma unroll
            for (int bt = 0; bt < 2; ++bt) {
                uint32_t r0, r1, r2, r3;
                uint32_t addr = sB + swz((bRow + bt * 16) * 128 + g * 16);
                ldsm4(r0, r1, r2, r3, addr);
                bT[bt * 2 + 0][0] = r0; bT[bt * 2 + 0][1] = r2;
                bT[bt * 2 + 1][0] = r1; bT[bt * 2 + 1][1] = r3;
            }
#pragma unroll
            for (int mt = 0; mt < 8; ++mt) {
                uint32_t addr = sA + swz((aRow + mt * 16) * 128 + g * 16);
                ldsm4(aT[mt][0], aT[mt][1], aT[mt][2], aT[mt][3], addr);
            }
#pragma unroll
            for (int mt = 0; mt < 8; ++mt)
#pragma unroll
                for (int nt = 0; nt < 4; ++nt)
                    mma16816(acc[mt][nt], aT[mt], bT[nt]);
        }
        if (cc + 3 < NC) issue(cc + 3);
        cp_commit();
    }

    // epilogue: direct frag stores with fused adds
#pragma unroll
    for (int mt = 0; mt < 8; ++mt) {
#pragma unroll
        for (int i = 0; i < 2; ++i) {
            int r = rowBase + wm * 128 + mt * 16 + (lane >> 2) + i * 8;
            float mk = mask[r];
            int bb = r >> 10;
            size_t rowoff = (size_t)r * cols;
#pragma unroll
            for (int nt = 0; nt < 4; ++nt) {
                int ccol = colBase + wn * 32 + nt * 8 + (lane & 3) * 2;
                float2 v = make_float2(acc[mt][nt][2 * i], acc[mt][nt][2 * i + 1]);
                if (Cadd) {
                    float2 a = *(const float2*)(Cadd + rowoff + ccol);
                    v.x += a.x; v.y += a.y;
                }
                if (colbias) {
                    float2 a = *(const float2*)(colbias + ccol);
                    v.x += a.x; v.y += a.y;
                }
                if (pbias) {
                    float2 p = *(const float2*)(pbias + (size_t)bb * cols + ccol);
                    v.x += mk * p.x; v.y += mk * p.y;
                }
                *(float2*)(C + rowoff + ccol) = v;
            }
        }
    }
}

// ---------------- sentence-level gates: gd / gi / go ----------------
__global__ void small_gates_k(const float* __restrict__ dh, const float* __restrict__ se,
                              const float* __restrict__ comb, const float* __restrict__ gWx,
                              const float* __restrict__ gWg, const float* __restrict__ gWh,
                              const float* __restrict__ gb, const float* __restrict__ ln_a,
                              const float* __restrict__ ln_b) {
    int b = blockIdx.x, g = blockIdx.y, c = threadIdx.x;
    __shared__ float sx[256], ss[256], sc[256];
    sx[c] = dh[b * 256 + c];
    ss[c] = se[b * 256 + c];
    sc[c] = comb[b * 256 + c];
    __syncthreads();
    const float* Wx = gWx + g * 65536;
    const float* Wg = gWg + g * 65536;
    const float* Wh = gWh + g * 65536;
    float acc = (g == 0) ? gb[c] : ((g == 2) ? gb[512 + c] : 0.f);
#pragma unroll 8
    for (int k = 0; k < 256; k++) {
        acc += sx[k] * Wx[k * 256 + c];
        acc += ss[k] * Wg[k * 256 + c];
        acc += sc[k] * Wh[k * 256 + c];
    }
    float2 r = blk_reduce2(acc, acc * acc);
    float mean = r.x * (1.f / 256.f);
    float sd2 = fmaxf(r.y - 256.f * mean * mean, 0.f);
    float invs = 1.f / (sqrtf(sd2 * (1.f / 255.f)) + EPSV);
    int lnrow = (g == 0) ? 6 : ((g == 1) ? 9 : 7);
    float y = ln_a[lnrow * 256 + c] * (acc - mean) * invs + ln_b[lnrow * 256 + c];
    if (g == 1) y += gb[256 + c];
    float sg = sigf(y);
    if (g == 0) g_gd[b * 256 + c] = sg;
    else if (g == 1) g_gi[b * 256 + c] = sg;
    else g_go[b * 256 + c] = sg;
}

// ---------------- per-batch biases: Bd = dh@Wd_g ; Bfx = dh@gWx3 ----------------
__global__ void bd_k(const float* __restrict__ dh, const float* __restrict__ Wd_g) {
    int b = blockIdx.x, g = blockIdx.y, c = threadIdx.x;
    __shared__ float sx[256];
    sx[c] = dh[b * 256 + c];
    __syncthreads();
    const float* W = Wd_g + g * 65536;
    float acc = 0.f;
#pragma unroll 8
    for (int k = 0; k < 256; k++) acc += sx[k] * W[k * 256 + c];
    g_Bd[b * 1536 + g * 256 + c] = acc;
}
__global__ void bfx_k(const float* __restrict__ dh, const float* __restrict__ gWx) {
    int b = blockIdx.x, c = threadIdx.x;
    __shared__ float sx[256];
    sx[c] = dh[b * 256 + c];
    __syncthreads();
    const float* W = gWx + 3 * 65536;
    float acc = 0.f;
#pragma unroll 8
    for (int k = 0; k < 256; k++) acc += sx[k] * W[k * 256 + c];
    g_Bfx[b * 256 + c] = acc;
}

// ---------------- layer-invariant: tln = tanh(ln(se @ gWg3)) ----------------
__global__ void tln_k(const float* __restrict__ se, const float* __restrict__ gWg,
                      const float* __restrict__ ln_a, const float* __restrict__ ln_b) {
    int b = blockIdx.x, c = threadIdx.x;
    __shared__ float ss[256];
    ss[c] = se[b * 256 + c];
    __syncthreads();
    const float* W = gWg + 3 * 65536;
    float acc = 0.f;
#pragma unroll 8
    for (int k = 0; k < 256; k++) acc += ss[k] * W[k * 256 + c];
    float2 r = blk_reduce2(acc, acc * acc);
    float mean = r.x * (1.f / 256.f);
    float sd2 = fmaxf(r.y - 256.f * mean * mean, 0.f);
    float invs = 1.f / (sqrtf(sd2 * (1.f / 255.f)) + EPSV);
    float y = ln_a[10 * 256 + c] * (acc - mean) * invs + ln_b[10 * 256 + c];
    g_tln[b * 256 + c] = tanhf(y);
}

// ---------------- fused gf LN + sigmoid + exp + score partials (warp-per-row) ----------------
__global__ void score_ln_part_k(const float* __restrict__ GFp, const float* __restrict__ Cc,
                                const float* __restrict__ mask, const float* __restrict__ ln_a,
                                const float* __restrict__ ln_b) {
    int b = blockIdx.x, s = blockIdx.y;
    int w = threadIdx.x >> 5, lane = threadIdx.x & 31;
    int rbase = (b << 10) + s * 128 + w * 16;
    float la[8], lb[8];
#pragma unroll
    for (int j = 0; j < 8; ++j) {
        la[j] = ln_a[8 * 256 + lane + 32 * j];
        lb[j] = ln_b[8 * 256 + lane + 32 * j];
    }
    float s1[8], s2[8];
#pragma unroll
    for (int j = 0; j < 8; ++j) { s1[j] = 0.f; s2[j] = 0.f; }
    for (int r16 = 0; r16 < 16; ++r16) {
        int row = rbase + r16;
        size_t off = (size_t)row * 256;
        float x[8], cv[8];
        float sum = 0.f, sq = 0.f;
#pragma unroll
        for (int j = 0; j < 8; ++j) {
            x[j] = GFp[off + lane + 32 * j];
            cv[j] = Cc[off + lane + 32 * j];
            sum += x[j];
            sq += x[j] * x[j];
        }
#pragma unroll
        for (int o = 16; o; o >>= 1) {
            sum += __shfl_xor_sync(0xffffffffu, sum, o);
            sq  += __shfl_xor_sync(0xffffffffu, sq, o);
        }
        float mean = sum * (1.f / 256.f);
        float sd2 = fmaxf(sq - 256.f * mean * mean, 0.f);
        float invs = 1.f / (sqrtf(sd2 * (1.f / 255.f)) + EPSV);
        float msm = mask[row] * 1e25f - 1e25f;
#pragma unroll
        for (int j = 0; j < 8; ++j) {
            float y = la[j] * (x[j] - mean) * invs + lb[j];
            float e = __expf(sigf(y) + msm);
            s1[j] += e;
            s2[j] += e * cv[j];
        }
    }
    int slice = b * 64 + s * 8 + w;
#pragma unroll
    for (int j = 0; j < 8; ++j) {
        g_p1[slice * 256 + lane + 32 * j] = s1[j];
        g_p2[slice * 256 + lane + 32 * j] = s2[j];
    }
}

__global__ void score_fin_k(const float* __restrict__ dcOld, float* __restrict__ dhN,
                            float* __restrict__ dcN) {
    int b = blockIdx.x, c = threadIdx.x;
    int i = b * 256 + c;
    float S1 = 0.f, S2 = 0.f;
#pragma unroll 8
    for (int s = 0; s < 64; s++) {
        S1 += g_p1[(b * 64 + s) * 256 + c];
        S2 += g_p2[(b * 64 + s) * 256 + c];
    }
    float ed = __expf(g_gd[i]);
    float ei = __expf(g_gi[i]);
    float den = S1 + ed + ei;
    float dcn = (S2 + ed * dcOld[i] + ei * g_tln[i]) / den;
    dcN[i] = dcn;
    dhN[i] = g_go[i] * tanhf(dcn);
}

// ---------------- main epilogue: 6-gate LN + sigmoid + 5-softmax + state update ----------------
// also emits the fp16 hi/lo split of h_new (next layer's GEMM A operand)
__global__ void gates_epi_k(const float* __restrict__ Cc, const float* __restrict__ dcOld,
                            const float* __restrict__ mask, const float* __restrict__ ln_a,
                            const float* __restrict__ ln_b, float* __restrict__ Hn,
                            float* __restrict__ Cn) {
    __shared__ float sP[6][256];
    __shared__ float sMean[6], sInv[6];
    int n = blockIdx.x, tid = threadIdx.x;
    size_t base = (size_t)n * 1536;
#pragma unroll
    for (int g = 0; g < 6; g++) sP[g][tid] = g_PRE[base + g * 256 + tid];
    __syncthreads();
    int w = tid >> 5, lane = tid & 31;
    if (w < 6) {
        float s = 0.f, q = 0.f;
#pragma unroll
        for (int j = 0; j < 8; j++) {
            float v = sP[w][lane + j * 32];
            s += v;
            q += v * v;
        }
#pragma unroll
        for (int o = 16; o; o >>= 1) {
            s += __shfl_xor_sync(0xffffffffu, s, o);
            q += __shfl_xor_sync(0xffffffffu, q, o);
        }
        if (lane == 0) {
            float mean = s * (1.f / 256.f);
            float sd2 = fmaxf(q - 256.f * mean * mean, 0.f);
            sMean[w] = mean;
            sInv[w] = 1.f / (sqrtf(sd2 * (1.f / 255.f)) + EPSV);
        }
    }
    __syncthreads();
    int c = tid;
    float sgm[6];
#pragma unroll
    for (int g = 0; g < 6; g++) {
        float y = ln_a[g * 256 + c] * (sP[g][c] - sMean[g]) * sInv[g] + ln_b[g * 256 + c];
        sgm[g] = sigf(y);
    }
    float e[5], es = 0.f;
#pragma unroll
    for (int g = 0; g < 5; g++) { e[g] = __expf(sgm[g]); es += e[g]; }
    float inv = 1.f / es;
    int l = n & 1023, b = n >> 10;
    float mk = mask[n];
    float cb = (l > 0) ? Cc[(size_t)(n - 1) * 256 + c] : 0.f;
    float ca = (l < 1023) ? Cc[(size_t)(n + 1) * 256 + c] : 0.f;
    float ccur = Cc[(size_t)n * 256 + c];
    float tdc = dcOld[b * 256 + c] * mk;
    float cnew = (cb * e[0] + ca * e[1] + g_emb[(size_t)n * 256 + c] * e[2] + tdc * e[3] + ccur * e[4]) * inv;
    float hnew = sgm[5] * tanhf(cnew) * mk;
    Hn[(size_t)n * 256 + c] = hnew;
    Cn[(size_t)n * 256 + c] = cnew * mk;
    __half bh, bl;
    h_split(hnew, bh, bl);
    g_hhi[(size_t)n * 256 + c] = bh;
    g_hlo[(size_t)n * 256 + c] = bl;
}

// ---------------- host orchestration ----------------
extern "C" void kernel_launch(void* const* d_in, const int* in_sizes, int n_in,
                              void* d_out, int out_size) {
    const float* word = (const float*)d_in[0];
    const float* se   = (const float*)d_in[1];
    const float* mask = (const float*)d_in[2];
    const float* h0   = (const float*)d_in[3];
    const float* c0   = (const float*)d_in[4];
    const float* Wx_g = (const float*)d_in[5];
    const float* Wh_g = (const float*)d_in[6];
    const float* Wi_g = (const float*)d_in[7];
    const float* Wd_g = (const float*)d_in[8];
    const float* b_g  = (const float*)d_in[9];
    const float* gWx  = (const float*)d_in[10];
    const float* gWh  = (const float*)d_in[11];
    const float* gWg  = (const float*)d_in[12];
    const float* gb   = (const float*)d_in[13];
    const float* ln_a = (const float*)d_in[14];
    const float* ln_b = (const float*)d_in[15];
    float* out = (float*)d_out;

    cudaFuncSetAttribute(gemm_mma_k<true>,  cudaFuncAttributeMaxDynamicSharedMemorySize, SMEM_MMA);
    cudaFuncSetAttribute(gemm_mma_k<false>, cudaFuncAttributeMaxDynamicSharedMemorySize, SMEM_MMA);

    float *ph, *pc, *pemb, *pE, *pPRE, *pGFp, *pdh, *pdc, *pcomb, *pcp, *pBd, *pBfx;
    __half *pWf, *pWxf, *pgff, *phhi, *phlo, *pehi, *pelo;
    cudaGetSymbolAddress((void**)&ph,    g_h);
    cudaGetSymbolAddress((void**)&pc,    g_c);
    cudaGetSymbolAddress((void**)&pemb,  g_emb);
    cudaGetSymbolAddress((void**)&pE,    g_E);
    cudaGetSymbolAddress((void**)&pPRE,  g_PRE);
    cudaGetSymbolAddress((void**)&pGFp,  g_GFp);
    cudaGetSymbolAddress((void**)&pdh,   g_dh);
    cudaGetSymbolAddress((void**)&pdc,   g_dc);
    cudaGetSymbolAddress((void**)&pcomb, g_comb);
    cudaGetSymbolAddress((void**)&pcp,   g_cp);
    cudaGetSymbolAddress((void**)&pBd,   g_Bd);
    cudaGetSymbolAddress((void**)&pBfx,  g_Bfx);
    cudaGetSymbolAddress((void**)&pWf,   g_Wf);
    cudaGetSymbolAddress((void**)&pWxf,  g_Wxf);
    cudaGetSymbolAddress((void**)&pgff,  g_gff);
    cudaGetSymbolAddress((void**)&phhi,  g_hhi);
    cudaGetSymbolAddress((void**)&phlo,  g_hlo);
    cudaGetSymbolAddress((void**)&pehi,  g_ehi);
    cudaGetSymbolAddress((void**)&pelo,  g_elo);

    const int SB = BBATCH * HDIM;

    // prep + initial means
    prep_k<<<NH / 1024, 256>>>(word, h0, c0, mask, pemb, ph, pc);
    colpart_k<<<dim3(32, 8), 256>>>(ph, pcp);
    colfin_k<<<32, 256>>>(pcp, pdh);
    colpart_k<<<dim3(32, 8), 256>>>(pc, pcp);
    colfin_k<<<32, 256>>>(pcp, pdc);

    // fp16 packing + layer-invariants
    packW_k<<<4608, 256>>>(Wh_g, Wi_g);
    packWx_k<<<1536, 256>>>(Wx_g);
    packGf_k<<<256, 256>>>(gWh);
    split_k<<<NH / 4 / 256, 256>>>((const float4*)pemb, (uint2*)pehi, (uint2*)pelo);
    split_k<<<NH / 4 / 256, 256>>>((const float4*)ph, (uint2*)phhi, (uint2*)phlo);
    tln_k<<<32, 256>>>(se, gWg, ln_a, ln_b);
    gemm_mma_k<false><<<dim3(12, 128), 256, SMEM_MMA>>>(
        pehi, pelo, pWxf, nullptr, nullptr, nullptr, mask, pE, 1536, 256);

    for (int layer = 0; layer < 4; ++layer) {
        int cur = layer & 1, nxt = 1 - cur;
        float* hc = ph + (size_t)cur * NH;
        float* hn = ph + (size_t)nxt * NH;
        float* cc = pc + (size_t)cur * NH;
        float* cn = pc + (size_t)nxt * NH;
        float* dhc = pdh + cur * SB;
        float* dhn = pdh + nxt * SB;
        float* dcc = pdc + cur * SB;
        float* dcn = pdc + nxt * SB;
        float* htarget = (layer == 3) ? out : hn;

        colpart_k<<<dim3(32, 8), 256>>>(hc, pcp);
        colfin_k<<<32, 256>>>(pcp, pcomb);

        small_gates_k<<<dim3(32, 3), 256>>>(dhc, se, pcomb, gWx, gWg, gWh, gb, ln_a, ln_b);
        bd_k<<<dim3(32, 6), 256>>>(dhc, Wd_g);
        bfx_k<<<32, 256>>>(dhc, gWx);

        // gf path (K=256, N=256): GEMM then fused warp-level LN+exp+partials
        gemm_mma_k<false><<<dim3(2, 128), 256, SMEM_MMA>>>(
            phhi, phlo, pgff, nullptr, gb + 768, pBfx, mask, pGFp, 256, 256);
        score_ln_part_k<<<dim3(32, 8), 256>>>(pGFp, cc, mask, ln_a, ln_b);
        score_fin_k<<<32, 256>>>(dcc, dhn, dcn);

        // main pre-activation GEMM (3-tap conv over h) + fused E/bias epilogue
        gemm_mma_k<true><<<dim3(12, 128), 256, SMEM_MMA>>>(
            phhi, phlo, pWf, pE, b_g, pBd, mask, pPRE, 1536, 768);
        gates_epi_k<<<NROWS, 256>>>(cc, dcc, mask, ln_a, ln_b, htarget, cn);
    }
}

// round 14
// speedup vs baseline: 2.7027x; 1.3407x over previous
#include <cuda_runtime.h>
#include <cuda_fp16.h>
#include <math.h>
#include <stdint.h>

#define BBATCH 32
#define LSEQ   1024
#define HDIM   256
#define NROWS  (BBATCH * LSEQ)      // 32768
#define NH     (NROWS * HDIM)       // 8388608
#define EPSV   1e-3f

typedef unsigned long long ull;

// ---------------- scratch (__device__ globals; allocation is forbidden) ----------------
__device__ float g_h[2][NH];
__device__ float g_c[2][NH];
__device__ float g_emb[NH];
__device__ float g_E[NROWS * 1536];
__device__ float g_PRE[NROWS * 1536];
__device__ float g_GFp[NH];
__device__ float g_dh[2][BBATCH * HDIM];
__device__ float g_dc[2][BBATCH * HDIM];
__device__ float g_comb[BBATCH * HDIM];
__device__ float g_gd[BBATCH * HDIM];
__device__ float g_gi[BBATCH * HDIM];
__device__ float g_go[BBATCH * HDIM];
__device__ float g_tln[BBATCH * HDIM];
__device__ float g_Bfx[BBATCH * HDIM];
__device__ float g_Bd[BBATCH * 1536];
__device__ float g_p1[BBATCH * 64 * HDIM];   // per-warp partial slices
__device__ float g_p2[BBATCH * 64 * HDIM];
__device__ float g_cp[BBATCH * 8 * HDIM];

// fp16 operands (single-split A, single fp16 B)
__device__ __half g_Wf[1536 * 768];    // main weights, [n][k] (B operand layout)
__device__ __half g_Wxf[1536 * 256];   // Wx packed transposed
__device__ __half g_gff[256 * 256];    // gWh[3] transposed
__device__ __half g_hf[NH];
__device__ __half g_ef[NH];

// ---------------- low-level helpers ----------------
__device__ __forceinline__ uint32_t smem_to_u32(const void* smem_ptr) {
    uint32_t addr;
    asm("{ .reg .u64 tmp; cvta.to.shared.u64 tmp, %1; cvt.u32.u64 %0, tmp; }"
        : "=r"(addr) : "l"(smem_ptr));
    return addr;
}
__device__ __forceinline__ uint32_t swz(uint32_t off) { return off ^ ((off >> 3) & 0x70); }

__device__ __forceinline__ void cpasync16(uint32_t dst, const void* src, int sz) {
    asm volatile("cp.async.cg.shared.global [%0], [%1], 16, %2;"
                 :: "r"(dst), "l"(src), "r"(sz) : "memory");
}
__device__ __forceinline__ void cp_commit() {
    asm volatile("cp.async.commit_group;" ::: "memory");
}
__device__ __forceinline__ void cp_wait2() {
    asm volatile("cp.async.wait_group 2;" ::: "memory");
}
__device__ __forceinline__ void ldsm4(uint32_t& r0, uint32_t& r1, uint32_t& r2, uint32_t& r3,
                                      uint32_t addr) {
    asm volatile("ldmatrix.sync.aligned.m8n8.x4.shared.b16 {%0,%1,%2,%3}, [%4];"
                 : "=r"(r0), "=r"(r1), "=r"(r2), "=r"(r3) : "r"(addr));
}
__device__ __forceinline__ void mma16816(float* c, const uint32_t* a, const uint32_t* b) {
    asm volatile(
        "mma.sync.aligned.m16n8k16.row.col.f32.f16.f16.f32 "
        "{%0,%1,%2,%3}, {%4,%5,%6,%7}, {%8,%9}, {%0,%1,%2,%3};"
        : "+f"(c[0]), "+f"(c[1]), "+f"(c[2]), "+f"(c[3])
        : "r"(a[0]), "r"(a[1]), "r"(a[2]), "r"(a[3]), "r"(b[0]), "r"(b[1]));
}

__device__ __forceinline__ float sigf(float x) { return 1.f / (1.f + __expf(-x)); }

__device__ __forceinline__ float2 blk_reduce2(float a, float b) {
    __shared__ float sA[8], sB[8];
    int lane = threadIdx.x & 31, w = threadIdx.x >> 5;
#pragma unroll
    for (int o = 16; o; o >>= 1) {
        a += __shfl_xor_sync(0xffffffffu, a, o);
        b += __shfl_xor_sync(0xffffffffu, b, o);
    }
    __syncthreads();
    if (lane == 0) { sA[w] = a; sB[w] = b; }
    __syncthreads();
    float ra = 0.f, rb = 0.f;
#pragma unroll
    for (int i = 0; i < 8; i++) { ra += sA[i]; rb += sB[i]; }
    return make_float2(ra, rb);
}

// ---------------- prep: masked inputs (+ fp16 emb/h) ----------------
__global__ void prep_k(const float* __restrict__ word, const float* __restrict__ h0,
                       const float* __restrict__ c0, const float* __restrict__ mask,
                       float* __restrict__ emb, float* __restrict__ h, float* __restrict__ c) {
    int i4 = blockIdx.x * blockDim.x + threadIdx.x;
    if (i4 >= NH / 4) return;
    float m = mask[i4 >> 6];
    float4 w = ((const float4*)word)[i4];
    float4 a = ((const float4*)h0)[i4];
    float4 b = ((const float4*)c0)[i4];
    w.x *= m; w.y *= m; w.z *= m; w.w *= m;
    a.x *= m; a.y *= m; a.z *= m; a.w *= m;
    b.x *= m; b.y *= m; b.z *= m; b.w *= m;
    ((float4*)emb)[i4] = w;
    ((float4*)h)[i4]   = a;
    ((float4*)c)[i4]   = b;
    uint2 E, H;
    E.x = ((uint32_t)__half_as_ushort(__float2half_rn(w.y)) << 16) | __half_as_ushort(__float2half_rn(w.x));
    E.y = ((uint32_t)__half_as_ushort(__float2half_rn(w.w)) << 16) | __half_as_ushort(__float2half_rn(w.z));
    H.x = ((uint32_t)__half_as_ushort(__float2half_rn(a.y)) << 16) | __half_as_ushort(__float2half_rn(a.x));
    H.y = ((uint32_t)__half_as_ushort(__float2half_rn(a.w)) << 16) | __half_as_ushort(__float2half_rn(a.z));
    ((uint2*)g_ef)[i4] = E;
    ((uint2*)g_hf)[i4] = H;
}

// ---------------- column mean over L (two-stage) ----------------
__global__ void colpart_k(const float* __restrict__ X, float* __restrict__ part) {
    int b = blockIdx.x, s = blockIdx.y, c = threadIdx.x;
    float acc = 0.f;
    int rbase = (b << 10) + s * 128;
#pragma unroll 4
    for (int j = 0; j < 128; j++) acc += X[(size_t)(rbase + j) * HDIM + c];
    part[(b * 8 + s) * HDIM + c] = acc;
}
__global__ void colfin_k(const float* __restrict__ part, float* __restrict__ out) {
    int b = blockIdx.x, c = threadIdx.x;
    float a = 0.f;
#pragma unroll
    for (int s = 0; s < 8; s++) a += part[(b * 8 + s) * HDIM + c];
    out[b * HDIM + c] = a * (1.f / 1024.f);
}

// ---------------- fp16 packing ----------------
__global__ void packW_k(const float* __restrict__ Wh_g, const float* __restrict__ Wi_g) {
    int idx = blockIdx.x * 256 + threadIdx.x;            // 1536*768
    if (idx >= 1536 * 768) return;
    int n = idx / 768, kk = idx - n * 768;
    int g = n >> 8, c = n & 255;
    float v = (kk < 512) ? Wh_g[g * 131072 + kk * 256 + c]
                         : Wi_g[g * 65536 + (kk - 512) * 256 + c];
    g_Wf[idx] = __float2half_rn(v);
}
__global__ void packWx_k(const float* __restrict__ Wx_g) {
    int idx = blockIdx.x * 256 + threadIdx.x;            // 1536*256
    if (idx >= 1536 * 256) return;
    int n = idx / 256, k = idx - n * 256;
    int g = n >> 8, c = n & 255;
    g_Wxf[idx] = __float2half_rn(Wx_g[g * 65536 + k * 256 + c]);
}
__global__ void packGf_k(const float* __restrict__ gWh) {
    int idx = blockIdx.x * 256 + threadIdx.x;            // 256*256
    if (idx >= 256 * 256) return;
    int n = idx / 256, k = idx - n * 256;
    g_gff[idx] = __float2half_rn(gWh[3 * 65536 + k * 256 + n]);
}

// ---------------- fp16 GEMM via legacy mma.sync (HMMA) ----------------
// C[NROWS x cols] = A @ B^T (+Cadd +colbias +mask*pbias), A/B single fp16
// CTA tile 256x128, K-stage 64, SW128, 4-stage cp.async, ONE barrier per chunk.
#define SMEM_MMA (4 * 49152)
template <bool TAPS>
__global__ __launch_bounds__(256) void gemm_mma_k(
    const __half* __restrict__ Af, const __half* __restrict__ Bf,
    const float* __restrict__ Cadd, const float* __restrict__ colbias,
    const float* __restrict__ pbias, const float* __restrict__ mask,
    float* __restrict__ C, int cols, int K) {
    extern __shared__ char sm[];
    const uint32_t sbase = smem_to_u32(sm);
    const int tid = threadIdx.x, wid = tid >> 5, lane = tid & 31;
    const int wm = wid >> 2, wn = wid & 3;         // 2 x 4 warp grid, warp = 128x32
    const int rowBase = blockIdx.y * 256;
    const int colBase = blockIdx.x * 128;
    const int NC = K >> 6;             // 64-elem chunks (single split)

    float acc[8][4][4];
#pragma unroll
    for (int a = 0; a < 8; a++)
#pragma unroll
        for (int b = 0; b < 4; b++)
#pragma unroll
            for (int d = 0; d < 4; d++) acc[a][b][d] = 0.f;

    auto issue = [&](int kc) {
        const int buf = kc & 3;
        const int tap = TAPS ? (kc >> 2) : 2;
        const int chA = TAPS ? ((kc & 3) << 6) : (kc << 6);
        const int kB = kc << 6;
        const int d = (tap == 0) ? -1 : ((tap == 1) ? 1 : 0);
        const uint32_t sA = sbase + buf * 49152;   // 32KB A + 16KB B
        const uint32_t sB = sA + 32768;
#pragma unroll
        for (int i = 0; i < 8; ++i) {
            int idx = tid + i * 256;                  // 0..2047 (256 rows x 8 vec)
            int r = idx >> 3, g = idx & 7;
            int grow = rowBase + r, l = grow & 1023;
            bool ok = (tap == 0) ? (l > 0) : ((tap == 1) ? (l < 1023) : true);
            const __half* src = Af + (size_t)(grow + (ok ? d : 0)) * 256 + chA + g * 8;
            cpasync16(sA + swz(r * 128 + g * 16), src, ok ? 16 : 0);
        }
#pragma unroll
        for (int i = 0; i < 4; ++i) {
            int idx = tid + i * 256;                  // 0..1023 (128 n-rows x 8 vec)
            int n = idx >> 3, g = idx & 7;
            const __half* src = Bf + (size_t)(colBase + n) * K + kB + g * 8;
            cpasync16(sB + swz(n * 128 + g * 16), src, 16);
        }
    };

    issue(0); cp_commit();
    if (NC > 1) issue(1); cp_commit();
    if (NC > 2) issue(2); cp_commit();

    const int aRow = wm * 128 + (lane & 15);
    const int bRow = wn * 32 + (lane & 15);
    const int gSel = lane >> 4;

    for (int cc = 0; cc < NC; ++cc) {
        cp_wait2();
        __syncthreads();   // loads of cc visible + all warps done with cc-1 (buffer (cc+3)&3)
        const int buf = cc & 3;
        const uint32_t sA = sbase + buf * 49152;
        const uint32_t sB = sA + 32768;
#pragma unroll
        for (int ks = 0; ks < 4; ++ks) {
            uint32_t aT[8][4], bT[4][2];
            const int g = ks * 2 + gSel;
#pragma unroll
            for (int bt = 0; bt < 2; ++bt) {
                uint32_t r0, r1, r2, r3;
                uint32_t addr = sB + swz((bRow + bt * 16) * 128 + g * 16);
                ldsm4(r0, r1, r2, r3, addr);
                bT[bt * 2 + 0][0] = r0; bT[bt * 2 + 0][1] = r2;
                bT[bt * 2 + 1][0] = r1; bT[bt * 2 + 1][1] = r3;
            }
#pragma unroll
            for (int mt = 0; mt < 8; ++mt) {
                uint32_t addr = sA + swz((aRow + mt * 16) * 128 + g * 16);
                ldsm4(aT[mt][0], aT[mt][1], aT[mt][2], aT[mt][3], addr);
            }
#pragma unroll
            for (int mt = 0; mt < 8; ++mt)
#pragma unroll
                for (int nt = 0; nt < 4; ++nt)
                    mma16816(acc[mt][nt], aT[mt], bT[nt]);
        }
        if (cc + 3 < NC) issue(cc + 3);
        cp_commit();
    }

    // epilogue: direct frag stores with fused adds
#pragma unroll
    for (int mt = 0; mt < 8; ++mt) {
#pragma unroll
        for (int i = 0; i < 2; ++i) {
            int r = rowBase + wm * 128 + mt * 16 + (lane >> 2) + i * 8;
            float mk = mask[r];
            int bb = r >> 10;
            size_t rowoff = (size_t)r * cols;
#pragma unroll
            for (int nt = 0; nt < 4; ++nt) {
                int ccol = colBase + wn * 32 + nt * 8 + (lane & 3) * 2;
                float2 v = make_float2(acc[mt][nt][2 * i], acc[mt][nt][2 * i + 1]);
                if (Cadd) {
                    float2 a = *(const float2*)(Cadd + rowoff + ccol);
                    v.x += a.x; v.y += a.y;
                }
                if (colbias) {
                    float2 a = *(const float2*)(colbias + ccol);
                    v.x += a.x; v.y += a.y;
                }
                if (pbias) {
                    float2 p = *(const float2*)(pbias + (size_t)bb * cols + ccol);
                    v.x += mk * p.x; v.y += mk * p.y;
                }
                *(float2*)(C + rowoff + ccol) = v;
            }
        }
    }
}

// ---------------- sentence-level gates: gd / gi / go ----------------
__global__ void small_gates_k(const float* __restrict__ dh, const float* __restrict__ se,
                              const float* __restrict__ comb, const float* __restrict__ gWx,
                              const float* __restrict__ gWg, const float* __restrict__ gWh,
                              const float* __restrict__ gb, const float* __restrict__ ln_a,
                              const float* __restrict__ ln_b) {
    int b = blockIdx.x, g = blockIdx.y, c = threadIdx.x;
    __shared__ float sx[256], ss[256], sc[256];
    sx[c] = dh[b * 256 + c];
    ss[c] = se[b * 256 + c];
    sc[c] = comb[b * 256 + c];
    __syncthreads();
    const float* Wx = gWx + g * 65536;
    const float* Wg = gWg + g * 65536;
    const float* Wh = gWh + g * 65536;
    float acc = (g == 0) ? gb[c] : ((g == 2) ? gb[512 + c] : 0.f);
#pragma unroll 8
    for (int k = 0; k < 256; k++) {
        acc += sx[k] * Wx[k * 256 + c];
        acc += ss[k] * Wg[k * 256 + c];
        acc += sc[k] * Wh[k * 256 + c];
    }
    float2 r = blk_reduce2(acc, acc * acc);
    float mean = r.x * (1.f / 256.f);
    float sd2 = fmaxf(r.y - 256.f * mean * mean, 0.f);
    float invs = 1.f / (sqrtf(sd2 * (1.f / 255.f)) + EPSV);
    int lnrow = (g == 0) ? 6 : ((g == 1) ? 9 : 7);
    float y = ln_a[lnrow * 256 + c] * (acc - mean) * invs + ln_b[lnrow * 256 + c];
    if (g == 1) y += gb[256 + c];
    float sg = sigf(y);
    if (g == 0) g_gd[b * 256 + c] = sg;
    else if (g == 1) g_gi[b * 256 + c] = sg;
    else g_go[b * 256 + c] = sg;
}

// ---------------- per-batch biases: Bd = dh@Wd_g ; Bfx = dh@gWx3 ----------------
__global__ void bd_k(const float* __restrict__ dh, const float* __restrict__ Wd_g) {
    int b = blockIdx.x, g = blockIdx.y, c = threadIdx.x;
    __shared__ float sx[256];
    sx[c] = dh[b * 256 + c];
    __syncthreads();
    const float* W = Wd_g + g * 65536;
    float acc = 0.f;
#pragma unroll 8
    for (int k = 0; k < 256; k++) acc += sx[k] * W[k * 256 + c];
    g_Bd[b * 1536 + g * 256 + c] = acc;
}
__global__ void bfx_k(const float* __restrict__ dh, const float* __restrict__ gWx) {
    int b = blockIdx.x, c = threadIdx.x;
    __shared__ float sx[256];
    sx[c] = dh[b * 256 + c];
    __syncthreads();
    const float* W = gWx + 3 * 65536;
    float acc = 0.f;
#pragma unroll 8
    for (int k = 0; k < 256; k++) acc += sx[k] * W[k * 256 + c];
    g_Bfx[b * 256 + c] = acc;
}

// ---------------- layer-invariant: tln = tanh(ln(se @ gWg3)) ----------------
__global__ void tln_k(const float* __restrict__ se, const float* __restrict__ gWg,
                      const float* __restrict__ ln_a, const float* __restrict__ ln_b) {
    int b = blockIdx.x, c = threadIdx.x;
    __shared__ float ss[256];
    ss[c] = se[b * 256 + c];
    __syncthreads();
    const float* W = gWg + 3 * 65536;
    float acc = 0.f;
#pragma unroll 8
    for (int k = 0; k < 256; k++) acc += ss[k] * W[k * 256 + c];
    float2 r = blk_reduce2(acc, acc * acc);
    float mean = r.x * (1.f / 256.f);
    float sd2 = fmaxf(r.y - 256.f * mean * mean, 0.f);
    float invs = 1.f / (sqrtf(sd2 * (1.f / 255.f)) + EPSV);
    float y = ln_a[10 * 256 + c] * (acc - mean) * invs + ln_b[10 * 256 + c];
    g_tln[b * 256 + c] = tanhf(y);
}

// ---------------- fused gf LN + sigmoid + exp + score partials (warp-per-row) ----------------
__global__ void score_ln_part_k(const float* __restrict__ GFp, const float* __restrict__ Cc,
                                const float* __restrict__ mask, const float* __restrict__ ln_a,
                                const float* __restrict__ ln_b) {
    int b = blockIdx.x, s = blockIdx.y;
    int w = threadIdx.x >> 5, lane = threadIdx.x & 31;
    int rbase = (b << 10) + s * 128 + w * 16;
    float la[8], lb[8];
#pragma unroll
    for (int j = 0; j < 8; ++j) {
        la[j] = ln_a[8 * 256 + lane + 32 * j];
        lb[j] = ln_b[8 * 256 + lane + 32 * j];
    }
    float s1[8], s2[8];
#pragma unroll
    for (int j = 0; j < 8; ++j) { s1[j] = 0.f; s2[j] = 0.f; }
    for (int r16 = 0; r16 < 16; ++r16) {
        int row = rbase + r16;
        size_t off = (size_t)row * 256;
        float x[8], cv[8];
        float sum = 0.f, sq = 0.f;
#pragma unroll
        for (int j = 0; j < 8; ++j) {
            x[j] = GFp[off + lane + 32 * j];
            cv[j] = Cc[off + lane + 32 * j];
            sum += x[j];
            sq += x[j] * x[j];
        }
#pragma unroll
        for (int o = 16; o; o >>= 1) {
            sum += __shfl_xor_sync(0xffffffffu, sum, o);
            sq  += __shfl_xor_sync(0xffffffffu, sq, o);
        }
        float mean = sum * (1.f / 256.f);
        float sd2 = fmaxf(sq - 256.f * mean * mean, 0.f);
        float invs = 1.f / (sqrtf(sd2 * (1.f / 255.f)) + EPSV);
        float msm = mask[row] * 1e25f - 1e25f;
#pragma unroll
        for (int j = 0; j < 8; ++j) {
            float y = la[j] * (x[j] - mean) * invs + lb[j];
            float e = __expf(sigf(y) + msm);
            s1[j] += e;
            s2[j] += e * cv[j];
        }
    }
    int slice = b * 64 + s * 8 + w;
#pragma unroll
    for (int j = 0; j < 8; ++j) {
        g_p1[slice * 256 + lane + 32 * j] = s1[j];
        g_p2[slice * 256 + lane + 32 * j] = s2[j];
    }
}

__global__ void score_fin_k(const float* __restrict__ dcOld, float* __restrict__ dhN,
                            float* __restrict__ dcN) {
    int b = blockIdx.x, c = threadIdx.x;
    int i = b * 256 + c;
    float S1 = 0.f, S2 = 0.f;
#pragma unroll 8
    for (int s = 0; s < 64; s++) {
        S1 += g_p1[(b * 64 + s) * 256 + c];
        S2 += g_p2[(b * 64 + s) * 256 + c];
    }
    float ed = __expf(g_gd[i]);
    float ei = __expf(g_gi[i]);
    float den = S1 + ed + ei;
    float dcn = (S2 + ed * dcOld[i] + ei * g_tln[i]) / den;
    dcN[i] = dcn;
    dhN[i] = g_go[i] * tanhf(dcn);
}

// ---------------- main epilogue: 6-gate LN + sigmoid + 5-softmax + state update ----------------
// also emits fp16 h_new (next layer's GEMM A operand)
__global__ void gates_epi_k(const float* __restrict__ Cc, const float* __restrict__ dcOld,
                            const float* __restrict__ mask, const float* __restrict__ ln_a,
                            const float* __restrict__ ln_b, float* __restrict__ Hn,
                            float* __restrict__ Cn) {
    __shared__ float sP[6][256];
    __shared__ float sMean[6], sInv[6];
    int n = blockIdx.x, tid = threadIdx.x;
    size_t base = (size_t)n * 1536;
#pragma unroll
    for (int g = 0; g < 6; g++) sP[g][tid] = g_PRE[base + g * 256 + tid];
    __syncthreads();
    int w = tid >> 5, lane = tid & 31;
    if (w < 6) {
        float s = 0.f, q = 0.f;
#pragma unroll
        for (int j = 0; j < 8; j++) {
            float v = sP[w][lane + j * 32];
            s += v;
            q += v * v;
        }
#pragma unroll
        for (int o = 16; o; o >>= 1) {
            s += __shfl_xor_sync(0xffffffffu, s, o);
            q += __shfl_xor_sync(0xffffffffu, q, o);
        }
        if (lane == 0) {
            float mean = s * (1.f / 256.f);
            float sd2 = fmaxf(q - 256.f * mean * mean, 0.f);
            sMean[w] = mean;
            sInv[w] = 1.f / (sqrtf(sd2 * (1.f / 255.f)) + EPSV);
        }
    }
    __syncthreads();
    int c = tid;
    float sgm[6];
#pragma unroll
    for (int g = 0; g < 6; g++) {
        float y = ln_a[g * 256 + c] * (sP[g][c] - sMean[g]) * sInv[g] + ln_b[g * 256 + c];
        sgm[g] = sigf(y);
    }
    float e[5], es = 0.f;
#pragma unroll
    for (int g = 0; g < 5; g++) { e[g] = __expf(sgm[g]); es += e[g]; }
    float inv = 1.f / es;
    int l = n & 1023, b = n >> 10;
    float mk = mask[n];
    float cb = (l > 0) ? Cc[(size_t)(n - 1) * 256 + c] : 0.f;
    float ca = (l < 1023) ? Cc[(size_t)(n + 1) * 256 + c] : 0.f;
    float ccur = Cc[(size_t)n * 256 + c];
    float tdc = dcOld[b * 256 + c] * mk;
    float cnew = (cb * e[0] + ca * e[1] + g_emb[(size_t)n * 256 + c] * e[2] + tdc * e[3] + ccur * e[4]) * inv;
    float hnew = sgm[5] * tanhf(cnew) * mk;
    Hn[(size_t)n * 256 + c] = hnew;
    Cn[(size_t)n * 256 + c] = cnew * mk;
    g_hf[(size_t)n * 256 + c] = __float2half_rn(hnew);
}

// ---------------- host orchestration ----------------
extern "C" void kernel_launch(void* const* d_in, const int* in_sizes, int n_in,
                              void* d_out, int out_size) {
    const float* word = (const float*)d_in[0];
    const float* se   = (const float*)d_in[1];
    const float* mask = (const float*)d_in[2];
    const float* h0   = (const float*)d_in[3];
    const float* c0   = (const float*)d_in[4];
    const float* Wx_g = (const float*)d_in[5];
    const float* Wh_g = (const float*)d_in[6];
    const float* Wi_g = (const float*)d_in[7];
    const float* Wd_g = (const float*)d_in[8];
    const float* b_g  = (const float*)d_in[9];
    const float* gWx  = (const float*)d_in[10];
    const float* gWh  = (const float*)d_in[11];
    const float* gWg  = (const float*)d_in[12];
    const float* gb   = (const float*)d_in[13];
    const float* ln_a = (const float*)d_in[14];
    const float* ln_b = (const float*)d_in[15];
    float* out = (float*)d_out;

    cudaFuncSetAttribute(gemm_mma_k<true>,  cudaFuncAttributeMaxDynamicSharedMemorySize, SMEM_MMA);
    cudaFuncSetAttribute(gemm_mma_k<false>, cudaFuncAttributeMaxDynamicSharedMemorySize, SMEM_MMA);

    float *ph, *pc, *pemb, *pE, *pPRE, *pGFp, *pdh, *pdc, *pcomb, *pcp, *pBd, *pBfx;
    __half *pWf, *pWxf, *pgff, *phf, *pef;
    cudaGetSymbolAddress((void**)&ph,    g_h);
    cudaGetSymbolAddress((void**)&pc,    g_c);
    cudaGetSymbolAddress((void**)&pemb,  g_emb);
    cudaGetSymbolAddress((void**)&pE,    g_E);
    cudaGetSymbolAddress((void**)&pPRE,  g_PRE);
    cudaGetSymbolAddress((void**)&pGFp,  g_GFp);
    cudaGetSymbolAddress((void**)&pdh,   g_dh);
    cudaGetSymbolAddress((void**)&pdc,   g_dc);
    cudaGetSymbolAddress((void**)&pcomb, g_comb);
    cudaGetSymbolAddress((void**)&pcp,   g_cp);
    cudaGetSymbolAddress((void**)&pBd,   g_Bd);
    cudaGetSymbolAddress((void**)&pBfx,  g_Bfx);
    cudaGetSymbolAddress((void**)&pWf,   g_Wf);
    cudaGetSymbolAddress((void**)&pWxf,  g_Wxf);
    cudaGetSymbolAddress((void**)&pgff,  g_gff);
    cudaGetSymbolAddress((void**)&phf,   g_hf);
    cudaGetSymbolAddress((void**)&pef,   g_ef);

    const int SB = BBATCH * HDIM;

    // prep + initial means
    prep_k<<<NH / 1024, 256>>>(word, h0, c0, mask, pemb, ph, pc);
    colpart_k<<<dim3(32, 8), 256>>>(ph, pcp);
    colfin_k<<<32, 256>>>(pcp, pdh);
    colpart_k<<<dim3(32, 8), 256>>>(pc, pcp);
    colfin_k<<<32, 256>>>(pcp, pdc);

    // fp16 packing + layer-invariants
    packW_k<<<4608, 256>>>(Wh_g, Wi_g);
    packWx_k<<<1536, 256>>>(Wx_g);
    packGf_k<<<256, 256>>>(gWh);
    tln_k<<<32, 256>>>(se, gWg, ln_a, ln_b);
    gemm_mma_k<false><<<dim3(12, 128), 256, SMEM_MMA>>>(
        pef, pWxf, nullptr, nullptr, nullptr, mask, pE, 1536, 256);

    for (int layer = 0; layer < 4; ++layer) {
        int cur = layer & 1, nxt = 1 - cur;
        float* hc = ph + (size_t)cur * NH;
        float* hn = ph + (size_t)nxt * NH;
        float* cc = pc + (size_t)cur * NH;
        float* cn = pc + (size_t)nxt * NH;
        float* dhc = pdh + cur * SB;
        float* dhn = pdh + nxt * SB;
        float* dcc = pdc + cur * SB;
        float* dcn = pdc + nxt * SB;
        float* htarget = (layer == 3) ? out : hn;

        colpart_k<<<dim3(32, 8), 256>>>(hc, pcp);
        colfin_k<<<32, 256>>>(pcp, pcomb);

        small_gates_k<<<dim3(32, 3), 256>>>(dhc, se, pcomb, gWx, gWg, gWh, gb, ln_a, ln_b);
        bd_k<<<dim3(32, 6), 256>>>(dhc, Wd_g);
        bfx_k<<<32, 256>>>(dhc, gWx);

        // gf path (K=256, N=256): GEMM then fused warp-level LN+exp+partials
        gemm_mma_k<false><<<dim3(2, 128), 256, SMEM_MMA>>>(
            phf, pgff, nullptr, gb + 768, pBfx, mask, pGFp, 256, 256);
        score_ln_part_k<<<dim3(32, 8), 256>>>(pGFp, cc, mask, ln_a, ln_b);
        score_fin_k<<<32, 256>>>(dcc, dhn, dcn);

        // main pre-activation GEMM (3-tap conv over h) + fused E/bias epilogue
        gemm_mma_k<true><<<dim3(12, 128), 256, SMEM_MMA>>>(
            phf, pWf, pE, b_g, pBd, mask, pPRE, 1536, 768);
        gates_epi_k<<<NROWS, 256>>>(cc, dcc, mask, ln_a, ln_b, htarget, cn);
    }
}

// round 15
// speedup vs baseline: 2.7605x; 1.0214x over previous
#include <cuda_runtime.h>
#include <cuda_fp16.h>
#include <math.h>
#include <stdint.h>

#define BBATCH 32
#define LSEQ   1024
#define HDIM   256
#define NROWS  (BBATCH * LSEQ)      // 32768
#define NH     (NROWS * HDIM)       // 8388608
#define EPSV   1e-3f

typedef unsigned long long ull;

// ---------------- scratch (__device__ globals; allocation is forbidden) ----------------
__device__ float g_h[2][NH];
__device__ float g_c[2][NH];
__device__ float g_emb[NH];
__device__ __half g_E[NROWS * 1536];     // fp16 storage (pre-LN, LN is scale-invariant)
__device__ __half g_PRE[NROWS * 1536];
__device__ __half g_GFp[NH];
__device__ float g_dh[2][BBATCH * HDIM];
__device__ float g_dc[2][BBATCH * HDIM];
__device__ float g_comb[BBATCH * HDIM];
__device__ float g_gd[BBATCH * HDIM];
__device__ float g_gi[BBATCH * HDIM];
__device__ float g_go[BBATCH * HDIM];
__device__ float g_tln[BBATCH * HDIM];
__device__ float g_Bfx[BBATCH * HDIM];
__device__ float g_Bd[BBATCH * 1536];
__device__ float g_p1[BBATCH * 64 * HDIM];   // per-warp partial slices
__device__ float g_p2[BBATCH * 64 * HDIM];
__device__ float g_cp[BBATCH * 8 * HDIM];

// fp16 operands (single-split A, single fp16 B)
__device__ __half g_Wf[1536 * 768];    // main weights, [n][k] (B operand layout)
__device__ __half g_Wxf[1536 * 256];   // Wx packed transposed
__device__ __half g_gff[256 * 256];    // gWh[3] transposed
__device__ __half g_hf[NH];
__device__ __half g_ef[NH];

// ---------------- low-level helpers ----------------
__device__ __forceinline__ uint32_t smem_to_u32(const void* smem_ptr) {
    uint32_t addr;
    asm("{ .reg .u64 tmp; cvta.to.shared.u64 tmp, %1; cvt.u32.u64 %0, tmp; }"
        : "=r"(addr) : "l"(smem_ptr));
    return addr;
}
__device__ __forceinline__ uint32_t swz(uint32_t off) { return off ^ ((off >> 3) & 0x70); }

__device__ __forceinline__ void cpasync16(uint32_t dst, const void* src, int sz) {
    asm volatile("cp.async.cg.shared.global [%0], [%1], 16, %2;"
                 :: "r"(dst), "l"(src), "r"(sz) : "memory");
}
__device__ __forceinline__ void cp_commit() {
    asm volatile("cp.async.commit_group;" ::: "memory");
}
__device__ __forceinline__ void cp_wait2() {
    asm volatile("cp.async.wait_group 2;" ::: "memory");
}
__device__ __forceinline__ void ldsm4(uint32_t& r0, uint32_t& r1, uint32_t& r2, uint32_t& r3,
                                      uint32_t addr) {
    asm volatile("ldmatrix.sync.aligned.m8n8.x4.shared.b16 {%0,%1,%2,%3}, [%4];"
                 : "=r"(r0), "=r"(r1), "=r"(r2), "=r"(r3) : "r"(addr));
}
__device__ __forceinline__ void mma16816(float* c, const uint32_t* a, const uint32_t* b) {
    asm volatile(
        "mma.sync.aligned.m16n8k16.row.col.f32.f16.f16.f32 "
        "{%0,%1,%2,%3}, {%4,%5,%6,%7}, {%8,%9}, {%0,%1,%2,%3};"
        : "+f"(c[0]), "+f"(c[1]), "+f"(c[2]), "+f"(c[3])
        : "r"(a[0]), "r"(a[1]), "r"(a[2]), "r"(a[3]), "r"(b[0]), "r"(b[1]));
}

__device__ __forceinline__ float sigf(float x) { return 1.f / (1.f + __expf(-x)); }

__device__ __forceinline__ float2 blk_reduce2(float a, float b) {
    __shared__ float sA[8], sB[8];
    int lane = threadIdx.x & 31, w = threadIdx.x >> 5;
#pragma unroll
    for (int o = 16; o; o >>= 1) {
        a += __shfl_xor_sync(0xffffffffu, a, o);
        b += __shfl_xor_sync(0xffffffffu, b, o);
    }
    __syncthreads();
    if (lane == 0) { sA[w] = a; sB[w] = b; }
    __syncthreads();
    float ra = 0.f, rb = 0.f;
#pragma unroll
    for (int i = 0; i < 8; i++) { ra += sA[i]; rb += sB[i]; }
    return make_float2(ra, rb);
}

// ---------------- prep: masked inputs (+ fp16 emb/h) ----------------
__global__ void prep_k(const float* __restrict__ word, const float* __restrict__ h0,
                       const float* __restrict__ c0, const float* __restrict__ mask,
                       float* __restrict__ emb, float* __restrict__ h, float* __restrict__ c) {
    int i4 = blockIdx.x * blockDim.x + threadIdx.x;
    if (i4 >= NH / 4) return;
    float m = mask[i4 >> 6];
    float4 w = ((const float4*)word)[i4];
    float4 a = ((const float4*)h0)[i4];
    float4 b = ((const float4*)c0)[i4];
    w.x *= m; w.y *= m; w.z *= m; w.w *= m;
    a.x *= m; a.y *= m; a.z *= m; a.w *= m;
    b.x *= m; b.y *= m; b.z *= m; b.w *= m;
    ((float4*)emb)[i4] = w;
    ((float4*)h)[i4]   = a;
    ((float4*)c)[i4]   = b;
    uint2 E, H;
    E.x = ((uint32_t)__half_as_ushort(__float2half_rn(w.y)) << 16) | __half_as_ushort(__float2half_rn(w.x));
    E.y = ((uint32_t)__half_as_ushort(__float2half_rn(w.w)) << 16) | __half_as_ushort(__float2half_rn(w.z));
    H.x = ((uint32_t)__half_as_ushort(__float2half_rn(a.y)) << 16) | __half_as_ushort(__float2half_rn(a.x));
    H.y = ((uint32_t)__half_as_ushort(__float2half_rn(a.w)) << 16) | __half_as_ushort(__float2half_rn(a.z));
    ((uint2*)g_ef)[i4] = E;
    ((uint2*)g_hf)[i4] = H;
}

// ---------------- column mean over L (two-stage) ----------------
__global__ void colpart_k(const float* __restrict__ X, float* __restrict__ part) {
    int b = blockIdx.x, s = blockIdx.y, c = threadIdx.x;
    float acc = 0.f;
    int rbase = (b << 10) + s * 128;
#pragma unroll 4
    for (int j = 0; j < 128; j++) acc += X[(size_t)(rbase + j) * HDIM + c];
    part[(b * 8 + s) * HDIM + c] = acc;
}
__global__ void colfin_k(const float* __restrict__ part, float* __restrict__ out) {
    int b = blockIdx.x, c = threadIdx.x;
    float a = 0.f;
#pragma unroll
    for (int s = 0; s < 8; s++) a += part[(b * 8 + s) * HDIM + c];
    out[b * HDIM + c] = a * (1.f / 1024.f);
}

// ---------------- fp16 packing ----------------
__global__ void packW_k(const float* __restrict__ Wh_g, const float* __restrict__ Wi_g) {
    int idx = blockIdx.x * 256 + threadIdx.x;            // 1536*768
    if (idx >= 1536 * 768) return;
    int n = idx / 768, kk = idx - n * 768;
    int g = n >> 8, c = n & 255;
    float v = (kk < 512) ? Wh_g[g * 131072 + kk * 256 + c]
                         : Wi_g[g * 65536 + (kk - 512) * 256 + c];
    g_Wf[idx] = __float2half_rn(v);
}
__global__ void packWx_k(const float* __restrict__ Wx_g) {
    int idx = blockIdx.x * 256 + threadIdx.x;            // 1536*256
    if (idx >= 1536 * 256) return;
    int n = idx / 256, k = idx - n * 256;
    int g = n >> 8, c = n & 255;
    g_Wxf[idx] = __float2half_rn(Wx_g[g * 65536 + k * 256 + c]);
}
__global__ void packGf_k(const float* __restrict__ gWh) {
    int idx = blockIdx.x * 256 + threadIdx.x;            // 256*256
    if (idx >= 256 * 256) return;
    int n = idx / 256, k = idx - n * 256;
    g_gff[idx] = __float2half_rn(gWh[3 * 65536 + k * 256 + n]);
}

// ---------------- fp16 GEMM via legacy mma.sync (HMMA) ----------------
// Ch[NROWS x cols] (fp16) = A @ B^T (+Cadd(fp16) +colbias +mask*pbias)
// CTA tile 256x128, K-stage 64, SW128, 4-stage cp.async, ONE barrier per chunk.
#define SMEM_MMA (4 * 49152)
template <bool TAPS>
__global__ __launch_bounds__(256) void gemm_mma_k(
    const __half* __restrict__ Af, const __half* __restrict__ Bf,
    const __half* __restrict__ Cadd, const float* __restrict__ colbias,
    const float* __restrict__ pbias, const float* __restrict__ mask,
    __half* __restrict__ C, int cols, int K) {
    extern __shared__ char sm[];
    const uint32_t sbase = smem_to_u32(sm);
    const int tid = threadIdx.x, wid = tid >> 5, lane = tid & 31;
    const int wm = wid >> 2, wn = wid & 3;         // 2 x 4 warp grid, warp = 128x32
    const int rowBase = blockIdx.y * 256;
    const int colBase = blockIdx.x * 128;
    const int NC = K >> 6;             // 64-elem chunks (single split)

    float acc[8][4][4];
#pragma unroll
    for (int a = 0; a < 8; a++)
#pragma unroll
        for (int b = 0; b < 4; b++)
#pragma unroll
            for (int d = 0; d < 4; d++) acc[a][b][d] = 0.f;

    auto issue = [&](int kc) {
        const int buf = kc & 3;
        const int tap = TAPS ? (kc >> 2) : 2;
        const int chA = TAPS ? ((kc & 3) << 6) : (kc << 6);
        const int kB = kc << 6;
        const int d = (tap == 0) ? -1 : ((tap == 1) ? 1 : 0);
        const uint32_t sA = sbase + buf * 49152;   // 32KB A + 16KB B
        const uint32_t sB = sA + 32768;
#pragma unroll
        for (int i = 0; i < 8; ++i) {
            int idx = tid + i * 256;                  // 0..2047 (256 rows x 8 vec)
            int r = idx >> 3, g = idx & 7;
            int grow = rowBase + r, l = grow & 1023;
            bool ok = (tap == 0) ? (l > 0) : ((tap == 1) ? (l < 1023) : true);
            const __half* src = Af + (size_t)(grow + (ok ? d : 0)) * 256 + chA + g * 8;
            cpasync16(sA + swz(r * 128 + g * 16), src, ok ? 16 : 0);
        }
#pragma unroll
        for (int i = 0; i < 4; ++i) {
            int idx = tid + i * 256;                  // 0..1023 (128 n-rows x 8 vec)
            int n = idx >> 3, g = idx & 7;
            const __half* src = Bf + (size_t)(colBase + n) * K + kB + g * 8;
            cpasync16(sB + swz(n * 128 + g * 16), src, 16);
        }
    };

    issue(0); cp_commit();
    if (NC > 1) issue(1); cp_commit();
    if (NC > 2) issue(2); cp_commit();

    const int aRow = wm * 128 + (lane & 15);
    const int bRow = wn * 32 + (lane & 15);
    const int gSel = lane >> 4;

    for (int cc = 0; cc < NC; ++cc) {
        cp_wait2();
        __syncthreads();   // loads of cc visible + all warps done with cc-1 (buffer (cc+3)&3)
        const int buf = cc & 3;
        const uint32_t sA = sbase + buf * 49152;
        const uint32_t sB = sA + 32768;
#pragma unroll
        for (int ks = 0; ks < 4; ++ks) {
            uint32_t aT[8][4], bT[4][2];
            const int g = ks * 2 + gSel;
#pragma unroll
            for (int bt = 0; bt < 2; ++bt) {
                uint32_t r0, r1, r2, r3;
                uint32_t addr = sB + swz((bRow + bt * 16) * 128 + g * 16);
                ldsm4(r0, r1, r2, r3, addr);
                bT[bt * 2 + 0][0] = r0; bT[bt * 2 + 0][1] = r2;
                bT[bt * 2 + 1][0] = r1; bT[bt * 2 + 1][1] = r3;
            }
#pragma unroll
            for (int mt = 0; mt < 8; ++mt) {
                uint32_t addr = sA + swz((aRow + mt * 16) * 128 + g * 16);
                ldsm4(aT[mt][0], aT[mt][1], aT[mt][2], aT[mt][3], addr);
            }
#pragma unroll
            for (int mt = 0; mt < 8; ++mt)
#pragma unroll
                for (int nt = 0; nt < 4; ++nt)
                    mma16816(acc[mt][nt], aT[mt], bT[nt]);
        }
        if (cc + 3 < NC) issue(cc + 3);
        cp_commit();
    }

    // epilogue: fused adds, fp16 output
#pragma unroll
    for (int mt = 0; mt < 8; ++mt) {
#pragma unroll
        for (int i = 0; i < 2; ++i) {
            int r = rowBase + wm * 128 + mt * 16 + (lane >> 2) + i * 8;
            float mk = mask[r];
            int bb = r >> 10;
            size_t rowoff = (size_t)r * cols;
#pragma unroll
            for (int nt = 0; nt < 4; ++nt) {
                int ccol = colBase + wn * 32 + nt * 8 + (lane & 3) * 2;
                float2 v = make_float2(acc[mt][nt][2 * i], acc[mt][nt][2 * i + 1]);
                if (Cadd) {
                    float2 a = __half22float2(*(const __half2*)(Cadd + rowoff + ccol));
                    v.x += a.x; v.y += a.y;
                }
                if (colbias) {
                    float2 a = *(const float2*)(colbias + ccol);
                    v.x += a.x; v.y += a.y;
                }
                if (pbias) {
                    float2 p = *(const float2*)(pbias + (size_t)bb * cols + ccol);
                    v.x += mk * p.x; v.y += mk * p.y;
                }
                *(__half2*)(C + rowoff + ccol) = __float22half2_rn(v);
            }
        }
    }
}

// ---------------- sentence-level gates: gd / gi / go ----------------
__global__ void small_gates_k(const float* __restrict__ dh, const float* __restrict__ se,
                              const float* __restrict__ comb, const float* __restrict__ gWx,
                              const float* __restrict__ gWg, const float* __restrict__ gWh,
                              const float* __restrict__ gb, const float* __restrict__ ln_a,
                              const float* __restrict__ ln_b) {
    int b = blockIdx.x, g = blockIdx.y, c = threadIdx.x;
    __shared__ float sx[256], ss[256], sc[256];
    sx[c] = dh[b * 256 + c];
    ss[c] = se[b * 256 + c];
    sc[c] = comb[b * 256 + c];
    __syncthreads();
    const float* Wx = gWx + g * 65536;
    const float* Wg = gWg + g * 65536;
    const float* Wh = gWh + g * 65536;
    float acc = (g == 0) ? gb[c] : ((g == 2) ? gb[512 + c] : 0.f);
#pragma unroll 8
    for (int k = 0; k < 256; k++) {
        acc += sx[k] * Wx[k * 256 + c];
        acc += ss[k] * Wg[k * 256 + c];
        acc += sc[k] * Wh[k * 256 + c];
    }
    float2 r = blk_reduce2(acc, acc * acc);
    float mean = r.x * (1.f / 256.f);
    float sd2 = fmaxf(r.y - 256.f * mean * mean, 0.f);
    float invs = 1.f / (sqrtf(sd2 * (1.f / 255.f)) + EPSV);
    int lnrow = (g == 0) ? 6 : ((g == 1) ? 9 : 7);
    float y = ln_a[lnrow * 256 + c] * (acc - mean) * invs + ln_b[lnrow * 256 + c];
    if (g == 1) y += gb[256 + c];
    float sg = sigf(y);
    if (g == 0) g_gd[b * 256 + c] = sg;
    else if (g == 1) g_gi[b * 256 + c] = sg;
    else g_go[b * 256 + c] = sg;
}

// ---------------- per-batch biases: Bd = dh@Wd_g ; Bfx = dh@gWx3 ----------------
__global__ void bd_k(const float* __restrict__ dh, const float* __restrict__ Wd_g) {
    int b = blockIdx.x, g = blockIdx.y, c = threadIdx.x;
    __shared__ float sx[256];
    sx[c] = dh[b * 256 + c];
    __syncthreads();
    const float* W = Wd_g + g * 65536;
    float acc = 0.f;
#pragma unroll 8
    for (int k = 0; k < 256; k++) acc += sx[k] * W[k * 256 + c];
    g_Bd[b * 1536 + g * 256 + c] = acc;
}
__global__ void bfx_k(const float* __restrict__ dh, const float* __restrict__ gWx) {
    int b = blockIdx.x, c = threadIdx.x;
    __shared__ float sx[256];
    sx[c] = dh[b * 256 + c];
    __syncthreads();
    const float* W = gWx + 3 * 65536;
    float acc = 0.f;
#pragma unroll 8
    for (int k = 0; k < 256; k++) acc += sx[k] * W[k * 256 + c];
    g_Bfx[b * 256 + c] = acc;
}

// ---------------- layer-invariant: tln = tanh(ln(se @ gWg3)) ----------------
__global__ void tln_k(const float* __restrict__ se, const float* __restrict__ gWg,
                      const float* __restrict__ ln_a, const float* __restrict__ ln_b) {
    int b = blockIdx.x, c = threadIdx.x;
    __shared__ float ss[256];
    ss[c] = se[b * 256 + c];
    __syncthreads();
    const float* W = gWg + 3 * 65536;
    float acc = 0.f;
#pragma unroll 8
    for (int k = 0; k < 256; k++) acc += ss[k] * W[k * 256 + c];
    float2 r = blk_reduce2(acc, acc * acc);
    float mean = r.x * (1.f / 256.f);
    float sd2 = fmaxf(r.y - 256.f * mean * mean, 0.f);
    float invs = 1.f / (sqrtf(sd2 * (1.f / 255.f)) + EPSV);
    float y = ln_a[10 * 256 + c] * (acc - mean) * invs + ln_b[10 * 256 + c];
    g_tln[b * 256 + c] = tanhf(y);
}

// ---------------- fused gf LN + sigmoid + exp + score partials (warp-per-row) ----------------
__global__ void score_ln_part_k(const __half* __restrict__ GFp, const float* __restrict__ Cc,
                                const float* __restrict__ mask, const float* __restrict__ ln_a,
                                const float* __restrict__ ln_b) {
    int b = blockIdx.x, s = blockIdx.y;
    int w = threadIdx.x >> 5, lane = threadIdx.x & 31;
    int rbase = (b << 10) + s * 128 + w * 16;
    float la[8], lb[8];
#pragma unroll
    for (int j = 0; j < 8; ++j) {
        la[j] = ln_a[8 * 256 + lane + 32 * j];
        lb[j] = ln_b[8 * 256 + lane + 32 * j];
    }
    float s1[8], s2[8];
#pragma unroll
    for (int j = 0; j < 8; ++j) { s1[j] = 0.f; s2[j] = 0.f; }
    for (int r16 = 0; r16 < 16; ++r16) {
        int row = rbase + r16;
        size_t off = (size_t)row * 256;
        float x[8], cv[8];
        float sum = 0.f, sq = 0.f;
#pragma unroll
        for (int j = 0; j < 8; ++j) {
            x[j] = __half2float(GFp[off + lane + 32 * j]);
            cv[j] = Cc[off + lane + 32 * j];
            sum += x[j];
            sq += x[j] * x[j];
        }
#pragma unroll
        for (int o = 16; o; o >>= 1) {
            sum += __shfl_xor_sync(0xffffffffu, sum, o);
            sq  += __shfl_xor_sync(0xffffffffu, sq, o);
        }
        float mean = sum * (1.f / 256.f);
        float sd2 = fmaxf(sq - 256.f * mean * mean, 0.f);
        float invs = 1.f / (sqrtf(sd2 * (1.f / 255.f)) + EPSV);
        float msm = mask[row] * 1e25f - 1e25f;
#pragma unroll
        for (int j = 0; j < 8; ++j) {
            float y = la[j] * (x[j] - mean) * invs + lb[j];
            float e = __expf(sigf(y) + msm);
            s1[j] += e;
            s2[j] += e * cv[j];
        }
    }
    int slice = b * 64 + s * 8 + w;
#pragma unroll
    for (int j = 0; j < 8; ++j) {
        g_p1[slice * 256 + lane + 32 * j] = s1[j];
        g_p2[slice * 256 + lane + 32 * j] = s2[j];
    }
}

__global__ void score_fin_k(const float* __restrict__ dcOld, float* __restrict__ dhN,
                            float* __restrict__ dcN) {
    int b = blockIdx.x, c = threadIdx.x;
    int i = b * 256 + c;
    float S1 = 0.f, S2 = 0.f;
#pragma unroll 8
    for (int s = 0; s < 64; s++) {
        S1 += g_p1[(b * 64 + s) * 256 + c];
        S2 += g_p2[(b * 64 + s) * 256 + c];
    }
    float ed = __expf(g_gd[i]);
    float ei = __expf(g_gi[i]);
    float den = S1 + ed + ei;
    float dcn = (S2 + ed * dcOld[i] + ei * g_tln[i]) / den;
    dcN[i] = dcn;
    dhN[i] = g_go[i] * tanhf(dcn);
}

// ---------------- main epilogue: 6-gate LN + sigmoid + 5-softmax + state update ----------------
// also emits fp16 h_new (next layer's GEMM A operand)
__global__ void gates_epi_k(const float* __restrict__ Cc, const float* __restrict__ dcOld,
                            const float* __restrict__ mask, const float* __restrict__ ln_a,
                            const float* __restrict__ ln_b, float* __restrict__ Hn,
                            float* __restrict__ Cn) {
    __shared__ float sP[6][256];
    __shared__ float sMean[6], sInv[6];
    int n = blockIdx.x, tid = threadIdx.x;
    size_t base = (size_t)n * 1536;
#pragma unroll
    for (int g = 0; g < 6; g++) sP[g][tid] = __half2float(g_PRE[base + g * 256 + tid]);
    __syncthreads();
    int w = tid >> 5, lane = tid & 31;
    if (w < 6) {
        float s = 0.f, q = 0.f;
#pragma unroll
        for (int j = 0; j < 8; j++) {
            float v = sP[w][lane + j * 32];
            s += v;
            q += v * v;
        }
#pragma unroll
        for (int o = 16; o; o >>= 1) {
            s += __shfl_xor_sync(0xffffffffu, s, o);
            q += __shfl_xor_sync(0xffffffffu, q, o);
        }
        if (lane == 0) {
            float mean = s * (1.f / 256.f);
            float sd2 = fmaxf(q - 256.f * mean * mean, 0.f);
            sMean[w] = mean;
            sInv[w] = 1.f / (sqrtf(sd2 * (1.f / 255.f)) + EPSV);
        }
    }
    __syncthreads();
    int c = tid;
    float sgm[6];
#pragma unroll
    for (int g = 0; g < 6; g++) {
        float y = ln_a[g * 256 + c] * (sP[g][c] - sMean[g]) * sInv[g] + ln_b[g * 256 + c];
        sgm[g] = sigf(y);
    }
    float e[5], es = 0.f;
#pragma unroll
    for (int g = 0; g < 5; g++) { e[g] = __expf(sgm[g]); es += e[g]; }
    float inv = 1.f / es;
    int l = n & 1023, b = n >> 10;
    float mk = mask[n];
    float cb = (l > 0) ? Cc[(size_t)(n - 1) * 256 + c] : 0.f;
    float ca = (l < 1023) ? Cc[(size_t)(n + 1) * 256 + c] : 0.f;
    float ccur = Cc[(size_t)n * 256 + c];
    float tdc = dcOld[b * 256 + c] * mk;
    float cnew = (cb * e[0] + ca * e[1] + g_emb[(size_t)n * 256 + c] * e[2] + tdc * e[3] + ccur * e[4]) * inv;
    float hnew = sgm[5] * tanhf(cnew) * mk;
    Hn[(size_t)n * 256 + c] = hnew;
    Cn[(size_t)n * 256 + c] = cnew * mk;
    g_hf[(size_t)n * 256 + c] = __float2half_rn(hnew);
}

// ---------------- host orchestration ----------------
extern "C" void kernel_launch(void* const* d_in, const int* in_sizes, int n_in,
                              void* d_out, int out_size) {
    const float* word = (const float*)d_in[0];
    const float* se   = (const float*)d_in[1];
    const float* mask = (const float*)d_in[2];
    const float* h0   = (const float*)d_in[3];
    const float* c0   = (const float*)d_in[4];
    const float* Wx_g = (const float*)d_in[5];
    const float* Wh_g = (const float*)d_in[6];
    const float* Wi_g = (const float*)d_in[7];
    const float* Wd_g = (const float*)d_in[8];
    const float* b_g  = (const float*)d_in[9];
    const float* gWx  = (const float*)d_in[10];
    const float* gWh  = (const float*)d_in[11];
    const float* gWg  = (const float*)d_in[12];
    const float* gb   = (const float*)d_in[13];
    const float* ln_a = (const float*)d_in[14];
    const float* ln_b = (const float*)d_in[15];
    float* out = (float*)d_out;

    cudaFuncSetAttribute(gemm_mma_k<true>,  cudaFuncAttributeMaxDynamicSharedMemorySize, SMEM_MMA);
    cudaFuncSetAttribute(gemm_mma_k<false>, cudaFuncAttributeMaxDynamicSharedMemorySize, SMEM_MMA);

    float *ph, *pc, *pemb, *pdh, *pdc, *pcomb, *pcp, *pBd, *pBfx;
    __half *pE, *pPRE, *pGFp, *pWf, *pWxf, *pgff, *phf, *pef;
    cudaGetSymbolAddress((void**)&ph,    g_h);
    cudaGetSymbolAddress((void**)&pc,    g_c);
    cudaGetSymbolAddress((void**)&pemb,  g_emb);
    cudaGetSymbolAddress((void**)&pE,    g_E);
    cudaGetSymbolAddress((void**)&pPRE,  g_PRE);
    cudaGetSymbolAddress((void**)&pGFp,  g_GFp);
    cudaGetSymbolAddress((void**)&pdh,   g_dh);
    cudaGetSymbolAddress((void**)&pdc,   g_dc);
    cudaGetSymbolAddress((void**)&pcomb, g_comb);
    cudaGetSymbolAddress((void**)&pcp,   g_cp);
    cudaGetSymbolAddress((void**)&pBd,   g_Bd);
    cudaGetSymbolAddress((void**)&pBfx,  g_Bfx);
    cudaGetSymbolAddress((void**)&pWf,   g_Wf);
    cudaGetSymbolAddress((void**)&pWxf,  g_Wxf);
    cudaGetSymbolAddress((void**)&pgff,  g_gff);
    cudaGetSymbolAddress((void**)&phf,   g_hf);
    cudaGetSymbolAddress((void**)&pef,   g_ef);

    const int SB = BBATCH * HDIM;

    // prep + initial means
    prep_k<<<NH / 1024, 256>>>(word, h0, c0, mask, pemb, ph, pc);
    colpart_k<<<dim3(32, 8), 256>>>(ph, pcp);
    colfin_k<<<32, 256>>>(pcp, pdh);
    colpart_k<<<dim3(32, 8), 256>>>(pc, pcp);
    colfin_k<<<32, 256>>>(pcp, pdc);

    // fp16 packing + layer-invariants
    packW_k<<<4608, 256>>>(Wh_g, Wi_g);
    packWx_k<<<1536, 256>>>(Wx_g);
    packGf_k<<<256, 256>>>(gWh);
    tln_k<<<32, 256>>>(se, gWg, ln_a, ln_b);
    gemm_mma_k<false><<<dim3(12, 128), 256, SMEM_MMA>>>(
        pef, pWxf, nullptr, nullptr, nullptr, mask, pE, 1536, 256);

    for (int layer = 0; layer < 4; ++layer) {
        int cur = layer & 1, nxt = 1 - cur;
        float* hc = ph + (size_t)cur * NH;
        float* hn = ph + (size_t)nxt * NH;
        float* cc = pc + (size_t)cur * NH;
        float* cn = pc + (size_t)nxt * NH;
        float* dhc = pdh + cur * SB;
        float* dhn = pdh + nxt * SB;
        float* dcc = pdc + cur * SB;
        float* dcn = pdc + nxt * SB;
        float* htarget = (layer == 3) ? out : hn;

        colpart_k<<<dim3(32, 8), 256>>>(hc, pcp);
        colfin_k<<<32, 256>>>(pcp, pcomb);

        small_gates_k<<<dim3(32, 3), 256>>>(dhc, se, pcomb, gWx, gWg, gWh, gb, ln_a, ln_b);
        bd_k<<<dim3(32, 6), 256>>>(dhc, Wd_g);
        bfx_k<<<32, 256>>>(dhc, gWx);

        // gf path (K=256, N=256): GEMM then fused warp-level LN+exp+partials
        gemm_mma_k<false><<<dim3(2, 128), 256, SMEM_MMA>>>(
            phf, pgff, nullptr, gb + 768, pBfx, mask, pGFp, 256, 256);
        score_ln_part_k<<<dim3(32, 8), 256>>>(pGFp, cc, mask, ln_a, ln_b);
        score_fin_k<<<32, 256>>>(dcc, dhn, dcn);

        // main pre-activation GEMM (3-tap conv over h) + fused E/bias epilogue
        gemm_mma_k<true><<<dim3(12, 128), 256, SMEM_MMA>>>(
            phf, pWf, pE, b_g, pBd, mask, pPRE, 1536, 768);
        gates_epi_k<<<NROWS, 256>>>(cc, dcc, mask, ln_a, ln_b, htarget, cn);
    }
}

// round 16
// speedup vs baseline: 3.5560x; 1.2882x over previous
#include <cuda_runtime.h>
#include <cuda_fp16.h>
#include <math.h>
#include <stdint.h>

#define BBATCH 32
#define LSEQ   1024
#define HDIM   256
#define NROWS  (BBATCH * LSEQ)      // 32768
#define NH     (NROWS * HDIM)       // 8388608
#define EPSV   1e-3f

typedef unsigned long long ull;

// ---------------- scratch (__device__ globals; allocation is forbidden) ----------------
__device__ float g_c[2][NH];
__device__ float g_emb[NH];
__device__ __half g_E[NROWS * 1536];     // fp16 storage (pre-LN, LN is scale-invariant)
__device__ __half g_PRE[NROWS * 1536];
__device__ __half g_GFp[NH];
__device__ float g_dh[2][BBATCH * HDIM];
__device__ float g_dc[2][BBATCH * HDIM];
__device__ float g_gd[BBATCH * HDIM];
__device__ float g_gi[BBATCH * HDIM];
__device__ float g_go[BBATCH * HDIM];
__device__ float g_tln[BBATCH * HDIM];
__device__ float g_Bfx[BBATCH * HDIM];
__device__ float g_Bd[BBATCH * 1536];
__device__ float g_p1[BBATCH * 64 * HDIM];   // per-warp partial slices
__device__ float g_p2[BBATCH * 64 * HDIM];
__device__ float g_cp[BBATCH * 8 * HDIM];

// fp16 operands (single fp16 A and B)
__device__ __half g_Wf[1536 * 768];    // main weights, [n][k] (B operand layout)
__device__ __half g_Wxf[1536 * 256];   // Wx packed transposed
__device__ __half g_gff[256 * 256];    // gWh[3] transposed
__device__ __half g_hf[NH];            // h state, fp16 (sole h representation)
__device__ __half g_ef[NH];

// ---------------- low-level helpers ----------------
__device__ __forceinline__ uint32_t smem_to_u32(const void* smem_ptr) {
    uint32_t addr;
    asm("{ .reg .u64 tmp; cvta.to.shared.u64 tmp, %1; cvt.u32.u64 %0, tmp; }"
        : "=r"(addr) : "l"(smem_ptr));
    return addr;
}
__device__ __forceinline__ uint32_t swz(uint32_t off) { return off ^ ((off >> 3) & 0x70); }

__device__ __forceinline__ void cpasync16(uint32_t dst, const void* src, int sz) {
    asm volatile("cp.async.cg.shared.global [%0], [%1], 16, %2;"
                 :: "r"(dst), "l"(src), "r"(sz) : "memory");
}
__device__ __forceinline__ void cp_commit() {
    asm volatile("cp.async.commit_group;" ::: "memory");
}
__device__ __forceinline__ void cp_wait2() {
    asm volatile("cp.async.wait_group 2;" ::: "memory");
}
__device__ __forceinline__ void ldsm4(uint32_t& r0, uint32_t& r1, uint32_t& r2, uint32_t& r3,
                                      uint32_t addr) {
    asm volatile("ldmatrix.sync.aligned.m8n8.x4.shared.b16 {%0,%1,%2,%3}, [%4];"
                 : "=r"(r0), "=r"(r1), "=r"(r2), "=r"(r3) : "r"(addr));
}
__device__ __forceinline__ void mma16816(float* c, const uint32_t* a, const uint32_t* b) {
    asm volatile(
        "mma.sync.aligned.m16n8k16.row.col.f32.f16.f16.f32 "
        "{%0,%1,%2,%3}, {%4,%5,%6,%7}, {%8,%9}, {%0,%1,%2,%3};"
        : "+f"(c[0]), "+f"(c[1]), "+f"(c[2]), "+f"(c[3])
        : "r"(a[0]), "r"(a[1]), "r"(a[2]), "r"(a[3]), "r"(b[0]), "r"(b[1]));
}

__device__ __forceinline__ float sigf(float x) { return 1.f / (1.f + __expf(-x)); }

__device__ __forceinline__ float2 blk_reduce2(float a, float b) {
    __shared__ float sA[8], sB[8];
    int lane = threadIdx.x & 31, w = threadIdx.x >> 5;
#pragma unroll
    for (int o = 16; o; o >>= 1) {
        a += __shfl_xor_sync(0xffffffffu, a, o);
        b += __shfl_xor_sync(0xffffffffu, b, o);
    }
    __syncthreads();
    if (lane == 0) { sA[w] = a; sB[w] = b; }
    __syncthreads();
    float ra = 0.f, rb = 0.f;
#pragma unroll
    for (int i = 0; i < 8; i++) { ra += sA[i]; rb += sB[i]; }
    return make_float2(ra, rb);
}

// ---------------- prep: masked inputs (fp16 h; fp32 c/emb) ----------------
__global__ void prep_k(const float* __restrict__ word, const float* __restrict__ h0,
                       const float* __restrict__ c0, const float* __restrict__ mask,
                       float* __restrict__ emb, float* __restrict__ c) {
    int i4 = blockIdx.x * blockDim.x + threadIdx.x;
    if (i4 >= NH / 4) return;
    float m = mask[i4 >> 6];
    float4 w = ((const float4*)word)[i4];
    float4 a = ((const float4*)h0)[i4];
    float4 b = ((const float4*)c0)[i4];
    w.x *= m; w.y *= m; w.z *= m; w.w *= m;
    a.x *= m; a.y *= m; a.z *= m; a.w *= m;
    b.x *= m; b.y *= m; b.z *= m; b.w *= m;
    ((float4*)emb)[i4] = w;
    ((float4*)c)[i4]   = b;
    uint2 E, H;
    E.x = ((uint32_t)__half_as_ushort(__float2half_rn(w.y)) << 16) | __half_as_ushort(__float2half_rn(w.x));
    E.y = ((uint32_t)__half_as_ushort(__float2half_rn(w.w)) << 16) | __half_as_ushort(__float2half_rn(w.z));
    H.x = ((uint32_t)__half_as_ushort(__float2half_rn(a.y)) << 16) | __half_as_ushort(__float2half_rn(a.x));
    H.y = ((uint32_t)__half_as_ushort(__float2half_rn(a.w)) << 16) | __half_as_ushort(__float2half_rn(a.z));
    ((uint2*)g_ef)[i4] = E;
    ((uint2*)g_hf)[i4] = H;
}

// ---------------- column partial sums over L ----------------
__global__ void colpart_k(const float* __restrict__ X, float* __restrict__ part) {
    int b = blockIdx.x, s = blockIdx.y, c = threadIdx.x;
    float acc = 0.f;
    int rbase = (b << 10) + s * 128;
#pragma unroll 4
    for (int j = 0; j < 128; j++) acc += X[(size_t)(rbase + j) * HDIM + c];
    part[(b * 8 + s) * HDIM + c] = acc;
}
__global__ void colpart_h_k(const __half* __restrict__ X, float* __restrict__ part) {
    int b = blockIdx.x, s = blockIdx.y, c = threadIdx.x;
    float acc = 0.f;
    int rbase = (b << 10) + s * 128;
#pragma unroll 4
    for (int j = 0; j < 128; j++) acc += __half2float(X[(size_t)(rbase + j) * HDIM + c]);
    part[(b * 8 + s) * HDIM + c] = acc;
}
__global__ void colfin_k(const float* __restrict__ part, float* __restrict__ out) {
    int b = blockIdx.x, c = threadIdx.x;
    float a = 0.f;
#pragma unroll
    for (int s = 0; s < 8; s++) a += part[(b * 8 + s) * HDIM + c];
    out[b * HDIM + c] = a * (1.f / 1024.f);
}

// ---------------- fp16 packing ----------------
__global__ void packW_k(const float* __restrict__ Wh_g, const float* __restrict__ Wi_g) {
    int idx = blockIdx.x * 256 + threadIdx.x;            // 1536*768
    if (idx >= 1536 * 768) return;
    int n = idx / 768, kk = idx - n * 768;
    int g = n >> 8, c = n & 255;
    float v = (kk < 512) ? Wh_g[g * 131072 + kk * 256 + c]
                         : Wi_g[g * 65536 + (kk - 512) * 256 + c];
    g_Wf[idx] = __float2half_rn(v);
}
__global__ void packWx_k(const float* __restrict__ Wx_g) {
    int idx = blockIdx.x * 256 + threadIdx.x;            // 1536*256
    if (idx >= 1536 * 256) return;
    int n = idx / 256, k = idx - n * 256;
    int g = n >> 8, c = n & 255;
    g_Wxf[idx] = __float2half_rn(Wx_g[g * 65536 + k * 256 + c]);
}
__global__ void packGf_k(const float* __restrict__ gWh) {
    int idx = blockIdx.x * 256 + threadIdx.x;            // 256*256
    if (idx >= 256 * 256) return;
    int n = idx / 256, k = idx - n * 256;
    g_gff[idx] = __float2half_rn(gWh[3 * 65536 + k * 256 + n]);
}

// ---------------- fp16 GEMM via legacy mma.sync (HMMA) ----------------
#define SMEM_MMA (4 * 49152)
template <bool TAPS>
__global__ __launch_bounds__(256) void gemm_mma_k(
    const __half* __restrict__ Af, const __half* __restrict__ Bf,
    const __half* __restrict__ Cadd, const float* __restrict__ colbias,
    const float* __restrict__ pbias, const float* __restrict__ mask,
    __half* __restrict__ C, int cols, int K) {
    extern __shared__ char sm[];
    const uint32_t sbase = smem_to_u32(sm);
    const int tid = threadIdx.x, wid = tid >> 5, lane = tid & 31;
    const int wm = wid >> 2, wn = wid & 3;
    const int rowBase = blockIdx.y * 256;
    const int colBase = blockIdx.x * 128;
    const int NC = K >> 6;

    float acc[8][4][4];
#pragma unroll
    for (int a = 0; a < 8; a++)
#pragma unroll
        for (int b = 0; b < 4; b++)
#pragma unroll
            for (int d = 0; d < 4; d++) acc[a][b][d] = 0.f;

    auto issue = [&](int kc) {
        const int buf = kc & 3;
        const int tap = TAPS ? (kc >> 2) : 2;
        const int chA = TAPS ? ((kc & 3) << 6) : (kc << 6);
        const int kB = kc << 6;
        const int d = (tap == 0) ? -1 : ((tap == 1) ? 1 : 0);
        const uint32_t sA = sbase + buf * 49152;
        const uint32_t sB = sA + 32768;
#pragma unroll
        for (int i = 0; i < 8; ++i) {
            int idx = tid + i * 256;
            int r = idx >> 3, g = idx & 7;
            int grow = rowBase + r, l = grow & 1023;
            bool ok = (tap == 0) ? (l > 0) : ((tap == 1) ? (l < 1023) : true);
            const __half* src = Af + (size_t)(grow + (ok ? d : 0)) * 256 + chA + g * 8;
            cpasync16(sA + swz(r * 128 + g * 16), src, ok ? 16 : 0);
        }
#pragma unroll
        for (int i = 0; i < 4; ++i) {
            int idx = tid + i * 256;
            int n = idx >> 3, g = idx & 7;
            const __half* src = Bf + (size_t)(colBase + n) * K + kB + g * 8;
            cpasync16(sB + swz(n * 128 + g * 16), src, 16);
        }
    };

    issue(0); cp_commit();
    if (NC > 1) issue(1); cp_commit();
    if (NC > 2) issue(2); cp_commit();

    const int aRow = wm * 128 + (lane & 15);
    const int bRow = wn * 32 + (lane & 15);
    const int gSel = lane >> 4;

    for (int cc = 0; cc < NC; ++cc) {
        cp_wait2();
        __syncthreads();
        const int buf = cc & 3;
        const uint32_t sA = sbase + buf * 49152;
        const uint32_t sB = sA + 32768;
#pragma unroll
        for (int ks = 0; ks < 4; ++ks) {
            uint32_t aT[8][4], bT[4][2];
            const int g = ks * 2 + gSel;
#pragma unroll
            for (int bt = 0; bt < 2; ++bt) {
                uint32_t r0, r1, r2, r3;
                uint32_t addr = sB + swz((bRow + bt * 16) * 128 + g * 16);
                ldsm4(r0, r1, r2, r3, addr);
                bT[bt * 2 + 0][0] = r0; bT[bt * 2 + 0][1] = r2;
                bT[bt * 2 + 1][0] = r1; bT[bt * 2 + 1][1] = r3;
            }
#pragma unroll
            for (int mt = 0; mt < 8; ++mt) {
                uint32_t addr = sA + swz((aRow + mt * 16) * 128 + g * 16);
                ldsm4(aT[mt][0], aT[mt][1], aT[mt][2], aT[mt][3], addr);
            }
#pragma unroll
            for (int mt = 0; mt < 8; ++mt)
#pragma unroll
                for (int nt = 0; nt < 4; ++nt)
                    mma16816(acc[mt][nt], aT[mt], bT[nt]);
        }
        if (cc + 3 < NC) issue(cc + 3);
        cp_commit();
    }

#pragma unroll
    for (int mt = 0; mt < 8; ++mt) {
#pragma unroll
        for (int i = 0; i < 2; ++i) {
            int r = rowBase + wm * 128 + mt * 16 + (lane >> 2) + i * 8;
            float mk = mask[r];
            int bb = r >> 10;
            size_t rowoff = (size_t)r * cols;
#pragma unroll
            for (int nt = 0; nt < 4; ++nt) {
                int ccol = colBase + wn * 32 + nt * 8 + (lane & 3) * 2;
                float2 v = make_float2(acc[mt][nt][2 * i], acc[mt][nt][2 * i + 1]);
                if (Cadd) {
                    float2 a = __half22float2(*(const __half2*)(Cadd + rowoff + ccol));
                    v.x += a.x; v.y += a.y;
                }
                if (colbias) {
                    float2 a = *(const float2*)(colbias + ccol);
                    v.x += a.x; v.y += a.y;
                }
                if (pbias) {
                    float2 p = *(const float2*)(pbias + (size_t)bb * cols + ccol);
                    v.x += mk * p.x; v.y += mk * p.y;
                }
                *(__half2*)(C + rowoff + ccol) = __float22half2_rn(v);
            }
        }
    }
}

// ---------------- fused sentence-level kernel ----------------
// grid (32, 10): y=0..2 gates gd/gi/go (incl. comb from partials), y=3..8 Bd, y=9 Bfx
__global__ void sentence_k(const float* __restrict__ dh, const float* __restrict__ se,
                           const float* __restrict__ gWx, const float* __restrict__ gWg,
                           const float* __restrict__ gWh, const float* __restrict__ Wd_g,
                           const float* __restrict__ gb, const float* __restrict__ ln_a,
                           const float* __restrict__ ln_b) {
    int b = blockIdx.x, y = blockIdx.y, c = threadIdx.x;
    __shared__ float sx[256], ss[256], sc[256];
    sx[c] = dh[b * 256 + c];
    if (y < 3) {
        ss[c] = se[b * 256 + c];
        float a = 0.f;
#pragma unroll
        for (int s = 0; s < 8; s++) a += g_cp[(b * 8 + s) * HDIM + c];
        sc[c] = a * (1.f / 1024.f);
    }
    __syncthreads();

    if (y >= 3 && y <= 8) {
        const float* W = Wd_g + (y - 3) * 65536;
        float acc = 0.f;
#pragma unroll 8
        for (int k = 0; k < 256; k++) acc += sx[k] * W[k * 256 + c];
        g_Bd[b * 1536 + (y - 3) * 256 + c] = acc;
        return;
    }
    if (y == 9) {
        const float* W = gWx + 3 * 65536;
        float acc = 0.f;
#pragma unroll 8
        for (int k = 0; k < 256; k++) acc += sx[k] * W[k * 256 + c];
        g_Bfx[b * 256 + c] = acc;
        return;
    }
    int g = y;
    const float* Wx = gWx + g * 65536;
    const float* Wg = gWg + g * 65536;
    const float* Wh = gWh + g * 65536;
    float acc = (g == 0) ? gb[c] : ((g == 2) ? gb[512 + c] : 0.f);
#pragma unroll 8
    for (int k = 0; k < 256; k++) {
        acc += sx[k] * Wx[k * 256 + c];
        acc += ss[k] * Wg[k * 256 + c];
        acc += sc[k] * Wh[k * 256 + c];
    }
    float2 r = blk_reduce2(acc, acc * acc);
    float mean = r.x * (1.f / 256.f);
    float sd2 = fmaxf(r.y - 256.f * mean * mean, 0.f);
    float invs = 1.f / (sqrtf(sd2 * (1.f / 255.f)) + EPSV);
    int lnrow = (g == 0) ? 6 : ((g == 1) ? 9 : 7);
    float yv = ln_a[lnrow * 256 + c] * (acc - mean) * invs + ln_b[lnrow * 256 + c];
    if (g == 1) yv += gb[256 + c];
    float sg = sigf(yv);
    if (g == 0) g_gd[b * 256 + c] = sg;
    else if (g == 1) g_gi[b * 256 + c] = sg;
    else g_go[b * 256 + c] = sg;
}

// ---------------- layer-invariant: tln = tanh(ln(se @ gWg3)) ----------------
__global__ void tln_k(const float* __restrict__ se, const float* __restrict__ gWg,
                      const float* __restrict__ ln_a, const float* __restrict__ ln_b) {
    int b = blockIdx.x, c = threadIdx.x;
    __shared__ float ss[256];
    ss[c] = se[b * 256 + c];
    __syncthreads();
    const float* W = gWg + 3 * 65536;
    float acc = 0.f;
#pragma unroll 8
    for (int k = 0; k < 256; k++) acc += ss[k] * W[k * 256 + c];
    float2 r = blk_reduce2(acc, acc * acc);
    float mean = r.x * (1.f / 256.f);
    float sd2 = fmaxf(r.y - 256.f * mean * mean, 0.f);
    float invs = 1.f / (sqrtf(sd2 * (1.f / 255.f)) + EPSV);
    float y = ln_a[10 * 256 + c] * (acc - mean) * invs + ln_b[10 * 256 + c];
    g_tln[b * 256 + c] = tanhf(y);
}

// ---------------- fused gf LN + sigmoid + exp + score partials (warp-per-row) ----------------
__global__ void score_ln_part_k(const __half* __restrict__ GFp, const float* __restrict__ Cc,
                                const float* __restrict__ mask, const float* __restrict__ ln_a,
                                const float* __restrict__ ln_b) {
    int b = blockIdx.x, s = blockIdx.y;
    int w = threadIdx.x >> 5, lane = threadIdx.x & 31;
    int rbase = (b << 10) + s * 128 + w * 16;
    float la[8], lb[8];
#pragma unroll
    for (int j = 0; j < 8; ++j) {
        la[j] = ln_a[8 * 256 + lane + 32 * j];
        lb[j] = ln_b[8 * 256 + lane + 32 * j];
    }
    float s1[8], s2[8];
#pragma unroll
    for (int j = 0; j < 8; ++j) { s1[j] = 0.f; s2[j] = 0.f; }
    for (int r16 = 0; r16 < 16; ++r16) {
        int row = rbase + r16;
        size_t off = (size_t)row * 256;
        float x[8], cv[8];
        float sum = 0.f, sq = 0.f;
#pragma unroll
        for (int j = 0; j < 8; ++j) {
            x[j] = __half2float(GFp[off + lane + 32 * j]);
            cv[j] = Cc[off + lane + 32 * j];
            sum += x[j];
            sq += x[j] * x[j];
        }
#pragma unroll
        for (int o = 16; o; o >>= 1) {
            sum += __shfl_xor_sync(0xffffffffu, sum, o);
            sq  += __shfl_xor_sync(0xffffffffu, sq, o);
        }
        float mean = sum * (1.f / 256.f);
        float sd2 = fmaxf(sq - 256.f * mean * mean, 0.f);
        float invs = 1.f / (sqrtf(sd2 * (1.f / 255.f)) + EPSV);
        float msm = mask[row] * 1e25f - 1e25f;
#pragma unroll
        for (int j = 0; j < 8; ++j) {
            float y = la[j] * (x[j] - mean) * invs + lb[j];
            float e = __expf(sigf(y) + msm);
            s1[j] += e;
            s2[j] += e * cv[j];
        }
    }
    int slice = b * 64 + s * 8 + w;
#pragma unroll
    for (int j = 0; j < 8; ++j) {
        g_p1[slice * 256 + lane + 32 * j] = s1[j];
        g_p2[slice * 256 + lane + 32 * j] = s2[j];
    }
}

__global__ void score_fin_k(const float* __restrict__ dcOld, float* __restrict__ dhN,
                            float* __restrict__ dcN) {
    int b = blockIdx.x, c = threadIdx.x;
    int i = b * 256 + c;
    float S1 = 0.f, S2 = 0.f;
#pragma unroll 8
    for (int s = 0; s < 64; s++) {
        S1 += g_p1[(b * 64 + s) * 256 + c];
        S2 += g_p2[(b * 64 + s) * 256 + c];
    }
    float ed = __expf(g_gd[i]);
    float ei = __expf(g_gi[i]);
    float den = S1 + ed + ei;
    float dcn = (S2 + ed * dcOld[i] + ei * g_tln[i]) / den;
    dcN[i] = dcn;
    dhN[i] = g_go[i] * tanhf(dcn);
}

// ---------------- main epilogue ----------------
__global__ void gates_epi_k(const float* __restrict__ Cc, const float* __restrict__ dcOld,
                            const float* __restrict__ mask, const float* __restrict__ ln_a,
                            const float* __restrict__ ln_b, float* __restrict__ Hn,
                            float* __restrict__ Cn) {
    __shared__ float sP[6][256];
    __shared__ float sMean[6], sInv[6];
    int n = blockIdx.x, tid = threadIdx.x;
    size_t base = (size_t)n * 1536;
#pragma unroll
    for (int g = 0; g < 6; g++) sP[g][tid] = __half2float(g_PRE[base + g * 256 + tid]);
    __syncthreads();
    int w = tid >> 5, lane = tid & 31;
    if (w < 6) {
        float s = 0.f, q = 0.f;
#pragma unroll
        for (int j = 0; j < 8; j++) {
            float v = sP[w][lane + j * 32];
            s += v;
            q += v * v;
        }
#pragma unroll
        for (int o = 16; o; o >>= 1) {
            s += __shfl_xor_sync(0xffffffffu, s, o);
            q += __shfl_xor_sync(0xffffffffu, q, o);
        }
        if (lane == 0) {
            float mean = s * (1.f / 256.f);
            float sd2 = fmaxf(q - 256.f * mean * mean, 0.f);
            sMean[w] = mean;
            sInv[w] = 1.f / (sqrtf(sd2 * (1.f / 255.f)) + EPSV);
        }
    }
    __syncthreads();
    int c = tid;
    float sgm[6];
#pragma unroll
    for (int g = 0; g < 6; g++) {
        float y = ln_a[g * 256 + c] * (sP[g][c] - sMean[g]) * sInv[g] + ln_b[g * 256 + c];
        sgm[g] = sigf(y);
    }
    float e[5], es = 0.f;
#pragma unroll
    for (int g = 0; g < 5; g++) { e[g] = __expf(sgm[g]); es += e[g]; }
    float inv = 1.f / es;
    int l = n & 1023, b = n >> 10;
    float mk = mask[n];
    float cb = (l > 0) ? Cc[(size_t)(n - 1) * 256 + c] : 0.f;
    float ca = (l < 1023) ? Cc[(size_t)(n + 1) * 256 + c] : 0.f;
    float ccur = Cc[(size_t)n * 256 + c];
    float tdc = dcOld[b * 256 + c] * mk;
    float cnew = (cb * e[0] + ca * e[1] + g_emb[(size_t)n * 256 + c] * e[2] + tdc * e[3] + ccur * e[4]) * inv;
    float hnew = sgm[5] * tanhf(cnew) * mk;
    if (Hn) Hn[(size_t)n * 256 + c] = hnew;
    Cn[(size_t)n * 256 + c] = cnew * mk;
    g_hf[(size_t)n * 256 + c] = __float2half_rn(hnew);
}

// ---------------- host orchestration ----------------
extern "C" void kernel_launch(void* const* d_in, const int* in_sizes, int n_in,
                              void* d_out, int out_size) {
    const float* word = (const float*)d_in[0];
    const float* se   = (const float*)d_in[1];
    const float* mask = (const float*)d_in[2];
    const float* h0   = (const float*)d_in[3];
    const float* c0   = (const float*)d_in[4];
    const float* Wx_g = (const float*)d_in[5];
    const float* Wh_g = (const float*)d_in[6];
    const float* Wi_g = (const float*)d_in[7];
    const float* Wd_g = (const float*)d_in[8];
    const float* b_g  = (const float*)d_in[9];
    const float* gWx  = (const float*)d_in[10];
    const float* gWh  = (const float*)d_in[11];
    const float* gWg  = (const float*)d_in[12];
    const float* gb   = (const float*)d_in[13];
    const float* ln_a = (const float*)d_in[14];
    const float* ln_b = (const float*)d_in[15];
    float* out = (float*)d_out;

    cudaFuncSetAttribute(gemm_mma_k<true>,  cudaFuncAttributeMaxDynamicSharedMemorySize, SMEM_MMA);
    cudaFuncSetAttribute(gemm_mma_k<false>, cudaFuncAttributeMaxDynamicSharedMemorySize, SMEM_MMA);

    float *pc, *pemb, *pdh, *pdc, *pcp, *pBd, *pBfx;
    __half *pE, *pPRE, *pGFp, *pWf, *pWxf, *pgff, *phf, *pef;
    cudaGetSymbolAddress((void**)&pc,    g_c);
    cudaGetSymbolAddress((void**)&pemb,  g_emb);
    cudaGetSymbolAddress((void**)&pE,    g_E);
    cudaGetSymbolAddress((void**)&pPRE,  g_PRE);
    cudaGetSymbolAddress((void**)&pGFp,  g_GFp);
    cudaGetSymbolAddress((void**)&pdh,   g_dh);
    cudaGetSymbolAddress((void**)&pdc,   g_dc);
    cudaGetSymbolAddress((void**)&pcp,   g_cp);
    cudaGetSymbolAddress((void**)&pBd,   g_Bd);
    cudaGetSymbolAddress((void**)&pBfx,  g_Bfx);
    cudaGetSymbolAddress((void**)&pWf,   g_Wf);
    cudaGetSymbolAddress((void**)&pWxf,  g_Wxf);
    cudaGetSymbolAddress((void**)&pgff,  g_gff);
    cudaGetSymbolAddress((void**)&phf,   g_hf);
    cudaGetSymbolAddress((void**)&pef,   g_ef);

    const int SB = BBATCH * HDIM;

    prep_k<<<NH / 1024, 256>>>(word, h0, c0, mask, pemb, pc);
    colpart_h_k<<<dim3(32, 8), 256>>>(phf, pcp);
    colfin_k<<<32, 256>>>(pcp, pdh);
    colpart_k<<<dim3(32, 8), 256>>>(pc, pcp);
    colfin_k<<<32, 256>>>(pcp, pdc);

    packW_k<<<4608, 256>>>(Wh_g, Wi_g);
    packWx_k<<<1536, 256>>>(Wx_g);
    packGf_k<<<256, 256>>>(gWh);
    tln_k<<<32, 256>>>(se, gWg, ln_a, ln_b);
    gemm_mma_k<false><<<dim3(12, 128), 256, SMEM_MMA>>>(
        pef, pWxf, nullptr, nullptr, nullptr, mask, pE, 1536, 256);

    for (int layer = 0; layer < 4; ++layer) {
        int cur = layer & 1, nxt = 1 - cur;
        float* cc = pc + (size_t)cur * NH;
        float* cn = pc + (size_t)nxt * NH;
        float* dhc = pdh + cur * SB;
        float* dhn = pdh + nxt * SB;
        float* dcc = pdc + cur * SB;
        float* dcn = pdc + nxt * SB;
        float* htarget = (layer == 3) ? out : nullptr;

        colpart_h_k<<<dim3(32, 8), 256>>>(phf, pcp);
        sentence_k<<<dim3(32, 10), 256>>>(dhc, se, gWx, gWg, gWh, Wd_g, gb, ln_a, ln_b);

        gemm_mma_k<false><<<dim3(2, 128), 256, SMEM_MMA>>>(
            phf, pgff, nullptr, gb + 768, pBfx, mask, pGFp, 256, 256);
        score_ln_part_k<<<dim3(32, 8), 256>>>(pGFp, cc, mask, ln_a, ln_b);
        score_fin_k<<<32, 256>>>(dcc, dhn, dcn);

        gemm_mma_k<true><<<dim3(12, 128), 256, SMEM_MMA>>>(
            phf, pWf, pE, b_g, pBd, mask, pPRE, 1536, 768);
        gates_epi_k<<<NROWS, 256>>>(cc, dcc, mask, ln_a, ln_b, htarget, cn);
    }
}